// round 1
// baseline (speedup 1.0000x reference)
#include <cuda_runtime.h>
#include <cuda_bf16.h>
#include <math.h>

// ---------------- constants ----------------
#define BB   16
#define NN   4096
#define DD   64
#define NPT  512
#define KK   32
#define P_TOT (BB*NPT*KK)     // 262144
#define PB   (128*NPT)        // 65536 per-batch (c,s) block
#define EPSF 1e-5f

// ---------------- scratch (static device memory; no allocations) ----------------
__device__ float g_bufA[131L * P_TOT];          // 131 x P  (rows 128..130 = rel_xyz)
__device__ float g_bufB[128L * P_TOT];          // 128 x P
__device__ float g_xp[BB*128*NPT];              // pooled features [b][c][s]
__device__ float g_x0[BB*128*NPT];
__device__ float g_energy[BB*NPT*NPT];          // [b][n][m]
__device__ float g_x2[BB*128*NPT];
__device__ float g_t[BB*128*NPT];
__device__ float g_y[BB*128*NPT];
__device__ float g_mean[131];
__device__ float g_var[131];
__device__ int   g_fps[BB*NPT];
__device__ int   g_nbr[BB*NPT*KK];

// ---------------- FPS ----------------
__global__ void __launch_bounds__(1024) fps_kernel(const float* __restrict__ xyz,
                                                   int* __restrict__ fps) {
    extern __shared__ float sm[];
    float* sx = sm;
    float* sy = sm + NN;
    float* sz = sm + 2*NN;
    __shared__ unsigned long long swarp[32];
    __shared__ int sfar;
    int b = blockIdx.x, tid = threadIdx.x;
    const float* base = xyz + (long)b*3*NN;
    for (int i = tid; i < NN; i += 1024) {
        sx[i] = base[i];
        sy[i] = base[NN + i];
        sz[i] = base[2*NN + i];
    }
    __syncthreads();
    float dist[4];
    dist[0] = dist[1] = dist[2] = dist[3] = 1e10f;
    int far = 0;
    for (int it = 0; it < NPT; ++it) {
        if (tid == 0) fps[b*NPT + it] = far;
        float cx = sx[far], cy = sy[far], cz = sz[far];
        unsigned long long best = 0ull;
        #pragma unroll
        for (int j = 0; j < 4; ++j) {
            int n = tid + j*1024;
            float dx = sx[n]-cx, dy = sy[n]-cy, dz = sz[n]-cz;
            float d = dx*dx + dy*dy + dz*dz;
            float dd = fminf(dist[j], d);
            dist[j] = dd;
            unsigned long long key =
                ((unsigned long long)__float_as_uint(dd) << 32) |
                (unsigned long long)(0xFFFFFFFFu - (unsigned)n);
            best = (key > best) ? key : best;
        }
        #pragma unroll
        for (int off = 16; off > 0; off >>= 1) {
            unsigned long long o = __shfl_down_sync(0xFFFFFFFFu, best, off);
            best = (o > best) ? o : best;
        }
        if ((tid & 31) == 0) swarp[tid >> 5] = best;
        __syncthreads();
        if (tid < 32) {
            best = swarp[tid];
            #pragma unroll
            for (int off = 16; off > 0; off >>= 1) {
                unsigned long long o = __shfl_down_sync(0xFFFFFFFFu, best, off);
                best = (o > best) ? o : best;
            }
            if (tid == 0)
                sfar = (int)(0xFFFFFFFFu - (unsigned)(best & 0xFFFFFFFFull));
        }
        __syncthreads();
        far = sfar;
    }
}

// ---------------- new_xyz output ----------------
__global__ void newxyz_kernel(float* __restrict__ out, const float* __restrict__ xyz,
                              const int* __restrict__ fps) {
    int i = blockIdx.x*256 + threadIdx.x;
    if (i >= BB*3*NPT) return;
    int s = i & 511;
    int c = (i >> 9) % 3;
    int b = i / (3*NPT);
    out[i] = xyz[(long)b*3*NN + c*NN + fps[b*NPT + s]];
}

// ---------------- ball query ----------------
__global__ void __launch_bounds__(256) ball_kernel(const float* __restrict__ xyz,
                                                   const int* __restrict__ fps,
                                                   int* __restrict__ nbr) {
    extern __shared__ float sm[];
    float* sx = sm;
    float* sy = sm + NN;
    float* sz = sm + 2*NN;
    __shared__ int snb[8][KK];
    int b = blockIdx.y, tid = threadIdx.x;
    const float* base = xyz + (long)b*3*NN;
    for (int i = tid; i < NN; i += 256) {
        sx[i] = base[i];
        sy[i] = base[NN + i];
        sz[i] = base[2*NN + i];
    }
    __syncthreads();
    int w = tid >> 5, lane = tid & 31;
    int s = blockIdx.x*8 + w;
    int fi = fps[b*NPT + s];
    float cx = sx[fi], cy = sy[fi], cz = sz[fi];
    float cn = cx*cx + cy*cy + cz*cz;
    const float R2 = (float)(0.4*0.4);
    int cnt = 0;
    for (int n0 = 0; n0 < NN && cnt < KK; n0 += 32) {
        int n = n0 + lane;
        float px = sx[n], py = sy[n], pz = sz[n];
        float pn = px*px + py*py + pz*pz;
        float dt = cx*px + cy*py + cz*pz;
        float sq = (cn + pn) - 2.0f*dt;
        bool in = !(sq > R2);
        unsigned m = __ballot_sync(0xFFFFFFFFu, in);
        int pos = cnt + __popc(m & ((1u << lane) - 1u));
        if (in && pos < KK) snb[w][pos] = n;
        cnt += __popc(m);
    }
    __syncwarp();
    int v = (lane < cnt) ? snb[w][lane] : snb[w][0];
    nbr[(b*NPT + s)*KK + lane] = v;
}

// ---------------- feature build ----------------
__global__ void __launch_bounds__(256) feat_kernel(const float* __restrict__ points,
                                                   const float* __restrict__ xyz,
                                                   const int* __restrict__ fps,
                                                   const int* __restrict__ nbr,
                                                   float* __restrict__ X0,
                                                   float* __restrict__ relbuf) {
    int s = blockIdx.x, b = blockIdx.y, tid = threadIdx.x;
    __shared__ int snb[KK];
    __shared__ float scen[DD];
    __shared__ float scxyz[3];
    int fi = fps[b*NPT + s];
    if (tid < KK) snb[tid] = nbr[(b*NPT + s)*KK + tid];
    if (tid >= 32 && tid < 32+DD) scen[tid-32] = points[(long)b*DD*NN + (tid-32)*NN + fi];
    if (tid >= 96 && tid < 99)   scxyz[tid-96] = xyz[(long)b*3*NN + (tid-96)*NN + fi];
    __syncthreads();
    int k = tid & 31, cb = tid >> 5;   // cb 0..7
    int n = snb[k];
    int base = (b*NPT + s)*KK + k;
    #pragma unroll
    for (int q = 0; q < 8; ++q) {
        int c = q*8 + cb;
        float v = points[(long)b*DD*NN + c*NN + n];
        X0[(long)c*P_TOT + base] = v;
        X0[(long)(DD+c)*P_TOT + base] = v - scen[c];
    }
    if (cb < 3) {
        float v = xyz[(long)b*3*NN + cb*NN + n] - scxyz[cb];
        relbuf[(long)cb*P_TOT + base] = v;
    }
}

// ---------------- generic register-blocked GEMM ----------------
// Y[b][coBase+co][p] = sum_k A(co,k) * X[b][k][p] + bias[co]
// A(co,k) = TRANSA ? A[k*lda+co_glob] : A[co_glob*lda+k]
template<int COUT, bool TRANSA>
__global__ void __launch_bounds__(256)
gemm_k(const float* __restrict__ A, int lda, long aStride,
       const float* __restrict__ X, long xStride,
       float* __restrict__ Y, long yStride,
       const float* __restrict__ bias, int Cin, int P)
{
    constexpr int CR = COUT / 16;
    A += (long)blockIdx.y * aStride;
    X += (long)blockIdx.y * xStride;
    Y += (long)blockIdx.y * yStride;
    int coBase = blockIdx.z * COUT;
    int p0 = blockIdx.x * 128;
    int tid = threadIdx.x;
    int tx = tid & 15, ty = tid >> 4;

    __shared__ float sX[32][132];
    __shared__ float sW[32][COUT + 4];

    float acc[8][CR];
    #pragma unroll
    for (int i = 0; i < 8; ++i)
        #pragma unroll
        for (int j = 0; j < CR; ++j) acc[i][j] = 0.f;

    for (int k0 = 0; k0 < Cin; k0 += 32) {
        int kc = min(32, Cin - k0);
        for (int i = tid; i < kc*128; i += 256) {
            int kk = i >> 7, pp = i & 127;
            sX[kk][pp] = X[(long)(k0+kk)*P + p0 + pp];
        }
        for (int i = tid; i < kc*COUT; i += 256) {
            int kk = i / COUT, co = i % COUT;
            sW[kk][co] = TRANSA ? A[(long)(k0+kk)*lda + coBase + co]
                                : A[(long)(coBase+co)*lda + (k0+kk)];
        }
        __syncthreads();
        #pragma unroll 4
        for (int kk = 0; kk < kc; ++kk) {
            float4 xa = *reinterpret_cast<const float4*>(&sX[kk][tx*8]);
            float4 xb = *reinterpret_cast<const float4*>(&sX[kk][tx*8 + 4]);
            float xv[8] = {xa.x, xa.y, xa.z, xa.w, xb.x, xb.y, xb.z, xb.w};
            float wv[CR];
            #pragma unroll
            for (int j = 0; j < CR; j += 4) {
                float4 w4 = *reinterpret_cast<const float4*>(&sW[kk][ty*CR + j]);
                wv[j] = w4.x; wv[j+1] = w4.y; wv[j+2] = w4.z; wv[j+3] = w4.w;
            }
            #pragma unroll
            for (int i = 0; i < 8; ++i)
                #pragma unroll
                for (int j = 0; j < CR; ++j)
                    acc[i][j] = fmaf(xv[i], wv[j], acc[i][j]);
        }
        __syncthreads();
    }
    #pragma unroll
    for (int j = 0; j < CR; ++j) {
        int co = coBase + ty*CR + j;
        float bb = bias ? bias[co] : 0.f;
        float4 o0 = make_float4(acc[0][j]+bb, acc[1][j]+bb, acc[2][j]+bb, acc[3][j]+bb);
        float4 o1 = make_float4(acc[4][j]+bb, acc[5][j]+bb, acc[6][j]+bb, acc[7][j]+bb);
        float* yp = Y + (long)co*P + p0 + tx*8;
        *reinterpret_cast<float4*>(yp)     = o0;
        *reinterpret_cast<float4*>(yp + 4) = o1;
    }
}

// ---------------- BN stats ([C][P] layout) ----------------
__device__ __forceinline__ void block_reduce2(double& s, double& s2, int nthreads) {
    __shared__ double sh[64];
    #pragma unroll
    for (int off = 16; off > 0; off >>= 1) {
        s  += __shfl_down_sync(0xFFFFFFFFu, s,  off);
        s2 += __shfl_down_sync(0xFFFFFFFFu, s2, off);
    }
    int wid = threadIdx.x >> 5, lane = threadIdx.x & 31;
    if (lane == 0) { sh[wid] = s; sh[32 + wid] = s2; }
    __syncthreads();
    if (threadIdx.x < 32) {
        int nw = nthreads >> 5;
        s  = (threadIdx.x < nw) ? sh[threadIdx.x]      : 0.0;
        s2 = (threadIdx.x < nw) ? sh[32 + threadIdx.x] : 0.0;
        #pragma unroll
        for (int off = 16; off > 0; off >>= 1) {
            s  += __shfl_down_sync(0xFFFFFFFFu, s,  off);
            s2 += __shfl_down_sync(0xFFFFFFFFu, s2, off);
        }
    }
}

__global__ void __launch_bounds__(1024) bn_stats_cp(const float* __restrict__ X, int Pl,
                                                    float* __restrict__ mean,
                                                    float* __restrict__ var) {
    int c = blockIdx.x;
    const float* x = X + (long)c * Pl;
    double s = 0.0, s2 = 0.0;
    for (int i = threadIdx.x; i < Pl; i += 1024) {
        float v = x[i];
        s += v; s2 += (double)v * (double)v;
    }
    block_reduce2(s, s2, 1024);
    if (threadIdx.x == 0) {
        double m = s / Pl;
        mean[c] = (float)m;
        var[c]  = (float)(s2 / Pl - m*m);
    }
}

__global__ void __launch_bounds__(256) bn1d_stats(const float* __restrict__ y,
                                                  float* __restrict__ mean,
                                                  float* __restrict__ var) {
    int c = blockIdx.x;
    double s = 0.0, s2 = 0.0;
    for (int i = threadIdx.x; i < BB*NPT; i += 256) {
        int b = i >> 9, ss = i & 511;
        float v = y[(long)b*PB + c*NPT + ss];
        s += v; s2 += (double)v * (double)v;
    }
    block_reduce2(s, s2, 256);
    if (threadIdx.x == 0) {
        double m = s / (BB*NPT);
        mean[c] = (float)m;
        var[c]  = (float)(s2 / (BB*NPT) - m*m);
    }
}

// ---------------- BN apply + ReLU (in place, [C][P]) ----------------
__global__ void bn_apply_relu(float* __restrict__ X, const float* __restrict__ mean,
                              const float* __restrict__ var, const float* __restrict__ g,
                              const float* __restrict__ be, int Pl, int total) {
    int i = blockIdx.x*256 + threadIdx.x;
    if (i >= total) return;
    int c = i / Pl;
    float sc = g[c] * rsqrtf(var[c] + EPSF);
    float v = (X[i] - mean[c]) * sc + be[c];
    X[i] = fmaxf(v, 0.f);
}

// ---------------- maxpool over K ----------------
__global__ void maxpool_kernel(const float* __restrict__ X, float* __restrict__ xp) {
    int i = blockIdx.x*256 + threadIdx.x;
    if (i >= BB*128*NPT) return;
    int s = i & 511, c = (i >> 9) & 127, b = i >> 16;
    const float* p = X + (long)c*P_TOT + (b*NPT + s)*KK;
    float m = -3.4e38f;
    #pragma unroll
    for (int k = 0; k < KK; ++k) m = fmaxf(m, p[k]);
    xp[i] = m;
}

// ---------------- softmax rows ----------------
__global__ void softmax_kernel(float* __restrict__ e) {
    int gw = (blockIdx.x*256 + threadIdx.x) >> 5;
    int lane = threadIdx.x & 31;
    if (gw >= BB*NPT) return;
    float* row = e + (long)gw * NPT;
    float v[16];
    float mx = -3.4e38f;
    #pragma unroll
    for (int i = 0; i < 16; ++i) { v[i] = row[lane + i*32]; mx = fmaxf(mx, v[i]); }
    #pragma unroll
    for (int off = 16; off > 0; off >>= 1)
        mx = fmaxf(mx, __shfl_xor_sync(0xFFFFFFFFu, mx, off));
    float sum = 0.f;
    #pragma unroll
    for (int i = 0; i < 16; ++i) { v[i] = expf(v[i] - mx); sum += v[i]; }
    #pragma unroll
    for (int off = 16; off > 0; off >>= 1)
        sum += __shfl_xor_sync(0xFFFFFFFFu, sum, off);
    #pragma unroll
    for (int i = 0; i < 16; ++i) row[lane + i*32] = v[i] / sum;
}

// ---------------- column renormalize ----------------
__global__ void __launch_bounds__(512) colnorm_kernel(float* __restrict__ e) {
    int b = blockIdx.x, m = threadIdx.x;
    float* E = e + (long)b * NPT * NPT;
    float s = 0.f;
    for (int n = 0; n < NPT; ++n) s += E[n*NPT + m];
    float d = 1e-9f + s;
    for (int n = 0; n < NPT; ++n) E[n*NPT + m] = E[n*NPT + m] / d;
}

// ---------------- t = xp - x2 ----------------
__global__ void tdiff_kernel(const float* __restrict__ xp, const float* __restrict__ x2,
                             float* __restrict__ t) {
    int i = blockIdx.x*256 + threadIdx.x;
    if (i < BB*128*NPT) t[i] = xp[i] - x2[i];
}

// ---------------- final residual ----------------
__global__ void final_kernel(float* __restrict__ out, const float* __restrict__ xp,
                             const float* __restrict__ y, const float* __restrict__ mean,
                             const float* __restrict__ var, const float* __restrict__ gn,
                             const float* __restrict__ gb, const float* __restrict__ alpha,
                             const float* __restrict__ beta) {
    int i = blockIdx.x*256 + threadIdx.x;
    if (i >= BB*128*NPT) return;
    int c = (i >> 9) & 127;
    float xr = gn[c] * (y[i] - mean[c]) * rsqrtf(var[c] + EPSF) + gb[c];
    xr = fmaxf(xr, 0.f);
    out[i] = xp[i] + alpha[c]*xr + beta[c];
}

// ---------------- launch ----------------
extern "C" void kernel_launch(void* const* d_in, const int* in_sizes, int n_in,
                              void* d_out, int out_size) {
    const float* xyz    = (const float*)d_in[0];
    const float* points = (const float*)d_in[1];
    const float* w0 = (const float*)d_in[2];
    const float* b0 = (const float*)d_in[3];
    const float* g0 = (const float*)d_in[4];
    const float* be0= (const float*)d_in[5];
    const float* w1 = (const float*)d_in[6];
    const float* b1 = (const float*)d_in[7];
    const float* g1 = (const float*)d_in[8];
    const float* be1= (const float*)d_in[9];
    const float* w2 = (const float*)d_in[10];
    const float* b2 = (const float*)d_in[11];
    const float* g2 = (const float*)d_in[12];
    const float* be2= (const float*)d_in[13];
    const float* wl = (const float*)d_in[14];
    const float* bl = (const float*)d_in[15];
    const float* gl = (const float*)d_in[16];
    const float* bel= (const float*)d_in[17];
    const float* wv = (const float*)d_in[18];
    const float* bv = (const float*)d_in[19];
    const float* wt = (const float*)d_in[20];
    const float* bt = (const float*)d_in[21];
    const float* gn = (const float*)d_in[22];
    const float* gb = (const float*)d_in[23];
    const float* alpha = (const float*)d_in[24];
    const float* beta  = (const float*)d_in[25];
    float* out = (float*)d_out;

    float *bufA, *bufB, *xp, *x0, *energy, *x2, *t, *y, *mean, *var;
    int *fps, *nbr;
    cudaGetSymbolAddress((void**)&bufA, g_bufA);
    cudaGetSymbolAddress((void**)&bufB, g_bufB);
    cudaGetSymbolAddress((void**)&xp, g_xp);
    cudaGetSymbolAddress((void**)&x0, g_x0);
    cudaGetSymbolAddress((void**)&energy, g_energy);
    cudaGetSymbolAddress((void**)&x2, g_x2);
    cudaGetSymbolAddress((void**)&t, g_t);
    cudaGetSymbolAddress((void**)&y, g_y);
    cudaGetSymbolAddress((void**)&mean, g_mean);
    cudaGetSymbolAddress((void**)&var, g_var);
    cudaGetSymbolAddress((void**)&fps, g_fps);
    cudaGetSymbolAddress((void**)&nbr, g_nbr);

    const int SMEM_PTS = 3*NN*sizeof(float);   // 48KB
    cudaFuncSetAttribute(fps_kernel,  cudaFuncAttributeMaxDynamicSharedMemorySize, 64*1024);
    cudaFuncSetAttribute(ball_kernel, cudaFuncAttributeMaxDynamicSharedMemorySize, 64*1024);

    // geometry
    fps_kernel<<<BB, 1024, SMEM_PTS>>>(xyz, fps);
    newxyz_kernel<<<(BB*3*NPT + 255)/256, 256>>>(out, xyz, fps);
    ball_kernel<<<dim3(NPT/8, BB), 256, SMEM_PTS>>>(xyz, fps, nbr);
    feat_kernel<<<dim3(NPT, BB), 256>>>(points, xyz, fps, nbr, bufB, bufA + 128L*P_TOT);

    // MLP layer 0: 128 -> 64
    gemm_k<64,false><<<dim3(P_TOT/128,1,1), 256>>>(w0, 128, 0, bufB, 0, bufA, 0, b0, 128, P_TOT);
    bn_stats_cp<<<64, 1024>>>(bufA, P_TOT, mean, var);
    bn_apply_relu<<<(64*P_TOT + 255)/256, 256>>>(bufA, mean, var, g0, be0, P_TOT, 64*P_TOT);

    // MLP layer 1: 64 -> 64
    gemm_k<64,false><<<dim3(P_TOT/128,1,1), 256>>>(w1, 64, 0, bufA, 0, bufB, 0, b1, 64, P_TOT);
    bn_stats_cp<<<64, 1024>>>(bufB, P_TOT, mean, var);
    bn_apply_relu<<<(64*P_TOT + 255)/256, 256>>>(bufB, mean, var, g1, be1, P_TOT, 64*P_TOT);

    // MLP layer 2: 64 -> 128
    gemm_k<128,false><<<dim3(P_TOT/128,1,1), 256>>>(w2, 64, 0, bufB, 0, bufA, 0, b2, 64, P_TOT);
    bn_stats_cp<<<128, 1024>>>(bufA, P_TOT, mean, var);
    bn_apply_relu<<<(128*P_TOT + 255)/256, 256>>>(bufA, mean, var, g2, be2, P_TOT, 128*P_TOT);

    // layer l: 131 -> 128 (rel_xyz already resident in bufA rows 128..130)
    gemm_k<128,false><<<dim3(P_TOT/128,1,1), 256>>>(wl, 131, 0, bufA, 0, bufB, 0, bl, 131, P_TOT);
    bn_stats_cp<<<128, 1024>>>(bufB, P_TOT, mean, var);
    bn_apply_relu<<<(128*P_TOT + 255)/256, 256>>>(bufB, mean, var, gl, bel, P_TOT, 128*P_TOT);

    // pool over K
    maxpool_kernel<<<(BB*128*NPT + 255)/256, 256>>>(bufB, xp);

    // attention
    gemm_k<128,false><<<dim3(NPT/128, BB, 1), 256>>>(wv, 128, 0, xp, PB, x0, PB, bv, 128, NPT);
    gemm_k<128,true ><<<dim3(NPT/128, BB, 4), 256>>>(xp, NPT, PB, x0, PB, energy, (long)NPT*NPT, nullptr, 128, NPT);
    softmax_kernel<<<(BB*NPT*32 + 255)/256, 256>>>(energy);
    colnorm_kernel<<<BB, 512>>>(energy);
    gemm_k<128,false><<<dim3(NPT/128, BB, 1), 256>>>(x0, NPT, PB, energy, (long)NPT*NPT, x2, PB, nullptr, NPT, NPT);
    tdiff_kernel<<<(BB*128*NPT + 255)/256, 256>>>(xp, x2, t);
    gemm_k<128,false><<<dim3(NPT/128, BB, 1), 256>>>(wt, 128, 0, t, PB, y, PB, bt, 128, NPT);
    bn1d_stats<<<128, 256>>>(y, mean, var);
    final_kernel<<<(BB*128*NPT + 255)/256, 256>>>(out + BB*3*NPT, xp, y, mean, var, gn, gb, alpha, beta);
}

// round 2
// speedup vs baseline: 1.2344x; 1.2344x over previous
#include <cuda_runtime.h>
#include <cuda_bf16.h>
#include <math.h>

// ---------------- constants ----------------
#define BB   16
#define NN   4096
#define DD   64
#define NPT  512
#define KK   32
#define P_TOT (BB*NPT*KK)     // 262144
#define PB   (128*NPT)        // 65536 per-batch (c,s) block
#define EPSF 1e-5f

// ---------------- scratch ----------------
__device__ float g_bufA[131L * P_TOT];          // 131 x P  (rows 128..130 = rel_xyz)
__device__ float g_bufB[128L * P_TOT];          // 128 x P
__device__ float g_xp[BB*128*NPT];
__device__ float g_x0[BB*128*NPT];
__device__ float g_energy[BB*NPT*NPT];
__device__ float g_x2[BB*128*NPT];
__device__ float g_y[BB*128*NPT];
__device__ double g_ssum[5*128];
__device__ double g_ssq[5*128];
__device__ float g_tfs[5*132];                  // scale slots
__device__ float g_tfh[5*132];                  // shift slots
__device__ float g_tfl[5*132];                  // relu-lo slots
__device__ float g_colsum[BB*NPT];
__device__ int   g_fps[BB*NPT];
__device__ int   g_nbr[BB*NPT*KK];

// ---------------- zero stats ----------------
__global__ void zero_stats() {
    int i = blockIdx.x*256 + threadIdx.x;
    if (i < 5*128) { g_ssum[i] = 0.0; g_ssq[i] = 0.0; }
}

// ---------------- FPS ----------------
__global__ void __launch_bounds__(1024) fps_kernel(const float* __restrict__ xyz,
                                                   int* __restrict__ fps) {
    extern __shared__ float sm[];
    float* sx = sm;
    float* sy = sm + NN;
    float* sz = sm + 2*NN;
    __shared__ unsigned long long swarp[32];
    __shared__ int sfar;
    int b = blockIdx.x, tid = threadIdx.x;
    const float* base = xyz + (long)b*3*NN;
    for (int i = tid; i < NN; i += 1024) {
        sx[i] = base[i];
        sy[i] = base[NN + i];
        sz[i] = base[2*NN + i];
    }
    __syncthreads();
    float dist[4];
    dist[0] = dist[1] = dist[2] = dist[3] = 1e10f;
    int far = 0;
    for (int it = 0; it < NPT; ++it) {
        if (tid == 0) fps[b*NPT + it] = far;
        float cx = sx[far], cy = sy[far], cz = sz[far];
        unsigned long long best = 0ull;
        #pragma unroll
        for (int j = 0; j < 4; ++j) {
            int n = tid + j*1024;
            float dx = sx[n]-cx, dy = sy[n]-cy, dz = sz[n]-cz;
            float d = dx*dx + dy*dy + dz*dz;
            float dd = fminf(dist[j], d);
            dist[j] = dd;
            unsigned long long key =
                ((unsigned long long)__float_as_uint(dd) << 32) |
                (unsigned long long)(0xFFFFFFFFu - (unsigned)n);
            best = (key > best) ? key : best;
        }
        #pragma unroll
        for (int off = 16; off > 0; off >>= 1) {
            unsigned long long o = __shfl_down_sync(0xFFFFFFFFu, best, off);
            best = (o > best) ? o : best;
        }
        if ((tid & 31) == 0) swarp[tid >> 5] = best;
        __syncthreads();
        if (tid < 32) {
            best = swarp[tid];
            #pragma unroll
            for (int off = 16; off > 0; off >>= 1) {
                unsigned long long o = __shfl_down_sync(0xFFFFFFFFu, best, off);
                best = (o > best) ? o : best;
            }
            if (tid == 0)
                sfar = (int)(0xFFFFFFFFu - (unsigned)(best & 0xFFFFFFFFull));
        }
        __syncthreads();
        far = sfar;
    }
}

// ---------------- new_xyz output ----------------
__global__ void newxyz_kernel(float* __restrict__ out, const float* __restrict__ xyz,
                              const int* __restrict__ fps) {
    int i = blockIdx.x*256 + threadIdx.x;
    if (i >= BB*3*NPT) return;
    int s = i & 511;
    int c = (i >> 9) % 3;
    int b = i / (3*NPT);
    out[i] = xyz[(long)b*3*NN + c*NN + fps[b*NPT + s]];
}

// ---------------- ball query ----------------
__global__ void __launch_bounds__(256) ball_kernel(const float* __restrict__ xyz,
                                                   const int* __restrict__ fps,
                                                   int* __restrict__ nbr) {
    extern __shared__ float sm[];
    float* sx = sm;
    float* sy = sm + NN;
    float* sz = sm + 2*NN;
    __shared__ int snb[8][KK];
    int b = blockIdx.y, tid = threadIdx.x;
    const float* base = xyz + (long)b*3*NN;
    for (int i = tid; i < NN; i += 256) {
        sx[i] = base[i];
        sy[i] = base[NN + i];
        sz[i] = base[2*NN + i];
    }
    __syncthreads();
    int w = tid >> 5, lane = tid & 31;
    int s = blockIdx.x*8 + w;
    int fi = fps[b*NPT + s];
    float cx = sx[fi], cy = sy[fi], cz = sz[fi];
    float cn = cx*cx + cy*cy + cz*cz;
    const float R2 = (float)(0.4*0.4);
    int cnt = 0;
    for (int n0 = 0; n0 < NN && cnt < KK; n0 += 32) {
        int n = n0 + lane;
        float px = sx[n], py = sy[n], pz = sz[n];
        float pn = px*px + py*py + pz*pz;
        float dt = cx*px + cy*py + cz*pz;
        float sq = (cn + pn) - 2.0f*dt;
        bool in = !(sq > R2);
        unsigned m = __ballot_sync(0xFFFFFFFFu, in);
        int pos = cnt + __popc(m & ((1u << lane) - 1u));
        if (in && pos < KK) snb[w][pos] = n;
        cnt += __popc(m);
    }
    __syncwarp();
    int v = (lane < cnt) ? snb[w][lane] : snb[w][0];
    nbr[(b*NPT + s)*KK + lane] = v;
}

// ---------------- feature build ----------------
__global__ void __launch_bounds__(256) feat_kernel(const float* __restrict__ points,
                                                   const float* __restrict__ xyz,
                                                   const int* __restrict__ fps,
                                                   const int* __restrict__ nbr,
                                                   float* __restrict__ X0,
                                                   float* __restrict__ relbuf) {
    int s = blockIdx.x, b = blockIdx.y, tid = threadIdx.x;
    __shared__ int snb[KK];
    __shared__ float scen[DD];
    __shared__ float scxyz[3];
    int fi = fps[b*NPT + s];
    if (tid < KK) snb[tid] = nbr[(b*NPT + s)*KK + tid];
    if (tid >= 32 && tid < 32+DD) scen[tid-32] = points[(long)b*DD*NN + (tid-32)*NN + fi];
    if (tid >= 96 && tid < 99)   scxyz[tid-96] = xyz[(long)b*3*NN + (tid-96)*NN + fi];
    __syncthreads();
    int k = tid & 31, cb = tid >> 5;
    int n = snb[k];
    int base = (b*NPT + s)*KK + k;
    #pragma unroll
    for (int q = 0; q < 8; ++q) {
        int c = q*8 + cb;
        float v = points[(long)b*DD*NN + c*NN + n];
        X0[(long)c*P_TOT + base] = v;
        X0[(long)(DD+c)*P_TOT + base] = v - scen[c];
    }
    if (cb < 3) {
        float v = xyz[(long)b*3*NN + cb*NN + n] - scxyz[cb];
        relbuf[(long)cb*P_TOT + base] = v;
    }
}

// ---------------- fused GEMM ----------------
// Y[b][coBase+co][p] = sum_k A(co,k) * x'(k,p) + bias[co]
//   x'(k,p) = XFORM ? max(fma(x, xscale[k], xshift[k]), xlo[k]) : x
//   x       = SUB ? X[k][p]-X2[k][p] : X[k][p]
// STATS: per-channel double sum/sumsq of the stored Y values via atomics.
template<int COUT, bool TRANSA, bool XFORM, bool SUB, bool STATS>
__global__ void __launch_bounds__(256)
gemm_k(const float* __restrict__ A, int lda, long aStride,
       const float* __restrict__ X, const float* __restrict__ X2, long xStride,
       float* __restrict__ Y, long yStride,
       const float* __restrict__ bias,
       const float* __restrict__ xscale, const float* __restrict__ xshift,
       const float* __restrict__ xlo,
       double* __restrict__ ssum, double* __restrict__ ssq,
       int Cin, int P)
{
    constexpr int CR = COUT / 16;
    A += (long)blockIdx.y * aStride;
    X += (long)blockIdx.y * xStride;
    if (SUB) X2 += (long)blockIdx.y * xStride;
    Y += (long)blockIdx.y * yStride;
    int coBase = blockIdx.z * COUT;
    int p0 = blockIdx.x * 128;
    int tid = threadIdx.x;
    int tx = tid & 15, ty = tid >> 4;

    __shared__ float sX[32][132];
    __shared__ float sW[32][COUT + 4];

    float acc[8][CR];
    #pragma unroll
    for (int i = 0; i < 8; ++i)
        #pragma unroll
        for (int j = 0; j < CR; ++j) acc[i][j] = 0.f;

    for (int k0 = 0; k0 < Cin; k0 += 32) {
        int kc = min(32, Cin - k0);
        for (int i = tid; i < kc*128; i += 256) {
            int kk = i >> 7, pp = i & 127;
            long idx = (long)(k0+kk)*P + p0 + pp;
            float v = X[idx];
            if (SUB) v -= X2[idx];
            if (XFORM) v = fmaxf(fmaf(v, xscale[k0+kk], xshift[k0+kk]), xlo[k0+kk]);
            sX[kk][pp] = v;
        }
        for (int i = tid; i < kc*COUT; i += 256) {
            int kk = i / COUT, co = i % COUT;
            sW[kk][co] = TRANSA ? A[(long)(k0+kk)*lda + coBase + co]
                                : A[(long)(coBase+co)*lda + (k0+kk)];
        }
        __syncthreads();
        #pragma unroll 4
        for (int kk = 0; kk < kc; ++kk) {
            float4 xa = *reinterpret_cast<const float4*>(&sX[kk][tx*8]);
            float4 xb = *reinterpret_cast<const float4*>(&sX[kk][tx*8 + 4]);
            float xv[8] = {xa.x, xa.y, xa.z, xa.w, xb.x, xb.y, xb.z, xb.w};
            float wv[CR];
            #pragma unroll
            for (int j = 0; j < CR; j += 4) {
                float4 w4 = *reinterpret_cast<const float4*>(&sW[kk][ty*CR + j]);
                wv[j] = w4.x; wv[j+1] = w4.y; wv[j+2] = w4.z; wv[j+3] = w4.w;
            }
            #pragma unroll
            for (int i = 0; i < 8; ++i)
                #pragma unroll
                for (int j = 0; j < CR; ++j)
                    acc[i][j] = fmaf(xv[i], wv[j], acc[i][j]);
        }
        __syncthreads();
    }
    #pragma unroll
    for (int j = 0; j < CR; ++j) {
        int co = coBase + ty*CR + j;
        float bb = bias ? bias[co] : 0.f;
        float o[8];
        #pragma unroll
        for (int i = 0; i < 8; ++i) o[i] = acc[i][j] + bb;
        float4 o0 = make_float4(o[0], o[1], o[2], o[3]);
        float4 o1 = make_float4(o[4], o[5], o[6], o[7]);
        float* yp = Y + (long)co*P + p0 + tx*8;
        *reinterpret_cast<float4*>(yp)     = o0;
        *reinterpret_cast<float4*>(yp + 4) = o1;
        if (STATS) {
            double s = 0.0, q = 0.0;
            #pragma unroll
            for (int i = 0; i < 8; ++i) {
                double v = (double)o[i];
                s += v; q += v*v;
            }
            #pragma unroll
            for (int off = 8; off > 0; off >>= 1) {
                s += __shfl_down_sync(0xFFFFFFFFu, s, off, 16);
                q += __shfl_down_sync(0xFFFFFFFFu, q, off, 16);
            }
            if (tx == 0) {
                atomicAdd(&ssum[co], s);
                atomicAdd(&ssq[co], q);
            }
        }
    }
}

// ---------------- finalize BN -> affine transform ----------------
__global__ void finalize_bn(const double* __restrict__ ssum, const double* __restrict__ ssq,
                            int Cbn, double count,
                            const float* __restrict__ g, const float* __restrict__ be,
                            float* __restrict__ scale, float* __restrict__ shift,
                            float* __restrict__ lo) {
    int c = threadIdx.x;
    if (c < Cbn) {
        double m = ssum[c] / count;
        double v = ssq[c] / count - m*m;
        float sc = g[c] * rsqrtf((float)v + EPSF);
        scale[c] = sc;
        shift[c] = be[c] - (float)m * sc;
        lo[c] = 0.f;
    } else {
        scale[c] = 1.f;
        shift[c] = 0.f;
        lo[c] = -3.4e38f;
    }
}

// ---------------- maxpool over K (fused BN+ReLU) ----------------
__global__ void maxpool_kernel(const float* __restrict__ X, float* __restrict__ xp,
                               const float* __restrict__ scale,
                               const float* __restrict__ shift) {
    int i = blockIdx.x*256 + threadIdx.x;
    if (i >= BB*128*NPT) return;
    int s = i & 511, c = (i >> 9) & 127, b = i >> 16;
    const float* p = X + (long)c*P_TOT + (b*NPT + s)*KK;
    float sc = scale[c], sh = shift[c];
    float m = 0.f;  // relu output is >= 0, max over K>=1 elements >= 0... careful: max of relu'd values, all >=0, so init 0 valid only if at least one element; K=32 always. But must equal max of relu values: relu>=0 so init -inf then relu clamps; init 0 is exactly min possible value. Safe.
    m = -3.4e38f;
    #pragma unroll
    for (int k = 0; k < KK; ++k) {
        float v = fmaxf(fmaf(p[k], sc, sh), 0.f);
        m = fmaxf(m, v);
    }
    xp[i] = m;
}

// ---------------- softmax rows ----------------
__global__ void softmax_kernel(float* __restrict__ e) {
    int gw = (blockIdx.x*256 + threadIdx.x) >> 5;
    int lane = threadIdx.x & 31;
    if (gw >= BB*NPT) return;
    float* row = e + (long)gw * NPT;
    float v[16];
    float mx = -3.4e38f;
    #pragma unroll
    for (int i = 0; i < 16; ++i) { v[i] = row[lane + i*32]; mx = fmaxf(mx, v[i]); }
    #pragma unroll
    for (int off = 16; off > 0; off >>= 1)
        mx = fmaxf(mx, __shfl_xor_sync(0xFFFFFFFFu, mx, off));
    float sum = 0.f;
    #pragma unroll
    for (int i = 0; i < 16; ++i) { v[i] = expf(v[i] - mx); sum += v[i]; }
    #pragma unroll
    for (int off = 16; off > 0; off >>= 1)
        sum += __shfl_xor_sync(0xFFFFFFFFu, sum, off);
    #pragma unroll
    for (int i = 0; i < 16; ++i) row[lane + i*32] = v[i] / sum;
}

// ---------------- column sum + normalize ----------------
__global__ void colsum_kernel(const float* __restrict__ e, float* __restrict__ colsum) {
    int b = blockIdx.x, m = blockIdx.y*128 + threadIdx.x;
    const float* E = e + (long)b * NPT * NPT;
    float s = 0.f;
    for (int n = 0; n < NPT; ++n) s += E[n*NPT + m];
    colsum[b*NPT + m] = 1e-9f + s;
}
__global__ void colnorm_apply(float* __restrict__ e, const float* __restrict__ colsum) {
    long i = (long)blockIdx.x*256 + threadIdx.x;
    if (i >= (long)BB*NPT*NPT) return;
    int m = (int)(i & (NPT-1));
    int b = (int)(i >> 18);         // NPT*NPT = 2^18
    e[i] = e[i] / colsum[b*NPT + m];
}

// ---------------- final residual ----------------
__global__ void final_kernel(float* __restrict__ out, const float* __restrict__ xp,
                             const float* __restrict__ y,
                             const float* __restrict__ scale, const float* __restrict__ shift,
                             const float* __restrict__ alpha, const float* __restrict__ beta) {
    int i = blockIdx.x*256 + threadIdx.x;
    if (i >= BB*128*NPT) return;
    int c = (i >> 9) & 127;
    float xr = fmaxf(fmaf(y[i], scale[c], shift[c]), 0.f);
    out[i] = xp[i] + alpha[c]*xr + beta[c];
}

// ---------------- launch ----------------
extern "C" void kernel_launch(void* const* d_in, const int* in_sizes, int n_in,
                              void* d_out, int out_size) {
    const float* xyz    = (const float*)d_in[0];
    const float* points = (const float*)d_in[1];
    const float* w0 = (const float*)d_in[2];
    const float* b0 = (const float*)d_in[3];
    const float* g0 = (const float*)d_in[4];
    const float* be0= (const float*)d_in[5];
    const float* w1 = (const float*)d_in[6];
    const float* b1 = (const float*)d_in[7];
    const float* g1 = (const float*)d_in[8];
    const float* be1= (const float*)d_in[9];
    const float* w2 = (const float*)d_in[10];
    const float* b2 = (const float*)d_in[11];
    const float* g2 = (const float*)d_in[12];
    const float* be2= (const float*)d_in[13];
    const float* wl = (const float*)d_in[14];
    const float* bl = (const float*)d_in[15];
    const float* gl = (const float*)d_in[16];
    const float* bel= (const float*)d_in[17];
    const float* wv = (const float*)d_in[18];
    const float* bv = (const float*)d_in[19];
    const float* wt = (const float*)d_in[20];
    const float* bt = (const float*)d_in[21];
    const float* gn = (const float*)d_in[22];
    const float* gb = (const float*)d_in[23];
    const float* alpha = (const float*)d_in[24];
    const float* beta  = (const float*)d_in[25];
    float* out = (float*)d_out;

    float *bufA, *bufB, *xp, *x0, *energy, *x2, *y, *tfs, *tfh, *tfl, *colsum;
    double *ssum, *ssq;
    int *fps, *nbr;
    cudaGetSymbolAddress((void**)&bufA, g_bufA);
    cudaGetSymbolAddress((void**)&bufB, g_bufB);
    cudaGetSymbolAddress((void**)&xp, g_xp);
    cudaGetSymbolAddress((void**)&x0, g_x0);
    cudaGetSymbolAddress((void**)&energy, g_energy);
    cudaGetSymbolAddress((void**)&x2, g_x2);
    cudaGetSymbolAddress((void**)&y, g_y);
    cudaGetSymbolAddress((void**)&ssum, g_ssum);
    cudaGetSymbolAddress((void**)&ssq, g_ssq);
    cudaGetSymbolAddress((void**)&tfs, g_tfs);
    cudaGetSymbolAddress((void**)&tfh, g_tfh);
    cudaGetSymbolAddress((void**)&tfl, g_tfl);
    cudaGetSymbolAddress((void**)&colsum, g_colsum);
    cudaGetSymbolAddress((void**)&fps, g_fps);
    cudaGetSymbolAddress((void**)&nbr, g_nbr);

    const int SMEM_PTS = 3*NN*sizeof(float);   // 48KB
    cudaFuncSetAttribute(fps_kernel,  cudaFuncAttributeMaxDynamicSharedMemorySize, 64*1024);
    cudaFuncSetAttribute(ball_kernel, cudaFuncAttributeMaxDynamicSharedMemorySize, 64*1024);

    zero_stats<<<3, 256>>>();

    // geometry
    fps_kernel<<<BB, 1024, SMEM_PTS>>>(xyz, fps);
    newxyz_kernel<<<(BB*3*NPT + 255)/256, 256>>>(out, xyz, fps);
    ball_kernel<<<dim3(NPT/8, BB), 256, SMEM_PTS>>>(xyz, fps, nbr);
    feat_kernel<<<dim3(NPT, BB), 256>>>(points, xyz, fps, nbr, bufB, bufA + 128L*P_TOT);

    const double CNT_P = (double)P_TOT;
    const double CNT_S = (double)(BB*NPT);

    // L0: 128->64, stats slot0
    gemm_k<64,false,false,false,true><<<dim3(P_TOT/128,1,1), 256>>>(
        w0, 128, 0, bufB, nullptr, 0, bufA, 0, b0,
        nullptr, nullptr, nullptr, ssum+0, ssq+0, 128, P_TOT);
    finalize_bn<<<1, 64>>>(ssum+0, ssq+0, 64, CNT_P, g0, be0, tfs+0, tfh+0, tfl+0);

    // L1: 64->64, input xform tf0, stats slot1
    gemm_k<64,false,true,false,true><<<dim3(P_TOT/128,1,1), 256>>>(
        w1, 64, 0, bufA, nullptr, 0, bufB, 0, b1,
        tfs+0, tfh+0, tfl+0, ssum+128, ssq+128, 64, P_TOT);
    finalize_bn<<<1, 64>>>(ssum+128, ssq+128, 64, CNT_P, g1, be1, tfs+132, tfh+132, tfl+132);

    // L2: 64->128, input xform tf1, stats slot2
    gemm_k<128,false,true,false,true><<<dim3(P_TOT/128,1,1), 256>>>(
        w2, 64, 0, bufB, nullptr, 0, bufA, 0, b2,
        tfs+132, tfh+132, tfl+132, ssum+256, ssq+256, 64, P_TOT);
    // finalize for 131 channels (128 BN + 3 passthrough rel_xyz)
    finalize_bn<<<1, 131>>>(ssum+256, ssq+256, 128, CNT_P, g2, be2, tfs+264, tfh+264, tfl+264);

    // Ll: 131->128, input xform tf2, stats slot3
    gemm_k<128,false,true,false,true><<<dim3(P_TOT/128,1,1), 256>>>(
        wl, 131, 0, bufA, nullptr, 0, bufB, 0, bl,
        tfs+264, tfh+264, tfl+264, ssum+384, ssq+384, 131, P_TOT);
    finalize_bn<<<1, 128>>>(ssum+384, ssq+384, 128, CNT_P, gl, bel, tfs+396, tfh+396, tfl+396);

    // pool over K with fused BN+ReLU
    maxpool_kernel<<<(BB*128*NPT + 255)/256, 256>>>(bufB, xp, tfs+396, tfh+396);

    // attention
    gemm_k<128,false,false,false,false><<<dim3(NPT/128, BB, 1), 256>>>(
        wv, 128, 0, xp, nullptr, PB, x0, PB, bv,
        nullptr, nullptr, nullptr, nullptr, nullptr, 128, NPT);
    gemm_k<128,true,false,false,false><<<dim3(NPT/128, BB, 4), 256>>>(
        xp, NPT, PB, x0, nullptr, PB, energy, (long)NPT*NPT, nullptr,
        nullptr, nullptr, nullptr, nullptr, nullptr, 128, NPT);
    softmax_kernel<<<(BB*NPT*32 + 255)/256, 256>>>(energy);
    colsum_kernel<<<dim3(BB, NPT/128), 128>>>(energy, colsum);
    colnorm_apply<<<(int)(((long)BB*NPT*NPT + 255)/256), 256>>>(energy, colsum);
    gemm_k<128,false,false,false,false><<<dim3(NPT/128, BB, 1), 256>>>(
        x0, NPT, PB, energy, nullptr, (long)NPT*NPT, x2, PB, nullptr,
        nullptr, nullptr, nullptr, nullptr, nullptr, NPT, NPT);

    // wt GEMM on (xp - x2), stats slot4 (bn1d over B*NPT)
    gemm_k<128,false,false,true,true><<<dim3(NPT/128, BB, 1), 256>>>(
        wt, 128, 0, xp, x2, PB, y, PB, bt,
        nullptr, nullptr, nullptr, ssum+512, ssq+512, 128, NPT);
    finalize_bn<<<1, 128>>>(ssum+512, ssq+512, 128, CNT_S, gn, gb, tfs+528, tfh+528, tfl+528);

    final_kernel<<<(BB*128*NPT + 255)/256, 256>>>(out + BB*3*NPT, xp, y,
        tfs+528, tfh+528, alpha, beta);
}

// round 4
// speedup vs baseline: 1.4063x; 1.1393x over previous
#include <cuda_runtime.h>
#include <cuda_bf16.h>
#include <cstdint>
#include <math.h>

// ---------------- constants ----------------
#define BB   16
#define NN   4096
#define DD   64
#define NPT  512
#define KK   32
#define P_TOT (BB*NPT*KK)     // 262144
#define PB   (128*NPT)        // 65536 per-batch (c,s) block
#define EPSF 1e-5f

// ---------------- scratch ----------------
__device__ float g_bufA[131L * P_TOT];          // 131 x P  (rows 128..130 = rel_xyz)
__device__ float g_bufB[128L * P_TOT];          // 128 x P
__device__ float g_xp[BB*128*NPT];
__device__ float g_x0[BB*128*NPT];
__device__ float g_energy[BB*NPT*NPT];
__device__ float g_x2[BB*128*NPT];
__device__ float g_y[BB*128*NPT];
__device__ double g_ssum[5*128];
__device__ double g_ssq[5*128];
__device__ float g_tfs[5*132];
__device__ float g_tfh[5*132];
__device__ float g_tfl[5*132];
__device__ float g_colrcp[BB*NPT];
__device__ int   g_fps[BB*NPT];
__device__ int   g_nbr[BB*NPT*KK];

// ---------------- zero stats ----------------
__global__ void zero_stats() {
    int i = blockIdx.x*256 + threadIdx.x;
    if (i < 5*128) { g_ssum[i] = 0.0; g_ssq[i] = 0.0; }
}

// ---------------- FPS ----------------
__global__ void __launch_bounds__(1024) fps_kernel(const float* __restrict__ xyz,
                                                   int* __restrict__ fps) {
    extern __shared__ float sm[];
    float* sx = sm;
    float* sy = sm + NN;
    float* sz = sm + 2*NN;
    __shared__ unsigned long long swarp[32];
    __shared__ int sfar;
    int b = blockIdx.x, tid = threadIdx.x;
    const float* base = xyz + (long)b*3*NN;
    for (int i = tid; i < NN; i += 1024) {
        sx[i] = base[i];
        sy[i] = base[NN + i];
        sz[i] = base[2*NN + i];
    }
    __syncthreads();
    float dist[4];
    dist[0] = dist[1] = dist[2] = dist[3] = 1e10f;
    int far = 0;
    for (int it = 0; it < NPT; ++it) {
        if (tid == 0) fps[b*NPT + it] = far;
        float cx = sx[far], cy = sy[far], cz = sz[far];
        unsigned long long best = 0ull;
        #pragma unroll
        for (int j = 0; j < 4; ++j) {
            int n = tid + j*1024;
            float dx = sx[n]-cx, dy = sy[n]-cy, dz = sz[n]-cz;
            float d = dx*dx + dy*dy + dz*dz;
            float dd = fminf(dist[j], d);
            dist[j] = dd;
            unsigned long long key =
                ((unsigned long long)__float_as_uint(dd) << 32) |
                (unsigned long long)(0xFFFFFFFFu - (unsigned)n);
            best = (key > best) ? key : best;
        }
        #pragma unroll
        for (int off = 16; off > 0; off >>= 1) {
            unsigned long long o = __shfl_down_sync(0xFFFFFFFFu, best, off);
            best = (o > best) ? o : best;
        }
        if ((tid & 31) == 0) swarp[tid >> 5] = best;
        __syncthreads();
        if (tid < 32) {
            best = swarp[tid];
            #pragma unroll
            for (int off = 16; off > 0; off >>= 1) {
                unsigned long long o = __shfl_down_sync(0xFFFFFFFFu, best, off);
                best = (o > best) ? o : best;
            }
            if (tid == 0)
                sfar = (int)(0xFFFFFFFFu - (unsigned)(best & 0xFFFFFFFFull));
        }
        __syncthreads();
        far = sfar;
    }
}

// ---------------- new_xyz output ----------------
__global__ void newxyz_kernel(float* __restrict__ out, const float* __restrict__ xyz,
                              const int* __restrict__ fps) {
    int i = blockIdx.x*256 + threadIdx.x;
    if (i >= BB*3*NPT) return;
    int s = i & 511;
    int c = (i >> 9) % 3;
    int b = i / (3*NPT);
    out[i] = xyz[(long)b*3*NN + c*NN + fps[b*NPT + s]];
}

// ---------------- ball query ----------------
__global__ void __launch_bounds__(256) ball_kernel(const float* __restrict__ xyz,
                                                   const int* __restrict__ fps,
                                                   int* __restrict__ nbr) {
    extern __shared__ float sm[];
    float* sx = sm;
    float* sy = sm + NN;
    float* sz = sm + 2*NN;
    __shared__ int snb[8][KK];
    int b = blockIdx.y, tid = threadIdx.x;
    const float* base = xyz + (long)b*3*NN;
    for (int i = tid; i < NN; i += 256) {
        sx[i] = base[i];
        sy[i] = base[NN + i];
        sz[i] = base[2*NN + i];
    }
    __syncthreads();
    int w = tid >> 5, lane = tid & 31;
    int s = blockIdx.x*8 + w;
    int fi = fps[b*NPT + s];
    float cx = sx[fi], cy = sy[fi], cz = sz[fi];
    float cn = cx*cx + cy*cy + cz*cz;
    const float R2 = (float)(0.4*0.4);
    int cnt = 0;
    for (int n0 = 0; n0 < NN && cnt < KK; n0 += 32) {
        int n = n0 + lane;
        float px = sx[n], py = sy[n], pz = sz[n];
        float pn = px*px + py*py + pz*pz;
        float dt = cx*px + cy*py + cz*pz;
        float sq = (cn + pn) - 2.0f*dt;
        bool in = !(sq > R2);
        unsigned m = __ballot_sync(0xFFFFFFFFu, in);
        int pos = cnt + __popc(m & ((1u << lane) - 1u));
        if (in && pos < KK) snb[w][pos] = n;
        cnt += __popc(m);
    }
    __syncwarp();
    int v = (lane < cnt) ? snb[w][lane] : snb[w][0];
    nbr[(b*NPT + s)*KK + lane] = v;
}

// ---------------- feature build ----------------
__global__ void __launch_bounds__(256) feat_kernel(const float* __restrict__ points,
                                                   const float* __restrict__ xyz,
                                                   const int* __restrict__ fps,
                                                   const int* __restrict__ nbr,
                                                   float* __restrict__ X0,
                                                   float* __restrict__ relbuf) {
    int s = blockIdx.x, b = blockIdx.y, tid = threadIdx.x;
    __shared__ int snb[KK];
    __shared__ float scen[DD];
    __shared__ float scxyz[3];
    int fi = fps[b*NPT + s];
    if (tid < KK) snb[tid] = nbr[(b*NPT + s)*KK + tid];
    if (tid >= 32 && tid < 32+DD) scen[tid-32] = points[(long)b*DD*NN + (tid-32)*NN + fi];
    if (tid >= 96 && tid < 99)   scxyz[tid-96] = xyz[(long)b*3*NN + (tid-96)*NN + fi];
    __syncthreads();
    int k = tid & 31, cb = tid >> 5;
    int n = snb[k];
    int base = (b*NPT + s)*KK + k;
    #pragma unroll
    for (int q = 0; q < 8; ++q) {
        int c = q*8 + cb;
        float v = points[(long)b*DD*NN + c*NN + n];
        X0[(long)c*P_TOT + base] = v;
        X0[(long)(DD+c)*P_TOT + base] = v - scen[c];
    }
    if (cb < 3) {
        float v = xyz[(long)b*3*NN + cb*NN + n] - scxyz[cb];
        relbuf[(long)cb*P_TOT + base] = v;
    }
}

// ---------------- tf32 helpers ----------------
__device__ __forceinline__ uint32_t f2tf32(float v) {
    uint32_t r;
    asm("cvt.rna.tf32.f32 %0, %1;" : "=r"(r) : "f"(v));
    return r;
}
__device__ __forceinline__ void mma_tf32(float* d, uint32_t a0, uint32_t a1,
                                         uint32_t a2, uint32_t a3,
                                         uint32_t b0, uint32_t b1) {
    asm volatile("mma.sync.aligned.m16n8k8.row.col.f32.tf32.tf32.f32 "
        "{%0,%1,%2,%3},{%4,%5,%6,%7},{%8,%9},{%0,%1,%2,%3};"
        : "+f"(d[0]), "+f"(d[1]), "+f"(d[2]), "+f"(d[3])
        : "r"(a0), "r"(a1), "r"(a2), "r"(a3), "r"(b0), "r"(b1));
}

// ---------------- tensor-core fused GEMM ----------------
// Y[b][coBase+co][p] = sum_k A(co,k) * x'(k,p) + bias[co]
//   A(co,k) = TRANSA ? A[k*lda+co_glob] : A[co_glob*lda+k]
//   x'(k,p) = XFORM ? max(fma(x, xscale[k], xshift[k]), xlo[k]) : x
//   x       = (SUB ? X[k][p]-X2[k][p] : X[k][p]) * (PSCALE ? pscale[p] : 1)
// STATS: per-channel double sum/sumsq of stored Y via atomics.
template<int COUT, bool TRANSA, bool XFORM, bool SUB, bool PSCALE, bool STATS>
__global__ void __launch_bounds__(256)
gemm_tc(const float* __restrict__ A, int lda, long aStride,
        const float* __restrict__ X, const float* __restrict__ X2, long xStride,
        const float* __restrict__ pscale, int psStride,
        float* __restrict__ Y, long yStride,
        const float* __restrict__ bias,
        const float* __restrict__ xscale, const float* __restrict__ xshift,
        const float* __restrict__ xlo,
        double* __restrict__ ssum, double* __restrict__ ssq,
        int Cin, int P)
{
    constexpr int MW = COUT / 4;     // warp tile M
    constexpr int MF = MW / 16;      // m16 fragments per warp
    __shared__ uint32_t sX[32*136];
    __shared__ uint32_t sW[COUT*36];

    int by = blockIdx.y;
    A += (long)by * aStride;
    X += (long)by * xStride;
    if (SUB) X2 += (long)by * xStride;
    Y += (long)by * yStride;
    int coBase = blockIdx.z * COUT;
    int p0 = blockIdx.x * 128;
    const float* psc = PSCALE ? (pscale + (long)by*psStride + p0) : nullptr;

    int tid = threadIdx.x;
    int lane = tid & 31, wid = tid >> 5;
    int warpM = wid >> 1, warpN = wid & 1;
    int gid = lane >> 2, tig = lane & 3;

    float d[MF][8][4];
    #pragma unroll
    for (int mf = 0; mf < MF; ++mf)
        #pragma unroll
        for (int nf = 0; nf < 8; ++nf)
            #pragma unroll
            for (int i = 0; i < 4; ++i) d[mf][nf][i] = 0.f;

    int nchunk = (Cin + 31) >> 5;
    for (int c0 = 0; c0 < nchunk; ++c0) {
        int k0 = c0 * 32;
        // stage X tile
        for (int i = tid; i < 32*128; i += 256) {
            int kk = i >> 7, pp = i & 127;
            int k = k0 + kk;
            float v = 0.f;
            if (k < Cin) {
                long idx = (long)k*P + p0 + pp;
                v = X[idx];
                if (SUB) v -= X2[idx];
                if (XFORM) v = fmaxf(fmaf(v, xscale[k], xshift[k]), xlo[k]);
                if (PSCALE) v *= psc[pp];
            }
            sX[kk*136 + pp] = f2tf32(v);
        }
        // stage W tile
        for (int i = tid; i < COUT*32; i += 256) {
            int co = i >> 5, kk = i & 31;
            int k = k0 + kk;
            float w = 0.f;
            if (k < Cin)
                w = TRANSA ? A[(long)k*lda + coBase + co]
                           : A[(long)(coBase + co)*lda + k];
            sW[co*36 + kk] = f2tf32(w);
        }
        __syncthreads();
        #pragma unroll
        for (int k8 = 0; k8 < 4; ++k8) {
            int kb = k8*8;
            uint32_t a[MF][4];
            #pragma unroll
            for (int mf = 0; mf < MF; ++mf) {
                int r = warpM*MW + mf*16 + gid;
                a[mf][0] = sW[r*36 + kb + tig];
                a[mf][1] = sW[(r+8)*36 + kb + tig];
                a[mf][2] = sW[r*36 + kb + tig + 4];
                a[mf][3] = sW[(r+8)*36 + kb + tig + 4];
            }
            #pragma unroll
            for (int nf = 0; nf < 8; ++nf) {
                int col = warpN*64 + nf*8 + gid;
                uint32_t b0 = sX[(kb + tig)*136 + col];
                uint32_t b1 = sX[(kb + tig + 4)*136 + col];
                #pragma unroll
                for (int mf = 0; mf < MF; ++mf)
                    mma_tf32(d[mf][nf], a[mf][0], a[mf][1], a[mf][2], a[mf][3], b0, b1);
            }
        }
        __syncthreads();
    }

    // epilogue
    #pragma unroll
    for (int mf = 0; mf < MF; ++mf) {
        int r = warpM*MW + mf*16 + gid;
        int co0 = coBase + r, co1 = co0 + 8;
        float bb0 = bias ? bias[co0] : 0.f;
        float bb1 = bias ? bias[co1] : 0.f;
        double s0 = 0.0, q0 = 0.0, s1 = 0.0, q1 = 0.0;
        #pragma unroll
        for (int nf = 0; nf < 8; ++nf) {
            int p = p0 + warpN*64 + nf*8 + 2*tig;
            float o0 = d[mf][nf][0] + bb0, o1 = d[mf][nf][1] + bb0;
            float o2 = d[mf][nf][2] + bb1, o3 = d[mf][nf][3] + bb1;
            *reinterpret_cast<float2*>(&Y[(long)co0*P + p]) = make_float2(o0, o1);
            *reinterpret_cast<float2*>(&Y[(long)co1*P + p]) = make_float2(o2, o3);
            if (STATS) {
                s0 += (double)o0 + (double)o1;
                q0 += (double)o0*o0 + (double)o1*o1;
                s1 += (double)o2 + (double)o3;
                q1 += (double)o2*o2 + (double)o3*o3;
            }
        }
        if (STATS) {
            #pragma unroll
            for (int off = 1; off <= 2; off <<= 1) {
                s0 += __shfl_xor_sync(0xFFFFFFFFu, s0, off);
                q0 += __shfl_xor_sync(0xFFFFFFFFu, q0, off);
                s1 += __shfl_xor_sync(0xFFFFFFFFu, s1, off);
                q1 += __shfl_xor_sync(0xFFFFFFFFu, q1, off);
            }
            if (tig == 0) {
                atomicAdd(&ssum[co0], s0);
                atomicAdd(&ssq[co0], q0);
                atomicAdd(&ssum[co1], s1);
                atomicAdd(&ssq[co1], q1);
            }
        }
    }
}

// ---------------- finalize BN -> affine ----------------
__global__ void finalize_bn(const double* __restrict__ ssum, const double* __restrict__ ssq,
                            int Cbn, double count,
                            const float* __restrict__ g, const float* __restrict__ be,
                            float* __restrict__ scale, float* __restrict__ shift,
                            float* __restrict__ lo) {
    int c = threadIdx.x;
    if (c < Cbn) {
        double m = ssum[c] / count;
        double v = ssq[c] / count - m*m;
        float sc = g[c] * rsqrtf((float)v + EPSF);
        scale[c] = sc;
        shift[c] = be[c] - (float)m * sc;
        lo[c] = 0.f;
    } else {
        scale[c] = 1.f;
        shift[c] = 0.f;
        lo[c] = -3.4e38f;
    }
}

// ---------------- maxpool over K (fused BN+ReLU) ----------------
__global__ void maxpool_kernel(const float* __restrict__ X, float* __restrict__ xp,
                               const float* __restrict__ scale,
                               const float* __restrict__ shift) {
    int i = blockIdx.x*256 + threadIdx.x;
    if (i >= BB*128*NPT) return;
    int s = i & 511, c = (i >> 9) & 127, b = i >> 16;
    const float* p = X + (long)c*P_TOT + (b*NPT + s)*KK;
    float sc = scale[c], sh = shift[c];
    float m = -3.4e38f;
    #pragma unroll
    for (int k = 0; k < KK; ++k) {
        float v = fmaxf(fmaf(p[k], sc, sh), 0.f);
        m = fmaxf(m, v);
    }
    xp[i] = m;
}

// ---------------- softmax rows ----------------
__global__ void softmax_kernel(float* __restrict__ e) {
    int gw = (blockIdx.x*256 + threadIdx.x) >> 5;
    int lane = threadIdx.x & 31;
    if (gw >= BB*NPT) return;
    float* row = e + (long)gw * NPT;
    float v[16];
    float mx = -3.4e38f;
    #pragma unroll
    for (int i = 0; i < 16; ++i) { v[i] = row[lane + i*32]; mx = fmaxf(mx, v[i]); }
    #pragma unroll
    for (int off = 16; off > 0; off >>= 1)
        mx = fmaxf(mx, __shfl_xor_sync(0xFFFFFFFFu, mx, off));
    float sum = 0.f;
    #pragma unroll
    for (int i = 0; i < 16; ++i) { v[i] = expf(v[i] - mx); sum += v[i]; }
    #pragma unroll
    for (int off = 16; off > 0; off >>= 1)
        sum += __shfl_xor_sync(0xFFFFFFFFu, sum, off);
    #pragma unroll
    for (int i = 0; i < 16; ++i) row[lane + i*32] = v[i] / sum;
}

// ---------------- column sums (store reciprocal) ----------------
__global__ void colsum_kernel(const float* __restrict__ e, float* __restrict__ colrcp) {
    int b = blockIdx.x, m = blockIdx.y*128 + threadIdx.x;
    const float* E = e + (long)b * NPT * NPT;
    float s = 0.f;
    for (int n = 0; n < NPT; ++n) s += E[n*NPT + m];
    colrcp[b*NPT + m] = 1.f / (1e-9f + s);
}

// ---------------- final residual ----------------
__global__ void final_kernel(float* __restrict__ out, const float* __restrict__ xp,
                             const float* __restrict__ y,
                             const float* __restrict__ scale, const float* __restrict__ shift,
                             const float* __restrict__ alpha, const float* __restrict__ beta) {
    int i = blockIdx.x*256 + threadIdx.x;
    if (i >= BB*128*NPT) return;
    int c = (i >> 9) & 127;
    float xr = fmaxf(fmaf(y[i], scale[c], shift[c]), 0.f);
    out[i] = xp[i] + alpha[c]*xr + beta[c];
}

// ---------------- launch ----------------
extern "C" void kernel_launch(void* const* d_in, const int* in_sizes, int n_in,
                              void* d_out, int out_size) {
    const float* xyz    = (const float*)d_in[0];
    const float* points = (const float*)d_in[1];
    const float* w0 = (const float*)d_in[2];
    const float* b0 = (const float*)d_in[3];
    const float* g0 = (const float*)d_in[4];
    const float* be0= (const float*)d_in[5];
    const float* w1 = (const float*)d_in[6];
    const float* b1 = (const float*)d_in[7];
    const float* g1 = (const float*)d_in[8];
    const float* be1= (const float*)d_in[9];
    const float* w2 = (const float*)d_in[10];
    const float* b2 = (const float*)d_in[11];
    const float* g2 = (const float*)d_in[12];
    const float* be2= (const float*)d_in[13];
    const float* wl = (const float*)d_in[14];
    const float* bl = (const float*)d_in[15];
    const float* gl = (const float*)d_in[16];
    const float* bel= (const float*)d_in[17];
    const float* wv = (const float*)d_in[18];
    const float* bv = (const float*)d_in[19];
    const float* wt = (const float*)d_in[20];
    const float* bt = (const float*)d_in[21];
    const float* gn = (const float*)d_in[22];
    const float* gb = (const float*)d_in[23];
    const float* alpha = (const float*)d_in[24];
    const float* beta  = (const float*)d_in[25];
    float* out = (float*)d_out;

    float *bufA, *bufB, *xp, *x0, *energy, *x2, *y, *tfs, *tfh, *tfl, *colrcp;
    double *ssum, *ssq;
    int *fps, *nbr;
    cudaGetSymbolAddress((void**)&bufA, g_bufA);
    cudaGetSymbolAddress((void**)&bufB, g_bufB);
    cudaGetSymbolAddress((void**)&xp, g_xp);
    cudaGetSymbolAddress((void**)&x0, g_x0);
    cudaGetSymbolAddress((void**)&energy, g_energy);
    cudaGetSymbolAddress((void**)&x2, g_x2);
    cudaGetSymbolAddress((void**)&y, g_y);
    cudaGetSymbolAddress((void**)&ssum, g_ssum);
    cudaGetSymbolAddress((void**)&ssq, g_ssq);
    cudaGetSymbolAddress((void**)&tfs, g_tfs);
    cudaGetSymbolAddress((void**)&tfh, g_tfh);
    cudaGetSymbolAddress((void**)&tfl, g_tfl);
    cudaGetSymbolAddress((void**)&colrcp, g_colrcp);
    cudaGetSymbolAddress((void**)&fps, g_fps);
    cudaGetSymbolAddress((void**)&nbr, g_nbr);

    const int SMEM_PTS = 3*NN*sizeof(float);   // 48KB
    cudaFuncSetAttribute(fps_kernel,  cudaFuncAttributeMaxDynamicSharedMemorySize, 64*1024);
    cudaFuncSetAttribute(ball_kernel, cudaFuncAttributeMaxDynamicSharedMemorySize, 64*1024);

    zero_stats<<<3, 256>>>();

    // geometry
    fps_kernel<<<BB, 1024, SMEM_PTS>>>(xyz, fps);
    newxyz_kernel<<<(BB*3*NPT + 255)/256, 256>>>(out, xyz, fps);
    ball_kernel<<<dim3(NPT/8, BB), 256, SMEM_PTS>>>(xyz, fps, nbr);
    feat_kernel<<<dim3(NPT, BB), 256>>>(points, xyz, fps, nbr, bufB, bufA + 128L*P_TOT);

    const double CNT_P = (double)P_TOT;
    const double CNT_S = (double)(BB*NPT);

    // L0: 128->64, stats slot0
    gemm_tc<64,false,false,false,false,true><<<dim3(P_TOT/128,1,1), 256>>>(
        w0, 128, 0, bufB, nullptr, 0, nullptr, 0, bufA, 0, b0,
        nullptr, nullptr, nullptr, ssum+0, ssq+0, 128, P_TOT);
    finalize_bn<<<1, 64>>>(ssum+0, ssq+0, 64, CNT_P, g0, be0, tfs+0, tfh+0, tfl+0);

    // L1: 64->64, xform tf0, stats slot1
    gemm_tc<64,false,true,false,false,true><<<dim3(P_TOT/128,1,1), 256>>>(
        w1, 64, 0, bufA, nullptr, 0, nullptr, 0, bufB, 0, b1,
        tfs+0, tfh+0, tfl+0, ssum+128, ssq+128, 64, P_TOT);
    finalize_bn<<<1, 64>>>(ssum+128, ssq+128, 64, CNT_P, g1, be1, tfs+132, tfh+132, tfl+132);

    // L2: 64->128, xform tf1, stats slot2
    gemm_tc<128,false,true,false,false,true><<<dim3(P_TOT/128,1,1), 256>>>(
        w2, 64, 0, bufB, nullptr, 0, nullptr, 0, bufA, 0, b2,
        tfs+132, tfh+132, tfl+132, ssum+256, ssq+256, 64, P_TOT);
    finalize_bn<<<1, 131>>>(ssum+256, ssq+256, 128, CNT_P, g2, be2, tfs+264, tfh+264, tfl+264);

    // Ll: 131->128, xform tf2, stats slot3
    gemm_tc<128,false,true,false,false,true><<<dim3(P_TOT/128,1,1), 256>>>(
        wl, 131, 0, bufA, nullptr, 0, nullptr, 0, bufB, 0, bl,
        tfs+264, tfh+264, tfl+264, ssum+384, ssq+384, 131, P_TOT);
    finalize_bn<<<1, 128>>>(ssum+384, ssq+384, 128, CNT_P, gl, bel, tfs+396, tfh+396, tfl+396);

    // pool over K with fused BN+ReLU
    maxpool_kernel<<<(BB*128*NPT + 255)/256, 256>>>(bufB, xp, tfs+396, tfh+396);

    // attention
    gemm_tc<128,false,false,false,false,false><<<dim3(NPT/128, BB, 1), 256>>>(
        wv, 128, 0, xp, nullptr, PB, nullptr, 0, x0, PB, bv,
        nullptr, nullptr, nullptr, nullptr, nullptr, 128, NPT);
    gemm_tc<128,true,false,false,false,false><<<dim3(NPT/128, BB, 4), 256>>>(
        xp, NPT, PB, x0, nullptr, PB, nullptr, 0, energy, (long)NPT*NPT, nullptr,
        nullptr, nullptr, nullptr, nullptr, nullptr, 128, NPT);
    softmax_kernel<<<(BB*NPT*32 + 255)/256, 256>>>(energy);
    colsum_kernel<<<dim3(BB, NPT/128), 128>>>(energy, colrcp);
    // x2 = x0 @ attn (col-renorm fused via PSCALE)
    gemm_tc<128,false,false,false,true,false><<<dim3(NPT/128, BB, 1), 256>>>(
        x0, NPT, PB, energy, nullptr, (long)NPT*NPT, colrcp, NPT, x2, PB, nullptr,
        nullptr, nullptr, nullptr, nullptr, nullptr, NPT, NPT);
    // wt GEMM on (xp - x2), stats slot4
    gemm_tc<128,false,false,true,false,true><<<dim3(NPT/128, BB, 1), 256>>>(
        wt, 128, 0, xp, x2, PB, nullptr, 0, y, PB, bt,
        nullptr, nullptr, nullptr, ssum+512, ssq+512, 128, NPT);
    finalize_bn<<<1, 128>>>(ssum+512, ssq+512, 128, CNT_S, gn, gb, tfs+528, tfh+528, tfl+528);

    final_kernel<<<(BB*128*NPT + 255)/256, 256>>>(out + BB*3*NPT, xp, y,
        tfs+528, tfh+528, alpha, beta);
}

// round 6
// speedup vs baseline: 2.0498x; 1.4575x over previous
#include <cuda_runtime.h>
#include <cuda_bf16.h>
#include <cstdint>
#include <math.h>

// ---------------- constants ----------------
#define BB   16
#define NN   4096
#define DD   64
#define NPT  512
#define KK   32
#define P_TOT (BB*NPT*KK)     // 262144
#define PB   (128*NPT)        // 65536 per-batch (c,s) block
#define EPSF 1e-5f

// ---------------- scratch ----------------
__device__ float g_bufA[131L * P_TOT];          // 131 x P  (rows 128..130 = rel_xyz)
__device__ float g_bufB[128L * P_TOT];          // 128 x P
__device__ float g_xp[BB*128*NPT];
__device__ float g_x0[BB*128*NPT];
__device__ float g_energy[BB*NPT*NPT];
__device__ float g_x2[BB*128*NPT];
__device__ float g_y[BB*128*NPT];
__device__ float g_pmax[128*BB*NPT];
__device__ float g_pmin[128*BB*NPT];
__device__ double g_ssum[5*128];
__device__ double g_ssq[5*128];
__device__ float g_tfs[5*132];
__device__ float g_tfh[5*132];
__device__ float g_tfl[5*132];
__device__ float g_colrcp[BB*NPT];
__device__ int   g_fps[BB*NPT];
__device__ int   g_nbr[BB*NPT*KK];

// ---------------- FPS ----------------
__global__ void __launch_bounds__(1024) fps_kernel(const float* __restrict__ xyz,
                                                   int* __restrict__ fps) {
    extern __shared__ float sm[];
    float* sx = sm;
    float* sy = sm + NN;
    float* sz = sm + 2*NN;
    __shared__ unsigned long long swarp[32];
    __shared__ int sfar;
    int b = blockIdx.x, tid = threadIdx.x;
    const float* base = xyz + (long)b*3*NN;
    for (int i = tid; i < NN; i += 1024) {
        sx[i] = base[i];
        sy[i] = base[NN + i];
        sz[i] = base[2*NN + i];
    }
    __syncthreads();
    float dist[4];
    dist[0] = dist[1] = dist[2] = dist[3] = 1e10f;
    int far = 0;
    for (int it = 0; it < NPT; ++it) {
        if (tid == 0) fps[b*NPT + it] = far;
        float cx = sx[far], cy = sy[far], cz = sz[far];
        unsigned long long best = 0ull;
        #pragma unroll
        for (int j = 0; j < 4; ++j) {
            int n = tid + j*1024;
            float dx = sx[n]-cx, dy = sy[n]-cy, dz = sz[n]-cz;
            float d = dx*dx + dy*dy + dz*dz;
            float dd = fminf(dist[j], d);
            dist[j] = dd;
            unsigned long long key =
                ((unsigned long long)__float_as_uint(dd) << 32) |
                (unsigned long long)(0xFFFFFFFFu - (unsigned)n);
            best = (key > best) ? key : best;
        }
        #pragma unroll
        for (int off = 16; off > 0; off >>= 1) {
            unsigned long long o = __shfl_down_sync(0xFFFFFFFFu, best, off);
            best = (o > best) ? o : best;
        }
        if ((tid & 31) == 0) swarp[tid >> 5] = best;
        __syncthreads();
        if (tid < 32) {
            best = swarp[tid];
            #pragma unroll
            for (int off = 16; off > 0; off >>= 1) {
                unsigned long long o = __shfl_down_sync(0xFFFFFFFFu, best, off);
                best = (o > best) ? o : best;
            }
            if (tid == 0)
                sfar = (int)(0xFFFFFFFFu - (unsigned)(best & 0xFFFFFFFFull));
        }
        __syncthreads();
        far = sfar;
    }
}

// ---------------- new_xyz output ----------------
__global__ void newxyz_kernel(float* __restrict__ out, const float* __restrict__ xyz,
                              const int* __restrict__ fps) {
    int i = blockIdx.x*256 + threadIdx.x;
    if (i >= BB*3*NPT) return;
    int s = i & 511;
    int c = (i >> 9) % 3;
    int b = i / (3*NPT);
    out[i] = xyz[(long)b*3*NN + c*NN + fps[b*NPT + s]];
}

// ---------------- ball query ----------------
__global__ void __launch_bounds__(256) ball_kernel(const float* __restrict__ xyz,
                                                   const int* __restrict__ fps,
                                                   int* __restrict__ nbr) {
    extern __shared__ float sm[];
    float* sx = sm;
    float* sy = sm + NN;
    float* sz = sm + 2*NN;
    __shared__ int snb[8][KK];
    int b = blockIdx.y, tid = threadIdx.x;
    const float* base = xyz + (long)b*3*NN;
    for (int i = tid; i < NN; i += 256) {
        sx[i] = base[i];
        sy[i] = base[NN + i];
        sz[i] = base[2*NN + i];
    }
    __syncthreads();
    int w = tid >> 5, lane = tid & 31;
    int s = blockIdx.x*8 + w;
    int fi = fps[b*NPT + s];
    float cx = sx[fi], cy = sy[fi], cz = sz[fi];
    float cn = cx*cx + cy*cy + cz*cz;
    const float R2 = (float)(0.4*0.4);
    int cnt = 0;
    for (int n0 = 0; n0 < NN && cnt < KK; n0 += 32) {
        int n = n0 + lane;
        float px = sx[n], py = sy[n], pz = sz[n];
        float pn = px*px + py*py + pz*pz;
        float dt = cx*px + cy*py + cz*pz;
        float sq = (cn + pn) - 2.0f*dt;
        bool in = !(sq > R2);
        unsigned m = __ballot_sync(0xFFFFFFFFu, in);
        int pos = cnt + __popc(m & ((1u << lane) - 1u));
        if (in && pos < KK) snb[w][pos] = n;
        cnt += __popc(m);
    }
    __syncwarp();
    int v = (lane < cnt) ? snb[w][lane] : snb[w][0];
    nbr[(b*NPT + s)*KK + lane] = v;
}

// ---------------- feature build (also zeros BN stat accumulators) ----------------
__global__ void __launch_bounds__(256) feat_kernel(const float* __restrict__ points,
                                                   const float* __restrict__ xyz,
                                                   const int* __restrict__ fps,
                                                   const int* __restrict__ nbr,
                                                   float* __restrict__ X0,
                                                   float* __restrict__ relbuf) {
    int s = blockIdx.x, b = blockIdx.y, tid = threadIdx.x;
    if (s == 0 && b == 0) {
        for (int i = tid; i < 5*128; i += 256) { g_ssum[i] = 0.0; g_ssq[i] = 0.0; }
    }
    __shared__ int snb[KK];
    __shared__ float scen[DD];
    __shared__ float scxyz[3];
    int fi = fps[b*NPT + s];
    if (tid < KK) snb[tid] = nbr[(b*NPT + s)*KK + tid];
    if (tid >= 32 && tid < 32+DD) scen[tid-32] = points[(long)b*DD*NN + (tid-32)*NN + fi];
    if (tid >= 96 && tid < 99)   scxyz[tid-96] = xyz[(long)b*3*NN + (tid-96)*NN + fi];
    __syncthreads();
    int k = tid & 31, cb = tid >> 5;
    int n = snb[k];
    int base = (b*NPT + s)*KK + k;
    #pragma unroll
    for (int q = 0; q < 8; ++q) {
        int c = q*8 + cb;
        float v = points[(long)b*DD*NN + c*NN + n];
        X0[(long)c*P_TOT + base] = v;
        X0[(long)(DD+c)*P_TOT + base] = v - scen[c];
    }
    if (cb < 3) {
        float v = xyz[(long)b*3*NN + cb*NN + n] - scxyz[cb];
        relbuf[(long)cb*P_TOT + base] = v;
    }
}

// ---------------- tf32 helpers ----------------
__device__ __forceinline__ uint32_t f2tf32(float v) {
    uint32_t r;
    asm("cvt.rna.tf32.f32 %0, %1;" : "=r"(r) : "f"(v));
    return r;
}
__device__ __forceinline__ void mma_tf32(float* d, uint32_t a0, uint32_t a1,
                                         uint32_t a2, uint32_t a3,
                                         uint32_t b0, uint32_t b1) {
    asm volatile("mma.sync.aligned.m16n8k8.row.col.f32.tf32.tf32.f32 "
        "{%0,%1,%2,%3},{%4,%5,%6,%7},{%8,%9},{%0,%1,%2,%3};"
        : "+f"(d[0]), "+f"(d[1]), "+f"(d[2]), "+f"(d[3])
        : "r"(a0), "r"(a1), "r"(a2), "r"(a3), "r"(b0), "r"(b1));
}

// ---------------- tensor-core fused GEMM ----------------
// Y[b][coBase+co][p] = sum_k A(co,k) * x'(k,p) + bias[co]
//   A(co,k) = TRANSA ? A[k*lda+co_glob] : A[co_glob*lda+k]
//   x'(k,p) = XFORM ? max(fma(x, xscale[k], xshift[k]), xlo[k]) : x
//   x       = (SUB ? X[k][p]-X2[k][p] : X[k][p]) * (PSCALE ? pscale[p] : 1)
// STATS: per-channel double sum/sumsq of Y via atomics.
// POOL:  instead of writing Y, write per-(channel, p/32) running max and min.
template<int COUT, bool TRANSA, bool XFORM, bool SUB, bool PSCALE, bool STATS, bool POOL>
__global__ void __launch_bounds__(256)
gemm_tc(const float* __restrict__ A, int lda, long aStride,
        const float* __restrict__ X, const float* __restrict__ X2, long xStride,
        const float* __restrict__ pscale, int psStride,
        float* __restrict__ Y, long yStride,
        const float* __restrict__ bias,
        const float* __restrict__ xscale, const float* __restrict__ xshift,
        const float* __restrict__ xlo,
        double* __restrict__ ssum, double* __restrict__ ssq,
        float* __restrict__ pmax, float* __restrict__ pmin,
        int Cin, int P)
{
    constexpr int MW = COUT / 4;     // warp tile M
    constexpr int MF = MW / 16;      // m16 fragments per warp
    constexpr int NW = (COUT*32)/256;   // scalar W loads per thread
    __shared__ uint32_t sX[32*136];
    __shared__ uint32_t sW[COUT*36];

    int by = blockIdx.y;
    A += (long)by * aStride;
    X += (long)by * xStride;
    if (SUB) X2 += (long)by * xStride;
    Y += (long)by * yStride;
    int coBase = blockIdx.z * COUT;
    int p0 = blockIdx.x * 128;
    const float* psc = PSCALE ? (pscale + (long)by*psStride + p0) : nullptr;

    int tid = threadIdx.x;
    int lane = tid & 31, wid = tid >> 5;
    int warpM = wid >> 1, warpN = wid & 1;
    int gid = lane >> 2, tig = lane & 3;

    float d[MF][8][4];
    #pragma unroll
    for (int mf = 0; mf < MF; ++mf)
        #pragma unroll
        for (int nf = 0; nf < 8; ++nf)
            #pragma unroll
            for (int i = 0; i < 4; ++i) d[mf][nf][i] = 0.f;

    uint32_t xs[16];
    uint32_t ws[NW];

    int nchunk = (Cin + 31) >> 5;

    auto loadX = [&](int k0) {
        #pragma unroll
        for (int j = 0; j < 4; ++j) {
            int id = tid + j*256;
            int row = id >> 5, c4 = id & 31;
            int k = k0 + row;
            float4 v = make_float4(0.f, 0.f, 0.f, 0.f);
            if (k < Cin) {
                v = *reinterpret_cast<const float4*>(&X[(long)k*P + p0 + c4*4]);
                if (SUB) {
                    float4 u = *reinterpret_cast<const float4*>(&X2[(long)k*P + p0 + c4*4]);
                    v.x -= u.x; v.y -= u.y; v.z -= u.z; v.w -= u.w;
                }
                if (XFORM) {
                    float s = xscale[k], h = xshift[k], l = xlo[k];
                    v.x = fmaxf(fmaf(v.x, s, h), l);
                    v.y = fmaxf(fmaf(v.y, s, h), l);
                    v.z = fmaxf(fmaf(v.z, s, h), l);
                    v.w = fmaxf(fmaf(v.w, s, h), l);
                }
                if (PSCALE) {
                    float4 pv = *reinterpret_cast<const float4*>(&psc[c4*4]);
                    v.x *= pv.x; v.y *= pv.y; v.z *= pv.z; v.w *= pv.w;
                }
            }
            xs[j*4+0] = f2tf32(v.x); xs[j*4+1] = f2tf32(v.y);
            xs[j*4+2] = f2tf32(v.z); xs[j*4+3] = f2tf32(v.w);
        }
    };
    // scalar W loads (lda may be odd -> no vector LDG)
    auto loadW = [&](int k0) {
        #pragma unroll
        for (int j = 0; j < NW; ++j) {
            int id = tid + j*256;          // id = co*32 + kk
            int co = id >> 5, kk = id & 31;
            int k = k0 + kk;
            float w = 0.f;
            if (k < Cin)
                w = TRANSA ? A[(long)k*lda + coBase + co]
                           : A[(long)(coBase + co)*lda + k];
            ws[j] = f2tf32(w);
        }
    };
    auto storeTiles = [&]() {
        #pragma unroll
        for (int j = 0; j < 4; ++j) {
            int id = tid + j*256;
            int row = id >> 5, c4 = id & 31;
            *reinterpret_cast<uint4*>(&sX[row*136 + c4*4]) =
                make_uint4(xs[j*4], xs[j*4+1], xs[j*4+2], xs[j*4+3]);
        }
        #pragma unroll
        for (int j = 0; j < NW; ++j) {
            int id = tid + j*256;
            int co = id >> 5, kk = id & 31;
            sW[co*36 + kk] = ws[j];
        }
    };

    loadX(0);
    loadW(0);
    for (int c0 = 0; c0 < nchunk; ++c0) {
        storeTiles();
        __syncthreads();
        if (c0 + 1 < nchunk) { loadX((c0+1)*32); loadW((c0+1)*32); }
        #pragma unroll
        for (int k8 = 0; k8 < 4; ++k8) {
            int kb = k8*8;
            uint32_t a[MF][4];
            #pragma unroll
            for (int mf = 0; mf < MF; ++mf) {
                int r = warpM*MW + mf*16 + gid;
                a[mf][0] = sW[r*36 + kb + tig];
                a[mf][1] = sW[(r+8)*36 + kb + tig];
                a[mf][2] = sW[r*36 + kb + tig + 4];
                a[mf][3] = sW[(r+8)*36 + kb + tig + 4];
            }
            #pragma unroll
            for (int nf = 0; nf < 8; ++nf) {
                int col = warpN*64 + nf*8 + gid;
                uint32_t b0 = sX[(kb + tig)*136 + col];
                uint32_t b1 = sX[(kb + tig + 4)*136 + col];
                #pragma unroll
                for (int mf = 0; mf < MF; ++mf)
                    mma_tf32(d[mf][nf], a[mf][0], a[mf][1], a[mf][2], a[mf][3], b0, b1);
            }
        }
        __syncthreads();
    }

    // epilogue
    #pragma unroll
    for (int mf = 0; mf < MF; ++mf) {
        int r = warpM*MW + mf*16 + gid;
        int co0 = coBase + r, co1 = co0 + 8;
        float bb0 = bias ? bias[co0] : 0.f;
        float bb1 = bias ? bias[co1] : 0.f;
        double s0 = 0.0, q0 = 0.0, s1 = 0.0, q1 = 0.0;
        float mxa[2], mna[2], mxb[2], mnb[2];
        if (POOL) {
            mxa[0] = mxa[1] = mxb[0] = mxb[1] = -3.4e38f;
            mna[0] = mna[1] = mnb[0] = mnb[1] =  3.4e38f;
        }
        #pragma unroll
        for (int nf = 0; nf < 8; ++nf) {
            int p = p0 + warpN*64 + nf*8 + 2*tig;
            float o0 = d[mf][nf][0] + bb0, o1 = d[mf][nf][1] + bb0;
            float o2 = d[mf][nf][2] + bb1, o3 = d[mf][nf][3] + bb1;
            if (!POOL) {
                *reinterpret_cast<float2*>(&Y[(long)co0*P + p]) = make_float2(o0, o1);
                *reinterpret_cast<float2*>(&Y[(long)co1*P + p]) = make_float2(o2, o3);
            } else {
                int g = nf >> 2;
                mxa[g] = fmaxf(mxa[g], fmaxf(o0, o1));
                mna[g] = fminf(mna[g], fminf(o0, o1));
                mxb[g] = fmaxf(mxb[g], fmaxf(o2, o3));
                mnb[g] = fminf(mnb[g], fminf(o2, o3));
            }
            if (STATS) {
                s0 += (double)o0 + (double)o1;
                q0 += (double)o0*o0 + (double)o1*o1;
                s1 += (double)o2 + (double)o3;
                q1 += (double)o2*o2 + (double)o3*o3;
            }
        }
        if (POOL) {
            int PS = P >> 5;
            #pragma unroll
            for (int g = 0; g < 2; ++g) {
                float ma = mxa[g], na = mna[g], mb = mxb[g], nb = mnb[g];
                #pragma unroll
                for (int off = 1; off <= 2; off <<= 1) {
                    ma = fmaxf(ma, __shfl_xor_sync(0xFFFFFFFFu, ma, off));
                    na = fminf(na, __shfl_xor_sync(0xFFFFFFFFu, na, off));
                    mb = fmaxf(mb, __shfl_xor_sync(0xFFFFFFFFu, mb, off));
                    nb = fminf(nb, __shfl_xor_sync(0xFFFFFFFFu, nb, off));
                }
                if (tig == 0) {
                    int ps = (p0 >> 5) + warpN*2 + g;
                    pmax[(long)co0*PS + ps] = ma;
                    pmin[(long)co0*PS + ps] = na;
                    pmax[(long)co1*PS + ps] = mb;
                    pmin[(long)co1*PS + ps] = nb;
                }
            }
        }
        if (STATS) {
            #pragma unroll
            for (int off = 1; off <= 2; off <<= 1) {
                s0 += __shfl_xor_sync(0xFFFFFFFFu, s0, off);
                q0 += __shfl_xor_sync(0xFFFFFFFFu, q0, off);
                s1 += __shfl_xor_sync(0xFFFFFFFFu, s1, off);
                q1 += __shfl_xor_sync(0xFFFFFFFFu, q1, off);
            }
            if (tig == 0) {
                atomicAdd(&ssum[co0], s0);
                atomicAdd(&ssq[co0], q0);
                atomicAdd(&ssum[co1], s1);
                atomicAdd(&ssq[co1], q1);
            }
        }
    }
}

// ---------------- finalize BN -> affine ----------------
__global__ void finalize_bn(const double* __restrict__ ssum, const double* __restrict__ ssq,
                            int Cbn, double count,
                            const float* __restrict__ g, const float* __restrict__ be,
                            float* __restrict__ scale, float* __restrict__ shift,
                            float* __restrict__ lo) {
    int c = threadIdx.x;
    if (c < Cbn) {
        double m = ssum[c] / count;
        double v = ssq[c] / count - m*m;
        float sc = g[c] * rsqrtf((float)v + EPSF);
        scale[c] = sc;
        shift[c] = be[c] - (float)m * sc;
        lo[c] = 0.f;
    } else {
        scale[c] = 1.f;
        shift[c] = 0.f;
        lo[c] = -3.4e38f;
    }
}

// ---------------- pooled BN+ReLU finalize: xp[b][c][s] ----------------
__global__ void pool_finalize(float* __restrict__ xp,
                              const float* __restrict__ pmax, const float* __restrict__ pmin,
                              const float* __restrict__ scale, const float* __restrict__ shift) {
    int i = blockIdx.x*256 + threadIdx.x;
    if (i >= BB*128*NPT) return;
    int s = i & 511, c = (i >> 9) & 127, b = i >> 16;
    int src = c*(BB*NPT) + b*NPT + s;
    float sc = scale[c], sh = shift[c];
    float v = (sc >= 0.f) ? pmax[src] : pmin[src];
    xp[i] = fmaxf(fmaf(v, sc, sh), 0.f);
}

// ---------------- softmax rows ----------------
__global__ void softmax_kernel(float* __restrict__ e) {
    int gw = (blockIdx.x*256 + threadIdx.x) >> 5;
    int lane = threadIdx.x & 31;
    if (gw >= BB*NPT) return;
    float* row = e + (long)gw * NPT;
    float v[16];
    float mx = -3.4e38f;
    #pragma unroll
    for (int i = 0; i < 16; ++i) { v[i] = row[lane + i*32]; mx = fmaxf(mx, v[i]); }
    #pragma unroll
    for (int off = 16; off > 0; off >>= 1)
        mx = fmaxf(mx, __shfl_xor_sync(0xFFFFFFFFu, mx, off));
    float sum = 0.f;
    #pragma unroll
    for (int i = 0; i < 16; ++i) { v[i] = expf(v[i] - mx); sum += v[i]; }
    #pragma unroll
    for (int off = 16; off > 0; off >>= 1)
        sum += __shfl_xor_sync(0xFFFFFFFFu, sum, off);
    #pragma unroll
    for (int i = 0; i < 16; ++i) row[lane + i*32] = v[i] / sum;
}

// ---------------- column sums (store reciprocal) ----------------
__global__ void colsum_kernel(const float* __restrict__ e, float* __restrict__ colrcp) {
    int b = blockIdx.x, m = blockIdx.y*128 + threadIdx.x;
    const float* E = e + (long)b * NPT * NPT;
    float s = 0.f;
    for (int n = 0; n < NPT; ++n) s += E[n*NPT + m];
    colrcp[b*NPT + m] = 1.f / (1e-9f + s);
}

// ---------------- final residual ----------------
__global__ void final_kernel(float* __restrict__ out, const float* __restrict__ xp,
                             const float* __restrict__ y,
                             const float* __restrict__ scale, const float* __restrict__ shift,
                             const float* __restrict__ alpha, const float* __restrict__ beta) {
    int i = blockIdx.x*256 + threadIdx.x;
    if (i >= BB*128*NPT) return;
    int c = (i >> 9) & 127;
    float xr = fmaxf(fmaf(y[i], scale[c], shift[c]), 0.f);
    out[i] = xp[i] + alpha[c]*xr + beta[c];
}

// ---------------- launch ----------------
extern "C" void kernel_launch(void* const* d_in, const int* in_sizes, int n_in,
                              void* d_out, int out_size) {
    const float* xyz    = (const float*)d_in[0];
    const float* points = (const float*)d_in[1];
    const float* w0 = (const float*)d_in[2];
    const float* b0 = (const float*)d_in[3];
    const float* g0 = (const float*)d_in[4];
    const float* be0= (const float*)d_in[5];
    const float* w1 = (const float*)d_in[6];
    const float* b1 = (const float*)d_in[7];
    const float* g1 = (const float*)d_in[8];
    const float* be1= (const float*)d_in[9];
    const float* w2 = (const float*)d_in[10];
    const float* b2 = (const float*)d_in[11];
    const float* g2 = (const float*)d_in[12];
    const float* be2= (const float*)d_in[13];
    const float* wl = (const float*)d_in[14];
    const float* bl = (const float*)d_in[15];
    const float* gl = (const float*)d_in[16];
    const float* bel= (const float*)d_in[17];
    const float* wv = (const float*)d_in[18];
    const float* bv = (const float*)d_in[19];
    const float* wt = (const float*)d_in[20];
    const float* bt = (const float*)d_in[21];
    const float* gn = (const float*)d_in[22];
    const float* gb = (const float*)d_in[23];
    const float* alpha = (const float*)d_in[24];
    const float* beta  = (const float*)d_in[25];
    float* out = (float*)d_out;

    float *bufA, *bufB, *xp, *x0, *energy, *x2, *y, *tfs, *tfh, *tfl, *colrcp, *pmax, *pmin;
    double *ssum, *ssq;
    int *fps, *nbr;
    cudaGetSymbolAddress((void**)&bufA, g_bufA);
    cudaGetSymbolAddress((void**)&bufB, g_bufB);
    cudaGetSymbolAddress((void**)&xp, g_xp);
    cudaGetSymbolAddress((void**)&x0, g_x0);
    cudaGetSymbolAddress((void**)&energy, g_energy);
    cudaGetSymbolAddress((void**)&x2, g_x2);
    cudaGetSymbolAddress((void**)&y, g_y);
    cudaGetSymbolAddress((void**)&ssum, g_ssum);
    cudaGetSymbolAddress((void**)&ssq, g_ssq);
    cudaGetSymbolAddress((void**)&tfs, g_tfs);
    cudaGetSymbolAddress((void**)&tfh, g_tfh);
    cudaGetSymbolAddress((void**)&tfl, g_tfl);
    cudaGetSymbolAddress((void**)&colrcp, g_colrcp);
    cudaGetSymbolAddress((void**)&pmax, g_pmax);
    cudaGetSymbolAddress((void**)&pmin, g_pmin);
    cudaGetSymbolAddress((void**)&fps, g_fps);
    cudaGetSymbolAddress((void**)&nbr, g_nbr);

    const int SMEM_PTS = 3*NN*sizeof(float);   // 48KB
    cudaFuncSetAttribute(fps_kernel,  cudaFuncAttributeMaxDynamicSharedMemorySize, 64*1024);
    cudaFuncSetAttribute(ball_kernel, cudaFuncAttributeMaxDynamicSharedMemorySize, 64*1024);

    const double CNT_P = (double)P_TOT;
    const double CNT_S = (double)(BB*NPT);

    // geometry (ordered so the 4th launch = L0 tensor-core GEMM for ncu capture)
    fps_kernel<<<BB, 1024, SMEM_PTS>>>(xyz, fps);
    ball_kernel<<<dim3(NPT/8, BB), 256, SMEM_PTS>>>(xyz, fps, nbr);
    feat_kernel<<<dim3(NPT, BB), 256>>>(points, xyz, fps, nbr, bufB, bufA + 128L*P_TOT);

    // L0: 128->64, stats slot0
    gemm_tc<64,false,false,false,false,true,false><<<dim3(P_TOT/128,1,1), 256>>>(
        w0, 128, 0, bufB, nullptr, 0, nullptr, 0, bufA, 0, b0,
        nullptr, nullptr, nullptr, ssum+0, ssq+0, nullptr, nullptr, 128, P_TOT);
    newxyz_kernel<<<(BB*3*NPT + 255)/256, 256>>>(out, xyz, fps);
    finalize_bn<<<1, 64>>>(ssum+0, ssq+0, 64, CNT_P, g0, be0, tfs+0, tfh+0, tfl+0);

    // L1: 64->64, xform tf0, stats slot1
    gemm_tc<64,false,true,false,false,true,false><<<dim3(P_TOT/128,1,1), 256>>>(
        w1, 64, 0, bufA, nullptr, 0, nullptr, 0, bufB, 0, b1,
        tfs+0, tfh+0, tfl+0, ssum+128, ssq+128, nullptr, nullptr, 64, P_TOT);
    finalize_bn<<<1, 64>>>(ssum+128, ssq+128, 64, CNT_P, g1, be1, tfs+132, tfh+132, tfl+132);

    // L2: 64->128, xform tf1, stats slot2
    gemm_tc<128,false,true,false,false,true,false><<<dim3(P_TOT/128,1,1), 256>>>(
        w2, 64, 0, bufB, nullptr, 0, nullptr, 0, bufA, 0, b2,
        tfs+132, tfh+132, tfl+132, ssum+256, ssq+256, nullptr, nullptr, 64, P_TOT);
    finalize_bn<<<1, 131>>>(ssum+256, ssq+256, 128, CNT_P, g2, be2, tfs+264, tfh+264, tfl+264);

    // Ll: 131->128, xform tf2, stats slot3, POOL epilogue (no Y write, no maxpool pass)
    gemm_tc<128,false,true,false,false,true,true><<<dim3(P_TOT/128,1,1), 256>>>(
        wl, 131, 0, bufA, nullptr, 0, nullptr, 0, bufB, 0, bl,
        tfs+264, tfh+264, tfl+264, ssum+384, ssq+384, pmax, pmin, 131, P_TOT);
    finalize_bn<<<1, 128>>>(ssum+384, ssq+384, 128, CNT_P, gl, bel, tfs+396, tfh+396, tfl+396);
    pool_finalize<<<(BB*128*NPT + 255)/256, 256>>>(xp, pmax, pmin, tfs+396, tfh+396);

    // attention
    gemm_tc<128,false,false,false,false,false,false><<<dim3(NPT/128, BB, 1), 256>>>(
        wv, 128, 0, xp, nullptr, PB, nullptr, 0, x0, PB, bv,
        nullptr, nullptr, nullptr, nullptr, nullptr, nullptr, nullptr, 128, NPT);
    gemm_tc<128,true,false,false,false,false,false><<<dim3(NPT/128, BB, 4), 256>>>(
        xp, NPT, PB, x0, nullptr, PB, nullptr, 0, energy, (long)NPT*NPT, nullptr,
        nullptr, nullptr, nullptr, nullptr, nullptr, nullptr, nullptr, 128, NPT);
    softmax_kernel<<<(BB*NPT*32 + 255)/256, 256>>>(energy);
    colsum_kernel<<<dim3(BB, NPT/128), 128>>>(energy, colrcp);
    // x2 = x0 @ attn (column renorm fused via PSCALE)
    gemm_tc<128,false,false,false,true,false,false><<<dim3(NPT/128, BB, 1), 256>>>(
        x0, NPT, PB, energy, nullptr, (long)NPT*NPT, colrcp, NPT, x2, PB, nullptr,
        nullptr, nullptr, nullptr, nullptr, nullptr, nullptr, nullptr, NPT, NPT);
    // wt GEMM on (xp - x2), stats slot4
    gemm_tc<128,false,false,true,false,true,false><<<dim3(NPT/128, BB, 1), 256>>>(
        wt, 128, 0, xp, x2, PB, nullptr, 0, y, PB, bt,
        nullptr, nullptr, nullptr, ssum+512, ssq+512, nullptr, nullptr, 128, NPT);
    finalize_bn<<<1, 128>>>(ssum+512, ssq+512, 128, CNT_S, gn, gb, tfs+528, tfh+528, tfl+528);

    final_kernel<<<(BB*128*NPT + 255)/256, 256>>>(out + BB*3*NPT, xp, y,
        tfs+528, tfh+528, alpha, beta);
}

// round 8
// speedup vs baseline: 2.4247x; 1.1829x over previous
#include <cuda_runtime.h>
#include <cuda_bf16.h>
#include <cstdint>
#include <math.h>

// ---------------- constants ----------------
#define BB   16
#define NN   4096
#define DD   64
#define NPT  512
#define KK   32
#define P_TOT (BB*NPT*KK)     // 262144
#define PB   (128*NPT)        // 65536 per-batch (c,s) block
#define EPSF 1e-5f
#define NST  3                // cp.async ring depth

// ---------------- scratch ----------------
__device__ float g_bufA[131L * P_TOT];          // 131 x P  (rows 128..130 = rel_xyz)
__device__ float g_bufB[128L * P_TOT];          // 128 x P
__device__ float g_xp[BB*128*NPT];
__device__ float g_x0[BB*128*NPT];
__device__ float g_energy[BB*NPT*NPT];
__device__ float g_x2[BB*128*NPT];
__device__ float g_y[BB*128*NPT];
__device__ float g_pmax[128*BB*NPT];
__device__ float g_pmin[128*BB*NPT];
__device__ double g_ssum[5*128];
__device__ double g_ssq[5*128];
__device__ float g_tfs[5*132];
__device__ float g_tfh[5*132];
__device__ float g_tfl[5*132];
__device__ float g_colrcp[BB*NPT];
__device__ int   g_fps[BB*NPT];
__device__ int   g_nbr[BB*NPT*KK];

// ---------------- FPS ----------------
__global__ void __launch_bounds__(1024) fps_kernel(const float* __restrict__ xyz,
                                                   int* __restrict__ fps) {
    extern __shared__ float sm[];
    float* sx = sm;
    float* sy = sm + NN;
    float* sz = sm + 2*NN;
    __shared__ unsigned long long swarp[32];
    __shared__ int sfar;
    int b = blockIdx.x, tid = threadIdx.x;
    const float* base = xyz + (long)b*3*NN;
    for (int i = tid; i < NN; i += 1024) {
        sx[i] = base[i];
        sy[i] = base[NN + i];
        sz[i] = base[2*NN + i];
    }
    __syncthreads();
    float dist[4];
    dist[0] = dist[1] = dist[2] = dist[3] = 1e10f;
    int far = 0;
    for (int it = 0; it < NPT; ++it) {
        if (tid == 0) fps[b*NPT + it] = far;
        float cx = sx[far], cy = sy[far], cz = sz[far];
        unsigned long long best = 0ull;
        #pragma unroll
        for (int j = 0; j < 4; ++j) {
            int n = tid + j*1024;
            float dx = sx[n]-cx, dy = sy[n]-cy, dz = sz[n]-cz;
            float d = dx*dx + dy*dy + dz*dz;
            float dd = fminf(dist[j], d);
            dist[j] = dd;
            unsigned long long key =
                ((unsigned long long)__float_as_uint(dd) << 32) |
                (unsigned long long)(0xFFFFFFFFu - (unsigned)n);
            best = (key > best) ? key : best;
        }
        #pragma unroll
        for (int off = 16; off > 0; off >>= 1) {
            unsigned long long o = __shfl_down_sync(0xFFFFFFFFu, best, off);
            best = (o > best) ? o : best;
        }
        if ((tid & 31) == 0) swarp[tid >> 5] = best;
        __syncthreads();
        if (tid < 32) {
            best = swarp[tid];
            #pragma unroll
            for (int off = 16; off > 0; off >>= 1) {
                unsigned long long o = __shfl_down_sync(0xFFFFFFFFu, best, off);
                best = (o > best) ? o : best;
            }
            if (tid == 0)
                sfar = (int)(0xFFFFFFFFu - (unsigned)(best & 0xFFFFFFFFull));
        }
        __syncthreads();
        far = sfar;
    }
}

// ---------------- new_xyz output ----------------
__global__ void newxyz_kernel(float* __restrict__ out, const float* __restrict__ xyz,
                              const int* __restrict__ fps) {
    int i = blockIdx.x*256 + threadIdx.x;
    if (i >= BB*3*NPT) return;
    int s = i & 511;
    int c = (i >> 9) % 3;
    int b = i / (3*NPT);
    out[i] = xyz[(long)b*3*NN + c*NN + fps[b*NPT + s]];
}

// ---------------- ball query ----------------
__global__ void __launch_bounds__(256) ball_kernel(const float* __restrict__ xyz,
                                                   const int* __restrict__ fps,
                                                   int* __restrict__ nbr) {
    extern __shared__ float sm[];
    float* sx = sm;
    float* sy = sm + NN;
    float* sz = sm + 2*NN;
    __shared__ int snb[8][KK];
    int b = blockIdx.y, tid = threadIdx.x;
    const float* base = xyz + (long)b*3*NN;
    for (int i = tid; i < NN; i += 256) {
        sx[i] = base[i];
        sy[i] = base[NN + i];
        sz[i] = base[2*NN + i];
    }
    __syncthreads();
    int w = tid >> 5, lane = tid & 31;
    int s = blockIdx.x*8 + w;
    int fi = fps[b*NPT + s];
    float cx = sx[fi], cy = sy[fi], cz = sz[fi];
    float cn = cx*cx + cy*cy + cz*cz;
    const float R2 = (float)(0.4*0.4);
    int cnt = 0;
    for (int n0 = 0; n0 < NN && cnt < KK; n0 += 32) {
        int n = n0 + lane;
        float px = sx[n], py = sy[n], pz = sz[n];
        float pn = px*px + py*py + pz*pz;
        float dt = cx*px + cy*py + cz*pz;
        float sq = (cn + pn) - 2.0f*dt;
        bool in = !(sq > R2);
        unsigned m = __ballot_sync(0xFFFFFFFFu, in);
        int pos = cnt + __popc(m & ((1u << lane) - 1u));
        if (in && pos < KK) snb[w][pos] = n;
        cnt += __popc(m);
    }
    __syncwarp();
    int v = (lane < cnt) ? snb[w][lane] : snb[w][0];
    nbr[(b*NPT + s)*KK + lane] = v;
}

// ---------------- feature build (also zeros BN stat accumulators) ----------------
__global__ void __launch_bounds__(256) feat_kernel(const float* __restrict__ points,
                                                   const float* __restrict__ xyz,
                                                   const int* __restrict__ fps,
                                                   const int* __restrict__ nbr,
                                                   float* __restrict__ X0,
                                                   float* __restrict__ relbuf) {
    int s = blockIdx.x, b = blockIdx.y, tid = threadIdx.x;
    if (s == 0 && b == 0) {
        for (int i = tid; i < 5*128; i += 256) { g_ssum[i] = 0.0; g_ssq[i] = 0.0; }
    }
    __shared__ int snb[KK];
    __shared__ float scen[DD];
    __shared__ float scxyz[3];
    int fi = fps[b*NPT + s];
    if (tid < KK) snb[tid] = nbr[(b*NPT + s)*KK + tid];
    if (tid >= 32 && tid < 32+DD) scen[tid-32] = points[(long)b*DD*NN + (tid-32)*NN + fi];
    if (tid >= 96 && tid < 99)   scxyz[tid-96] = xyz[(long)b*3*NN + (tid-96)*NN + fi];
    __syncthreads();
    int k = tid & 31, cb = tid >> 5;
    int n = snb[k];
    int base = (b*NPT + s)*KK + k;
    #pragma unroll
    for (int q = 0; q < 8; ++q) {
        int c = q*8 + cb;
        float v = points[(long)b*DD*NN + c*NN + n];
        X0[(long)c*P_TOT + base] = v;
        X0[(long)(DD+c)*P_TOT + base] = v - scen[c];
    }
    if (cb < 3) {
        float v = xyz[(long)b*3*NN + cb*NN + n] - scxyz[cb];
        relbuf[(long)cb*P_TOT + base] = v;
    }
}

// ---------------- tf32 helpers ----------------
__device__ __forceinline__ uint32_t f2tf32(float v) {
    uint32_t r;
    asm("cvt.rna.tf32.f32 %0, %1;" : "=r"(r) : "f"(v));
    return r;
}
__device__ __forceinline__ void mma_tf32(float* d, uint32_t a0, uint32_t a1,
                                         uint32_t a2, uint32_t a3,
                                         uint32_t b0, uint32_t b1) {
    asm volatile("mma.sync.aligned.m16n8k8.row.col.f32.tf32.tf32.f32 "
        "{%0,%1,%2,%3},{%4,%5,%6,%7},{%8,%9},{%0,%1,%2,%3};"
        : "+f"(d[0]), "+f"(d[1]), "+f"(d[2]), "+f"(d[3])
        : "r"(a0), "r"(a1), "r"(a2), "r"(a3), "r"(b0), "r"(b1));
}

// ---------------- tensor-core fused GEMM ----------------
// Y[b][coBase+co][p] = sum_k A(co,k) * x'(k,p) + bias[co]
//   A(co,k) = TRANSA ? A[k*lda+co_glob] : A[co_glob*lda+k]
//   x'(k,p) = XFORM ? max(fma(x, xscale[k], xshift[k]), xlo[k]) : x
//   x       = (SUB ? X[k][p]-X2[k][p] : X[k][p]) * (PSCALE ? pscale[p] : 1)
// STATS: per-channel double sum/sumsq of Y via atomics.
// POOL:  instead of writing Y, write per-(channel, p/32) running max and min.
// ASYNCX: stage raw X through an NST-deep cp.async shared-memory ring.
template<int COUT, bool TRANSA, bool XFORM, bool SUB, bool PSCALE, bool STATS, bool POOL, bool ASYNCX>
__global__ void __launch_bounds__(256)
gemm_tc(const float* __restrict__ A, int lda, long aStride,
        const float* __restrict__ X, const float* __restrict__ X2, long xStride,
        const float* __restrict__ pscale, int psStride,
        float* __restrict__ Y, long yStride,
        const float* __restrict__ bias,
        const float* __restrict__ xscale, const float* __restrict__ xshift,
        const float* __restrict__ xlo,
        double* __restrict__ ssum, double* __restrict__ ssq,
        float* __restrict__ pmax, float* __restrict__ pmin,
        int Cin, int P)
{
    constexpr int MW = COUT / 4;     // warp tile M
    constexpr int MF = MW / 16;      // m16 fragments per warp
    constexpr int NW = (COUT*32)/256;   // scalar W loads per thread
    extern __shared__ uint32_t smd[];
    uint32_t* ringw = smd;                               // NST*4096 words (ASYNCX only)
    uint32_t* sX = smd + (ASYNCX ? NST*4096 : 0);        // 32*136
    uint32_t* sW = sX + 32*136;                          // COUT*36

    int by = blockIdx.y;
    A += (long)by * aStride;
    X += (long)by * xStride;
    if (SUB) X2 += (long)by * xStride;
    Y += (long)by * yStride;
    int coBase = blockIdx.z * COUT;
    int p0 = blockIdx.x * 128;
    const float* psc = PSCALE ? (pscale + (long)by*psStride + p0) : nullptr;

    int tid = threadIdx.x;
    int lane = tid & 31, wid = tid >> 5;
    int warpM = wid >> 1, warpN = wid & 1;
    int gid = lane >> 2, tig = lane & 3;

    float d[MF][8][4];
    #pragma unroll
    for (int mf = 0; mf < MF; ++mf)
        #pragma unroll
        for (int nf = 0; nf < 8; ++nf)
            #pragma unroll
            for (int i = 0; i < 4; ++i) d[mf][nf][i] = 0.f;

    uint32_t xs[16];
    uint32_t ws[NW];

    int nchunk = (Cin + 31) >> 5;

    // issue one chunk of raw X into the ring via cp.async (16B per op, zfill tail)
    auto issueChunk = [&](int c) {
        int k0 = c*32;
        uint32_t* slot = ringw + (c % NST)*4096;
        #pragma unroll
        for (int j = 0; j < 4; ++j) {
            int id = tid + j*256;
            int row = id >> 5, c4 = id & 31;
            int k = k0 + row;
            unsigned sa = (unsigned)__cvta_generic_to_shared(slot + row*128 + c4*4);
            const float* src = X + (long)(k < Cin ? k : 0)*P + p0 + c4*4;
            int sz = (k < Cin) ? 16 : 0;
            asm volatile("cp.async.cg.shared.global [%0], [%1], 16, %2;\n"
                         :: "r"(sa), "l"(src), "r"(sz) : "memory");
        }
        asm volatile("cp.async.commit_group;\n" ::: "memory");
    };

    // ring -> registers (transform + tf32 convert)
    auto loadX_ring = [&](int c) {
        const uint32_t* rw = ringw + (c % NST)*4096;
        int k0 = c*32;
        #pragma unroll
        for (int j = 0; j < 4; ++j) {
            int id = tid + j*256;
            int row = id >> 5, c4 = id & 31;
            int k = k0 + row;
            uint4 r4 = *reinterpret_cast<const uint4*>(rw + row*128 + c4*4);
            float4 v;
            v.x = __uint_as_float(r4.x); v.y = __uint_as_float(r4.y);
            v.z = __uint_as_float(r4.z); v.w = __uint_as_float(r4.w);
            if (XFORM && k < Cin) {
                float s = xscale[k], h = xshift[k], l = xlo[k];
                v.x = fmaxf(fmaf(v.x, s, h), l);
                v.y = fmaxf(fmaf(v.y, s, h), l);
                v.z = fmaxf(fmaf(v.z, s, h), l);
                v.w = fmaxf(fmaf(v.w, s, h), l);
            }
            xs[j*4+0] = f2tf32(v.x); xs[j*4+1] = f2tf32(v.y);
            xs[j*4+2] = f2tf32(v.z); xs[j*4+3] = f2tf32(v.w);
        }
    };

    // direct gmem -> registers path (non-async)
    auto loadX_g = [&](int k0) {
        #pragma unroll
        for (int j = 0; j < 4; ++j) {
            int id = tid + j*256;
            int row = id >> 5, c4 = id & 31;
            int k = k0 + row;
            float4 v = make_float4(0.f, 0.f, 0.f, 0.f);
            if (k < Cin) {
                v = *reinterpret_cast<const float4*>(&X[(long)k*P + p0 + c4*4]);
                if (SUB) {
                    float4 u = *reinterpret_cast<const float4*>(&X2[(long)k*P + p0 + c4*4]);
                    v.x -= u.x; v.y -= u.y; v.z -= u.z; v.w -= u.w;
                }
                if (XFORM) {
                    float s = xscale[k], h = xshift[k], l = xlo[k];
                    v.x = fmaxf(fmaf(v.x, s, h), l);
                    v.y = fmaxf(fmaf(v.y, s, h), l);
                    v.z = fmaxf(fmaf(v.z, s, h), l);
                    v.w = fmaxf(fmaf(v.w, s, h), l);
                }
                if (PSCALE) {
                    float4 pv = *reinterpret_cast<const float4*>(&psc[c4*4]);
                    v.x *= pv.x; v.y *= pv.y; v.z *= pv.z; v.w *= pv.w;
                }
            }
            xs[j*4+0] = f2tf32(v.x); xs[j*4+1] = f2tf32(v.y);
            xs[j*4+2] = f2tf32(v.z); xs[j*4+3] = f2tf32(v.w);
        }
    };
    // scalar W loads (lda may be odd -> no vector LDG)
    auto loadW = [&](int k0) {
        #pragma unroll
        for (int j = 0; j < NW; ++j) {
            int id = tid + j*256;          // id = co*32 + kk
            int co = id >> 5, kk = id & 31;
            int k = k0 + kk;
            float w = 0.f;
            if (k < Cin)
                w = TRANSA ? A[(long)k*lda + coBase + co]
                           : A[(long)(coBase + co)*lda + k];
            ws[j] = f2tf32(w);
        }
    };
    auto storeTiles = [&]() {
        #pragma unroll
        for (int j = 0; j < 4; ++j) {
            int id = tid + j*256;
            int row = id >> 5, c4 = id & 31;
            *reinterpret_cast<uint4*>(sX + row*136 + c4*4) =
                make_uint4(xs[j*4], xs[j*4+1], xs[j*4+2], xs[j*4+3]);
        }
        #pragma unroll
        for (int j = 0; j < NW; ++j) {
            int id = tid + j*256;
            int co = id >> 5, kk = id & 31;
            sW[co*36 + kk] = ws[j];
        }
    };
    auto mmaPhase = [&]() {
        #pragma unroll
        for (int k8 = 0; k8 < 4; ++k8) {
            int kb = k8*8;
            uint32_t a[MF][4];
            #pragma unroll
            for (int mf = 0; mf < MF; ++mf) {
                int r = warpM*MW + mf*16 + gid;
                a[mf][0] = sW[r*36 + kb + tig];
                a[mf][1] = sW[(r+8)*36 + kb + tig];
                a[mf][2] = sW[r*36 + kb + tig + 4];
                a[mf][3] = sW[(r+8)*36 + kb + tig + 4];
            }
            #pragma unroll
            for (int nf = 0; nf < 8; ++nf) {
                int col = warpN*64 + nf*8 + gid;
                uint32_t b0 = sX[(kb + tig)*136 + col];
                uint32_t b1 = sX[(kb + tig + 4)*136 + col];
                #pragma unroll
                for (int mf = 0; mf < MF; ++mf)
                    mma_tf32(d[mf][nf], a[mf][0], a[mf][1], a[mf][2], a[mf][3], b0, b1);
            }
        }
    };

    if (ASYNCX) {
        issueChunk(0);
        if (nchunk > 1) issueChunk(1);
        loadW(0);
        for (int c0 = 0; c0 < nchunk; ++c0) {
            if (c0 + 2 <= nchunk)
                asm volatile("cp.async.wait_group 1;\n" ::: "memory");
            else
                asm volatile("cp.async.wait_group 0;\n" ::: "memory");
            __syncthreads();                       // ring visible + sX free (prev MMA done)
            loadX_ring(c0);
            storeTiles();
            __syncthreads();
            if (c0 + 2 < nchunk) issueChunk(c0 + 2);
            if (c0 + 1 < nchunk) loadW((c0 + 1) * 32);
            mmaPhase();
        }
    } else {
        loadX_g(0);
        loadW(0);
        for (int c0 = 0; c0 < nchunk; ++c0) {
            storeTiles();
            __syncthreads();
            if (c0 + 1 < nchunk) { loadX_g((c0+1)*32); loadW((c0+1)*32); }
            mmaPhase();
            __syncthreads();
        }
    }

    // epilogue
    #pragma unroll
    for (int mf = 0; mf < MF; ++mf) {
        int r = warpM*MW + mf*16 + gid;
        int co0 = coBase + r, co1 = co0 + 8;
        float bb0 = bias ? bias[co0] : 0.f;
        float bb1 = bias ? bias[co1] : 0.f;
        double s0 = 0.0, q0 = 0.0, s1 = 0.0, q1 = 0.0;
        float mxa[2], mna[2], mxb[2], mnb[2];
        if (POOL) {
            mxa[0] = mxa[1] = mxb[0] = mxb[1] = -3.4e38f;
            mna[0] = mna[1] = mnb[0] = mnb[1] =  3.4e38f;
        }
        #pragma unroll
        for (int nf = 0; nf < 8; ++nf) {
            int p = p0 + warpN*64 + nf*8 + 2*tig;
            float o0 = d[mf][nf][0] + bb0, o1 = d[mf][nf][1] + bb0;
            float o2 = d[mf][nf][2] + bb1, o3 = d[mf][nf][3] + bb1;
            if (!POOL) {
                *reinterpret_cast<float2*>(&Y[(long)co0*P + p]) = make_float2(o0, o1);
                *reinterpret_cast<float2*>(&Y[(long)co1*P + p]) = make_float2(o2, o3);
            } else {
                int g = nf >> 2;
                mxa[g] = fmaxf(mxa[g], fmaxf(o0, o1));
                mna[g] = fminf(mna[g], fminf(o0, o1));
                mxb[g] = fmaxf(mxb[g], fmaxf(o2, o3));
                mnb[g] = fminf(mnb[g], fminf(o2, o3));
            }
            if (STATS) {
                s0 += (double)o0 + (double)o1;
                q0 += (double)o0*o0 + (double)o1*o1;
                s1 += (double)o2 + (double)o3;
                q1 += (double)o2*o2 + (double)o3*o3;
            }
        }
        if (POOL) {
            int PS = P >> 5;
            #pragma unroll
            for (int g = 0; g < 2; ++g) {
                float ma = mxa[g], na = mna[g], mb = mxb[g], nb = mnb[g];
                #pragma unroll
                for (int off = 1; off <= 2; off <<= 1) {
                    ma = fmaxf(ma, __shfl_xor_sync(0xFFFFFFFFu, ma, off));
                    na = fminf(na, __shfl_xor_sync(0xFFFFFFFFu, na, off));
                    mb = fmaxf(mb, __shfl_xor_sync(0xFFFFFFFFu, mb, off));
                    nb = fminf(nb, __shfl_xor_sync(0xFFFFFFFFu, nb, off));
                }
                if (tig == 0) {
                    int ps = (p0 >> 5) + warpN*2 + g;
                    pmax[(long)co0*PS + ps] = ma;
                    pmin[(long)co0*PS + ps] = na;
                    pmax[(long)co1*PS + ps] = mb;
                    pmin[(long)co1*PS + ps] = nb;
                }
            }
        }
        if (STATS) {
            #pragma unroll
            for (int off = 1; off <= 2; off <<= 1) {
                s0 += __shfl_xor_sync(0xFFFFFFFFu, s0, off);
                q0 += __shfl_xor_sync(0xFFFFFFFFu, q0, off);
                s1 += __shfl_xor_sync(0xFFFFFFFFu, s1, off);
                q1 += __shfl_xor_sync(0xFFFFFFFFu, q1, off);
            }
            if (tig == 0) {
                atomicAdd(&ssum[co0], s0);
                atomicAdd(&ssq[co0], q0);
                atomicAdd(&ssum[co1], s1);
                atomicAdd(&ssq[co1], q1);
            }
        }
    }
}

// ---------------- finalize BN -> affine ----------------
__global__ void finalize_bn(const double* __restrict__ ssum, const double* __restrict__ ssq,
                            int Cbn, double count,
                            const float* __restrict__ g, const float* __restrict__ be,
                            float* __restrict__ scale, float* __restrict__ shift,
                            float* __restrict__ lo) {
    int c = threadIdx.x;
    if (c < Cbn) {
        double m = ssum[c] / count;
        double v = ssq[c] / count - m*m;
        float sc = g[c] * rsqrtf((float)v + EPSF);
        scale[c] = sc;
        shift[c] = be[c] - (float)m * sc;
        lo[c] = 0.f;
    } else {
        scale[c] = 1.f;
        shift[c] = 0.f;
        lo[c] = -3.4e38f;
    }
}

// ---------------- pooled BN+ReLU finalize: xp[b][c][s] ----------------
__global__ void pool_finalize(float* __restrict__ xp,
                              const float* __restrict__ pmax, const float* __restrict__ pmin,
                              const float* __restrict__ scale, const float* __restrict__ shift) {
    int i = blockIdx.x*256 + threadIdx.x;
    if (i >= BB*128*NPT) return;
    int s = i & 511, c = (i >> 9) & 127, b = i >> 16;
    int src = c*(BB*NPT) + b*NPT + s;
    float sc = scale[c], sh = shift[c];
    float v = (sc >= 0.f) ? pmax[src] : pmin[src];
    xp[i] = fmaxf(fmaf(v, sc, sh), 0.f);
}

// ---------------- softmax rows ----------------
__global__ void softmax_kernel(float* __restrict__ e) {
    int gw = (blockIdx.x*256 + threadIdx.x) >> 5;
    int lane = threadIdx.x & 31;
    if (gw >= BB*NPT) return;
    float* row = e + (long)gw * NPT;
    float v[16];
    float mx = -3.4e38f;
    #pragma unroll
    for (int i = 0; i < 16; ++i) { v[i] = row[lane + i*32]; mx = fmaxf(mx, v[i]); }
    #pragma unroll
    for (int off = 16; off > 0; off >>= 1)
        mx = fmaxf(mx, __shfl_xor_sync(0xFFFFFFFFu, mx, off));
    float sum = 0.f;
    #pragma unroll
    for (int i = 0; i < 16; ++i) { v[i] = expf(v[i] - mx); sum += v[i]; }
    #pragma unroll
    for (int off = 16; off > 0; off >>= 1)
        sum += __shfl_xor_sync(0xFFFFFFFFu, sum, off);
    #pragma unroll
    for (int i = 0; i < 16; ++i) row[lane + i*32] = v[i] / sum;
}

// ---------------- column sums (store reciprocal) ----------------
__global__ void colsum_kernel(const float* __restrict__ e, float* __restrict__ colrcp) {
    int b = blockIdx.x, m = blockIdx.y*128 + threadIdx.x;
    const float* E = e + (long)b * NPT * NPT;
    float s = 0.f;
    for (int n = 0; n < NPT; ++n) s += E[n*NPT + m];
    colrcp[b*NPT + m] = 1.f / (1e-9f + s);
}

// ---------------- final residual ----------------
__global__ void final_kernel(float* __restrict__ out, const float* __restrict__ xp,
                             const float* __restrict__ y,
                             const float* __restrict__ scale, const float* __restrict__ shift,
                             const float* __restrict__ alpha, const float* __restrict__ beta) {
    int i = blockIdx.x*256 + threadIdx.x;
    if (i >= BB*128*NPT) return;
    int c = (i >> 9) & 127;
    float xr = fmaxf(fmaf(y[i], scale[c], shift[c]), 0.f);
    out[i] = xp[i] + alpha[c]*xr + beta[c];
}

// ---------------- launch ----------------
extern "C" void kernel_launch(void* const* d_in, const int* in_sizes, int n_in,
                              void* d_out, int out_size) {
    const float* xyz    = (const float*)d_in[0];
    const float* points = (const float*)d_in[1];
    const float* w0 = (const float*)d_in[2];
    const float* b0 = (const float*)d_in[3];
    const float* g0 = (const float*)d_in[4];
    const float* be0= (const float*)d_in[5];
    const float* w1 = (const float*)d_in[6];
    const float* b1 = (const float*)d_in[7];
    const float* g1 = (const float*)d_in[8];
    const float* be1= (const float*)d_in[9];
    const float* w2 = (const float*)d_in[10];
    const float* b2 = (const float*)d_in[11];
    const float* g2 = (const float*)d_in[12];
    const float* be2= (const float*)d_in[13];
    const float* wl = (const float*)d_in[14];
    const float* bl = (const float*)d_in[15];
    const float* gl = (const float*)d_in[16];
    const float* bel= (const float*)d_in[17];
    const float* wv = (const float*)d_in[18];
    const float* bv = (const float*)d_in[19];
    const float* wt = (const float*)d_in[20];
    const float* bt = (const float*)d_in[21];
    const float* gn = (const float*)d_in[22];
    const float* gb = (const float*)d_in[23];
    const float* alpha = (const float*)d_in[24];
    const float* beta  = (const float*)d_in[25];
    float* out = (float*)d_out;

    float *bufA, *bufB, *xp, *x0, *energy, *x2, *y, *tfs, *tfh, *tfl, *colrcp, *pmax, *pmin;
    double *ssum, *ssq;
    int *fps, *nbr;
    cudaGetSymbolAddress((void**)&bufA, g_bufA);
    cudaGetSymbolAddress((void**)&bufB, g_bufB);
    cudaGetSymbolAddress((void**)&xp, g_xp);
    cudaGetSymbolAddress((void**)&x0, g_x0);
    cudaGetSymbolAddress((void**)&energy, g_energy);
    cudaGetSymbolAddress((void**)&x2, g_x2);
    cudaGetSymbolAddress((void**)&y, g_y);
    cudaGetSymbolAddress((void**)&ssum, g_ssum);
    cudaGetSymbolAddress((void**)&ssq, g_ssq);
    cudaGetSymbolAddress((void**)&tfs, g_tfs);
    cudaGetSymbolAddress((void**)&tfh, g_tfh);
    cudaGetSymbolAddress((void**)&tfl, g_tfl);
    cudaGetSymbolAddress((void**)&colrcp, g_colrcp);
    cudaGetSymbolAddress((void**)&pmax, g_pmax);
    cudaGetSymbolAddress((void**)&pmin, g_pmin);
    cudaGetSymbolAddress((void**)&fps, g_fps);
    cudaGetSymbolAddress((void**)&nbr, g_nbr);

    const int SMEM_PTS = 3*NN*sizeof(float);   // 48KB
    cudaFuncSetAttribute(fps_kernel,  cudaFuncAttributeMaxDynamicSharedMemorySize, 64*1024);
    cudaFuncSetAttribute(ball_kernel, cudaFuncAttributeMaxDynamicSharedMemorySize, 64*1024);

    // dynamic smem sizes
    const int SM_RING = NST*32*128*4;               // 49152
    const int SM_SX   = 32*136*4;                   // 17408
    const int SM_A64  = SM_RING + SM_SX + 64*36*4;  // 75776
    const int SM_A128 = SM_RING + SM_SX + 128*36*4; // 84992
    const int SM_N128 = SM_SX + 128*36*4;           // 35840
    cudaFuncSetAttribute(gemm_tc<64,false,false,false,false,true,false,true>,
                         cudaFuncAttributeMaxDynamicSharedMemorySize, SM_A64);
    cudaFuncSetAttribute(gemm_tc<64,false,true,false,false,true,false,true>,
                         cudaFuncAttributeMaxDynamicSharedMemorySize, SM_A64);
    cudaFuncSetAttribute(gemm_tc<128,false,true,false,false,true,false,true>,
                         cudaFuncAttributeMaxDynamicSharedMemorySize, SM_A128);
    cudaFuncSetAttribute(gemm_tc<128,false,true,false,false,true,true,true>,
                         cudaFuncAttributeMaxDynamicSharedMemorySize, SM_A128);

    const double CNT_P = (double)P_TOT;
    const double CNT_S = (double)(BB*NPT);

    // geometry (ordered so the 4th launch = L0 tensor-core GEMM for ncu capture)
    fps_kernel<<<BB, 1024, SMEM_PTS>>>(xyz, fps);
    ball_kernel<<<dim3(NPT/8, BB), 256, SMEM_PTS>>>(xyz, fps, nbr);
    feat_kernel<<<dim3(NPT, BB), 256>>>(points, xyz, fps, nbr, bufB, bufA + 128L*P_TOT);

    // L0: 128->64, stats slot0 (cp.async)
    gemm_tc<64,false,false,false,false,true,false,true><<<dim3(P_TOT/128,1,1), 256, SM_A64>>>(
        w0, 128, 0, bufB, nullptr, 0, nullptr, 0, bufA, 0, b0,
        nullptr, nullptr, nullptr, ssum+0, ssq+0, nullptr, nullptr, 128, P_TOT);
    newxyz_kernel<<<(BB*3*NPT + 255)/256, 256>>>(out, xyz, fps);
    finalize_bn<<<1, 64>>>(ssum+0, ssq+0, 64, CNT_P, g0, be0, tfs+0, tfh+0, tfl+0);

    // L1: 64->64, xform tf0, stats slot1 (cp.async)
    gemm_tc<64,false,true,false,false,true,false,true><<<dim3(P_TOT/128,1,1), 256, SM_A64>>>(
        w1, 64, 0, bufA, nullptr, 0, nullptr, 0, bufB, 0, b1,
        tfs+0, tfh+0, tfl+0, ssum+128, ssq+128, nullptr, nullptr, 64, P_TOT);
    finalize_bn<<<1, 64>>>(ssum+128, ssq+128, 64, CNT_P, g1, be1, tfs+132, tfh+132, tfl+132);

    // L2: 64->128, xform tf1, stats slot2 (cp.async)
    gemm_tc<128,false,true,false,false,true,false,true><<<dim3(P_TOT/128,1,1), 256, SM_A128>>>(
        w2, 64, 0, bufB, nullptr, 0, nullptr, 0, bufA, 0, b2,
        tfs+132, tfh+132, tfl+132, ssum+256, ssq+256, nullptr, nullptr, 64, P_TOT);
    finalize_bn<<<1, 131>>>(ssum+256, ssq+256, 128, CNT_P, g2, be2, tfs+264, tfh+264, tfl+264);

    // Ll: 131->128, xform tf2, stats slot3, POOL epilogue (cp.async)
    gemm_tc<128,false,true,false,false,true,true,true><<<dim3(P_TOT/128,1,1), 256, SM_A128>>>(
        wl, 131, 0, bufA, nullptr, 0, nullptr, 0, bufB, 0, bl,
        tfs+264, tfh+264, tfl+264, ssum+384, ssq+384, pmax, pmin, 131, P_TOT);
    finalize_bn<<<1, 128>>>(ssum+384, ssq+384, 128, CNT_P, gl, bel, tfs+396, tfh+396, tfl+396);
    pool_finalize<<<(BB*128*NPT + 255)/256, 256>>>(xp, pmax, pmin, tfs+396, tfh+396);

    // attention (small GEMMs: direct path)
    gemm_tc<128,false,false,false,false,false,false,false><<<dim3(NPT/128, BB, 1), 256, SM_N128>>>(
        wv, 128, 0, xp, nullptr, PB, nullptr, 0, x0, PB, bv,
        nullptr, nullptr, nullptr, nullptr, nullptr, nullptr, nullptr, 128, NPT);
    gemm_tc<128,true,false,false,false,false,false,false><<<dim3(NPT/128, BB, 4), 256, SM_N128>>>(
        xp, NPT, PB, x0, nullptr, PB, nullptr, 0, energy, (long)NPT*NPT, nullptr,
        nullptr, nullptr, nullptr, nullptr, nullptr, nullptr, nullptr, 128, NPT);
    softmax_kernel<<<(BB*NPT*32 + 255)/256, 256>>>(energy);
    colsum_kernel<<<dim3(BB, NPT/128), 128>>>(energy, colrcp);
    // x2 = x0 @ attn (column renorm fused via PSCALE)
    gemm_tc<128,false,false,false,true,false,false,false><<<dim3(NPT/128, BB, 1), 256, SM_N128>>>(
        x0, NPT, PB, energy, nullptr, (long)NPT*NPT, colrcp, NPT, x2, PB, nullptr,
        nullptr, nullptr, nullptr, nullptr, nullptr, nullptr, nullptr, NPT, NPT);
    // wt GEMM on (xp - x2), stats slot4
    gemm_tc<128,false,false,true,false,true,false,false><<<dim3(NPT/128, BB, 1), 256, SM_N128>>>(
        wt, 128, 0, xp, x2, PB, nullptr, 0, y, PB, bt,
        nullptr, nullptr, nullptr, ssum+512, ssq+512, nullptr, nullptr, 128, NPT);
    finalize_bn<<<1, 128>>>(ssum+512, ssq+512, 128, CNT_S, gn, gb, tfs+528, tfh+528, tfl+528);

    final_kernel<<<(BB*128*NPT + 255)/256, 256>>>(out + BB*3*NPT, xp, y,
        tfs+528, tfh+528, alpha, beta);
}

// round 9
// speedup vs baseline: 2.6065x; 1.0750x over previous
#include <cuda_runtime.h>
#include <cuda_bf16.h>
#include <cuda_fp16.h>
#include <cstdint>
#include <math.h>

// ---------------- constants ----------------
#define BB   16
#define NN   4096
#define DD   64
#define NPT  512
#define KK   32
#define P_TOT (BB*NPT*KK)     // 262144
#define PB   (128*NPT)        // 65536 per-batch (c,s) block
#define EPSF 1e-5f
#define NST  3                // cp.async ring depth

// ---------------- scratch ----------------
__device__ __half g_hA[131L * P_TOT];           // 131 x P halves (rows 128..130 = rel_xyz)
__device__ __half g_hB[128L * P_TOT];           // 128 x P halves
__device__ float g_xp[BB*128*NPT];
__device__ float g_x0[BB*128*NPT];
__device__ float g_energy[BB*NPT*NPT];
__device__ float g_x2[BB*128*NPT];
__device__ float g_y[BB*128*NPT];
__device__ float g_pmax[128*BB*NPT];
__device__ float g_pmin[128*BB*NPT];
__device__ double g_ssum[5*128];
__device__ double g_ssq[5*128];
__device__ float g_tfs[5*132];
__device__ float g_tfh[5*132];
__device__ float g_tfl[5*132];
__device__ float g_colrcp[BB*NPT];
__device__ int   g_fps[BB*NPT];
__device__ int   g_nbr[BB*NPT*KK];

// ---------------- FPS ----------------
__global__ void __launch_bounds__(1024) fps_kernel(const float* __restrict__ xyz,
                                                   int* __restrict__ fps) {
    extern __shared__ char xsm[];
    float* sm = (float*)xsm;
    float* sx = sm;
    float* sy = sm + NN;
    float* sz = sm + 2*NN;
    __shared__ unsigned long long swarp[32];
    __shared__ int sfar;
    int b = blockIdx.x, tid = threadIdx.x;
    const float* base = xyz + (long)b*3*NN;
    for (int i = tid; i < NN; i += 1024) {
        sx[i] = base[i];
        sy[i] = base[NN + i];
        sz[i] = base[2*NN + i];
    }
    __syncthreads();
    float dist[4];
    dist[0] = dist[1] = dist[2] = dist[3] = 1e10f;
    int far = 0;
    for (int it = 0; it < NPT; ++it) {
        if (tid == 0) fps[b*NPT + it] = far;
        float cx = sx[far], cy = sy[far], cz = sz[far];
        unsigned long long best = 0ull;
        #pragma unroll
        for (int j = 0; j < 4; ++j) {
            int n = tid + j*1024;
            float dx = sx[n]-cx, dy = sy[n]-cy, dz = sz[n]-cz;
            float d = dx*dx + dy*dy + dz*dz;
            float dd = fminf(dist[j], d);
            dist[j] = dd;
            unsigned long long key =
                ((unsigned long long)__float_as_uint(dd) << 32) |
                (unsigned long long)(0xFFFFFFFFu - (unsigned)n);
            best = (key > best) ? key : best;
        }
        #pragma unroll
        for (int off = 16; off > 0; off >>= 1) {
            unsigned long long o = __shfl_down_sync(0xFFFFFFFFu, best, off);
            best = (o > best) ? o : best;
        }
        if ((tid & 31) == 0) swarp[tid >> 5] = best;
        __syncthreads();
        if (tid < 32) {
            best = swarp[tid];
            #pragma unroll
            for (int off = 16; off > 0; off >>= 1) {
                unsigned long long o = __shfl_down_sync(0xFFFFFFFFu, best, off);
                best = (o > best) ? o : best;
            }
            if (tid == 0)
                sfar = (int)(0xFFFFFFFFu - (unsigned)(best & 0xFFFFFFFFull));
        }
        __syncthreads();
        far = sfar;
    }
}

// ---------------- new_xyz output ----------------
__global__ void newxyz_kernel(float* __restrict__ out, const float* __restrict__ xyz,
                              const int* __restrict__ fps) {
    int i = blockIdx.x*256 + threadIdx.x;
    if (i >= BB*3*NPT) return;
    int s = i & 511;
    int c = (i >> 9) % 3;
    int b = i / (3*NPT);
    out[i] = xyz[(long)b*3*NN + c*NN + fps[b*NPT + s]];
}

// ---------------- ball query ----------------
__global__ void __launch_bounds__(256) ball_kernel(const float* __restrict__ xyz,
                                                   const int* __restrict__ fps,
                                                   int* __restrict__ nbr) {
    extern __shared__ char xsm[];
    float* sm = (float*)xsm;
    float* sx = sm;
    float* sy = sm + NN;
    float* sz = sm + 2*NN;
    __shared__ int snb[8][KK];
    int b = blockIdx.y, tid = threadIdx.x;
    const float* base = xyz + (long)b*3*NN;
    for (int i = tid; i < NN; i += 256) {
        sx[i] = base[i];
        sy[i] = base[NN + i];
        sz[i] = base[2*NN + i];
    }
    __syncthreads();
    int w = tid >> 5, lane = tid & 31;
    int s = blockIdx.x*8 + w;
    int fi = fps[b*NPT + s];
    float cx = sx[fi], cy = sy[fi], cz = sz[fi];
    float cn = cx*cx + cy*cy + cz*cz;
    const float R2 = (float)(0.4*0.4);
    int cnt = 0;
    for (int n0 = 0; n0 < NN && cnt < KK; n0 += 32) {
        int n = n0 + lane;
        float px = sx[n], py = sy[n], pz = sz[n];
        float pn = px*px + py*py + pz*pz;
        float dt = cx*px + cy*py + cz*pz;
        float sq = (cn + pn) - 2.0f*dt;
        bool in = !(sq > R2);
        unsigned m = __ballot_sync(0xFFFFFFFFu, in);
        int pos = cnt + __popc(m & ((1u << lane) - 1u));
        if (in && pos < KK) snb[w][pos] = n;
        cnt += __popc(m);
    }
    __syncwarp();
    int v = (lane < cnt) ? snb[w][lane] : snb[w][0];
    nbr[(b*NPT + s)*KK + lane] = v;
}

// ---------------- feature build (half output; also zeros BN stats) ----------------
__global__ void __launch_bounds__(256) feat_kernel(const float* __restrict__ points,
                                                   const float* __restrict__ xyz,
                                                   const int* __restrict__ fps,
                                                   const int* __restrict__ nbr,
                                                   __half* __restrict__ X0,
                                                   __half* __restrict__ relbuf) {
    int s = blockIdx.x, b = blockIdx.y, tid = threadIdx.x;
    if (s == 0 && b == 0) {
        for (int i = tid; i < 5*128; i += 256) { g_ssum[i] = 0.0; g_ssq[i] = 0.0; }
    }
    __shared__ int snb[KK];
    __shared__ float scen[DD];
    __shared__ float scxyz[3];
    int fi = fps[b*NPT + s];
    if (tid < KK) snb[tid] = nbr[(b*NPT + s)*KK + tid];
    if (tid >= 32 && tid < 32+DD) scen[tid-32] = points[(long)b*DD*NN + (tid-32)*NN + fi];
    if (tid >= 96 && tid < 99)   scxyz[tid-96] = xyz[(long)b*3*NN + (tid-96)*NN + fi];
    __syncthreads();
    int k = tid & 31, cb = tid >> 5;
    int n = snb[k];
    int base = (b*NPT + s)*KK + k;
    #pragma unroll
    for (int q = 0; q < 8; ++q) {
        int c = q*8 + cb;
        float v = points[(long)b*DD*NN + c*NN + n];
        X0[(long)c*P_TOT + base] = __float2half(v);
        X0[(long)(DD+c)*P_TOT + base] = __float2half(v - scen[c]);
    }
    if (cb < 3) {
        float v = xyz[(long)b*3*NN + cb*NN + n] - scxyz[cb];
        relbuf[(long)cb*P_TOT + base] = __float2half(v);
    }
}

// ---------------- mma helpers ----------------
__device__ __forceinline__ uint32_t f2tf32(float v) {
    uint32_t r;
    asm("cvt.rna.tf32.f32 %0, %1;" : "=r"(r) : "f"(v));
    return r;
}
__device__ __forceinline__ void mma_tf32(float* d, uint32_t a0, uint32_t a1,
                                         uint32_t a2, uint32_t a3,
                                         uint32_t b0, uint32_t b1) {
    asm volatile("mma.sync.aligned.m16n8k8.row.col.f32.tf32.tf32.f32 "
        "{%0,%1,%2,%3},{%4,%5,%6,%7},{%8,%9},{%0,%1,%2,%3};"
        : "+f"(d[0]), "+f"(d[1]), "+f"(d[2]), "+f"(d[3])
        : "r"(a0), "r"(a1), "r"(a2), "r"(a3), "r"(b0), "r"(b1));
}
__device__ __forceinline__ void mma_f16(float* d, uint32_t a0, uint32_t a1,
                                        uint32_t a2, uint32_t a3,
                                        uint32_t b0, uint32_t b1) {
    asm volatile("mma.sync.aligned.m16n8k16.row.col.f32.f16.f16.f32 "
        "{%0,%1,%2,%3},{%4,%5,%6,%7},{%8,%9},{%0,%1,%2,%3};"
        : "+f"(d[0]), "+f"(d[1]), "+f"(d[2]), "+f"(d[3])
        : "r"(a0), "r"(a1), "r"(a2), "r"(a3), "r"(b0), "r"(b1));
}

// ================= fp16 big-layer GEMM =================
// Y[co][p] = sum_k W(co,k) * x'(k,p) + bias[co],  P = P_TOT fixed.
// x'(k,p) = XFORM ? max(fma(x, xscale[k], xshift[k]), xlo[k]) : x      (x = half input)
// STATS: per-channel double sum/sumsq of fp32 outputs via atomics.
// POOL:  per-(channel, p/32) running max and min instead of Y store.
template<int COUT, bool XFORM, bool STATS, bool POOL>
__global__ void __launch_bounds__(256)
gemm_h(const float* __restrict__ A, int lda,
       const __half* __restrict__ X,
       __half* __restrict__ Y,
       const float* __restrict__ bias,
       const float* __restrict__ xscale, const float* __restrict__ xshift,
       const float* __restrict__ xlo,
       double* __restrict__ ssum, double* __restrict__ ssq,
       float* __restrict__ pmax, float* __restrict__ pmin,
       int Cin)
{
    constexpr int MW = COUT / 4;       // warp tile M
    constexpr int MF = MW / 16;        // m16 fragments per warp
    constexpr int NH2 = COUT / 16;     // W half2 per thread per chunk
    extern __shared__ char xsm[];
    __half* ringh = (__half*)xsm;              // NST * 32*128 halves
    __half* sXh = ringh + NST*4096;            // [128][36] transposed tile
    __half* sWh = sXh + 128*36;                // [COUT][40]

    int p0 = blockIdx.x * 128;
    int tid = threadIdx.x;
    int lane = tid & 31, wid = tid >> 5;
    int warpM = wid >> 1, warpN = wid & 1;
    int gid = lane >> 2, tig = lane & 3;

    float d[MF][8][4];
    #pragma unroll
    for (int mf = 0; mf < MF; ++mf)
        #pragma unroll
        for (int nf = 0; nf < 8; ++nf)
            #pragma unroll
            for (int i = 0; i < 4; ++i) d[mf][nf][i] = 0.f;

    float wsf[2*NH2];
    int nchunk = (Cin + 31) >> 5;

    auto issueChunk = [&](int c) {
        int k0 = c*32;
        __half* slot = ringh + (c % NST)*4096;
        #pragma unroll
        for (int j = 0; j < 2; ++j) {
            int idx = tid + j*256;             // 0..511 : 16B segments
            int row = idx >> 4, seg = idx & 15;
            int k = k0 + row;
            unsigned sa = (unsigned)__cvta_generic_to_shared(slot + row*128 + seg*8);
            const __half* src = X + (long)(k < Cin ? k : 0)*P_TOT + p0 + seg*8;
            int sz = (k < Cin) ? 16 : 0;
            asm volatile("cp.async.cg.shared.global [%0], [%1], 16, %2;\n"
                         :: "r"(sa), "l"(src), "r"(sz) : "memory");
        }
        asm volatile("cp.async.commit_group;\n" ::: "memory");
    };

    // ring -> transform -> transposed sXh[p][k]
    auto stageX = [&](int c) {
        const __half* rw = ringh + (c % NST)*4096;
        int p = tid & 127;
        int kh = (tid >> 7) << 4;            // 0 or 16
        int k0c = c*32;
        #pragma unroll
        for (int i = 0; i < 16; i += 2) {
            int k = kh + i;
            float v0 = __half2float(rw[k*128 + p]);
            float v1 = __half2float(rw[(k+1)*128 + p]);
            if (XFORM) {
                int kg = k0c + k;
                if (kg < Cin)     v0 = fmaxf(fmaf(v0, xscale[kg], xshift[kg]), xlo[kg]);
                if (kg + 1 < Cin) v1 = fmaxf(fmaf(v1, xscale[kg+1], xshift[kg+1]), xlo[kg+1]);
            }
            *reinterpret_cast<__half2*>(&sXh[p*36 + k]) = __floats2half2_rn(v0, v1);
        }
    };

    auto loadWreg = [&](int k0c) {
        #pragma unroll
        for (int j = 0; j < NH2; ++j) {
            int hid = tid + j*256;
            int co = hid >> 4, kp = hid & 15;
            int k = k0c + 2*kp;
            wsf[2*j]   = (k   < Cin) ? A[(long)co*lda + k]   : 0.f;
            wsf[2*j+1] = (k+1 < Cin) ? A[(long)co*lda + k+1] : 0.f;
        }
    };
    auto storeW = [&]() {
        #pragma unroll
        for (int j = 0; j < NH2; ++j) {
            int hid = tid + j*256;
            int co = hid >> 4, kp = hid & 15;
            *reinterpret_cast<__half2*>(&sWh[co*40 + 2*kp]) =
                __floats2half2_rn(wsf[2*j], wsf[2*j+1]);
        }
    };

    auto mmaPhase = [&]() {
        #pragma unroll
        for (int g16 = 0; g16 < 32; g16 += 16) {
            uint32_t a[MF][4];
            #pragma unroll
            for (int mf = 0; mf < MF; ++mf) {
                int r = warpM*MW + mf*16 + gid;
                a[mf][0] = *reinterpret_cast<const uint32_t*>(&sWh[r*40 + g16 + 2*tig]);
                a[mf][1] = *reinterpret_cast<const uint32_t*>(&sWh[(r+8)*40 + g16 + 2*tig]);
                a[mf][2] = *reinterpret_cast<const uint32_t*>(&sWh[r*40 + g16 + 2*tig + 8]);
                a[mf][3] = *reinterpret_cast<const uint32_t*>(&sWh[(r+8)*40 + g16 + 2*tig + 8]);
            }
            #pragma unroll
            for (int nf = 0; nf < 8; ++nf) {
                int col = warpN*64 + nf*8 + gid;
                uint32_t b0 = *reinterpret_cast<const uint32_t*>(&sXh[col*36 + g16 + 2*tig]);
                uint32_t b1 = *reinterpret_cast<const uint32_t*>(&sXh[col*36 + g16 + 2*tig + 8]);
                #pragma unroll
                for (int mf = 0; mf < MF; ++mf)
                    mma_f16(d[mf][nf], a[mf][0], a[mf][1], a[mf][2], a[mf][3], b0, b1);
            }
        }
    };

    issueChunk(0);
    if (nchunk > 1) issueChunk(1);
    loadWreg(0);
    for (int c0 = 0; c0 < nchunk; ++c0) {
        if (c0 + 2 <= nchunk)
            asm volatile("cp.async.wait_group 1;\n" ::: "memory");
        else
            asm volatile("cp.async.wait_group 0;\n" ::: "memory");
        __syncthreads();                 // ring visible + tiles free (prev MMA done)
        stageX(c0);
        storeW();
        __syncthreads();
        if (c0 + 2 < nchunk) issueChunk(c0 + 2);
        if (c0 + 1 < nchunk) loadWreg((c0 + 1) * 32);
        mmaPhase();
    }

    // epilogue
    #pragma unroll
    for (int mf = 0; mf < MF; ++mf) {
        int r = warpM*MW + mf*16 + gid;
        int co0 = r, co1 = r + 8;
        float bb0 = bias ? bias[co0] : 0.f;
        float bb1 = bias ? bias[co1] : 0.f;
        double s0 = 0.0, q0 = 0.0, s1 = 0.0, q1 = 0.0;
        float mxa[2], mna[2], mxb[2], mnb[2];
        if (POOL) {
            mxa[0] = mxa[1] = mxb[0] = mxb[1] = -3.4e38f;
            mna[0] = mna[1] = mnb[0] = mnb[1] =  3.4e38f;
        }
        #pragma unroll
        for (int nf = 0; nf < 8; ++nf) {
            int p = p0 + warpN*64 + nf*8 + 2*tig;
            float o0 = d[mf][nf][0] + bb0, o1 = d[mf][nf][1] + bb0;
            float o2 = d[mf][nf][2] + bb1, o3 = d[mf][nf][3] + bb1;
            if (!POOL) {
                *reinterpret_cast<__half2*>(&Y[(long)co0*P_TOT + p]) = __floats2half2_rn(o0, o1);
                *reinterpret_cast<__half2*>(&Y[(long)co1*P_TOT + p]) = __floats2half2_rn(o2, o3);
            } else {
                int g = nf >> 2;
                mxa[g] = fmaxf(mxa[g], fmaxf(o0, o1));
                mna[g] = fminf(mna[g], fminf(o0, o1));
                mxb[g] = fmaxf(mxb[g], fmaxf(o2, o3));
                mnb[g] = fminf(mnb[g], fminf(o2, o3));
            }
            if (STATS) {
                s0 += (double)o0 + (double)o1;
                q0 += (double)o0*o0 + (double)o1*o1;
                s1 += (double)o2 + (double)o3;
                q1 += (double)o2*o2 + (double)o3*o3;
            }
        }
        if (POOL) {
            const int PS = P_TOT >> 5;
            #pragma unroll
            for (int g = 0; g < 2; ++g) {
                float ma = mxa[g], na = mna[g], mb = mxb[g], nb = mnb[g];
                #pragma unroll
                for (int off = 1; off <= 2; off <<= 1) {
                    ma = fmaxf(ma, __shfl_xor_sync(0xFFFFFFFFu, ma, off));
                    na = fminf(na, __shfl_xor_sync(0xFFFFFFFFu, na, off));
                    mb = fmaxf(mb, __shfl_xor_sync(0xFFFFFFFFu, mb, off));
                    nb = fminf(nb, __shfl_xor_sync(0xFFFFFFFFu, nb, off));
                }
                if (tig == 0) {
                    int ps = (p0 >> 5) + warpN*2 + g;
                    pmax[(long)co0*PS + ps] = ma;
                    pmin[(long)co0*PS + ps] = na;
                    pmax[(long)co1*PS + ps] = mb;
                    pmin[(long)co1*PS + ps] = nb;
                }
            }
        }
        if (STATS) {
            #pragma unroll
            for (int off = 1; off <= 2; off <<= 1) {
                s0 += __shfl_xor_sync(0xFFFFFFFFu, s0, off);
                q0 += __shfl_xor_sync(0xFFFFFFFFu, q0, off);
                s1 += __shfl_xor_sync(0xFFFFFFFFu, s1, off);
                q1 += __shfl_xor_sync(0xFFFFFFFFu, q1, off);
            }
            if (tig == 0) {
                atomicAdd(&ssum[co0], s0);
                atomicAdd(&ssq[co0], q0);
                atomicAdd(&ssum[co1], s1);
                atomicAdd(&ssq[co1], q1);
            }
        }
    }
}

// ================= fp32/tf32 GEMM (attention path) =================
template<int COUT, bool TRANSA, bool SUB, bool PSCALE, bool STATS>
__global__ void __launch_bounds__(256)
gemm_tc(const float* __restrict__ A, int lda, long aStride,
        const float* __restrict__ X, const float* __restrict__ X2, long xStride,
        const float* __restrict__ pscale, int psStride,
        float* __restrict__ Y, long yStride,
        const float* __restrict__ bias,
        double* __restrict__ ssum, double* __restrict__ ssq,
        int Cin, int P)
{
    constexpr int MW = COUT / 4;
    constexpr int MF = MW / 16;
    constexpr int NW = (COUT*32)/256;
    extern __shared__ char xsm[];
    uint32_t* sX = (uint32_t*)xsm;              // 32*136
    uint32_t* sW = sX + 32*136;                 // COUT*36

    int by = blockIdx.y;
    A += (long)by * aStride;
    X += (long)by * xStride;
    if (SUB) X2 += (long)by * xStride;
    Y += (long)by * yStride;
    int coBase = blockIdx.z * COUT;
    int p0 = blockIdx.x * 128;
    const float* psc = PSCALE ? (pscale + (long)by*psStride + p0) : nullptr;

    int tid = threadIdx.x;
    int lane = tid & 31, wid = tid >> 5;
    int warpM = wid >> 1, warpN = wid & 1;
    int gid = lane >> 2, tig = lane & 3;

    float d[MF][8][4];
    #pragma unroll
    for (int mf = 0; mf < MF; ++mf)
        #pragma unroll
        for (int nf = 0; nf < 8; ++nf)
            #pragma unroll
            for (int i = 0; i < 4; ++i) d[mf][nf][i] = 0.f;

    uint32_t xs[16];
    uint32_t ws[NW];
    int nchunk = (Cin + 31) >> 5;

    auto loadX_g = [&](int k0) {
        #pragma unroll
        for (int j = 0; j < 4; ++j) {
            int id = tid + j*256;
            int row = id >> 5, c4 = id & 31;
            int k = k0 + row;
            float4 v = make_float4(0.f, 0.f, 0.f, 0.f);
            if (k < Cin) {
                v = *reinterpret_cast<const float4*>(&X[(long)k*P + p0 + c4*4]);
                if (SUB) {
                    float4 u = *reinterpret_cast<const float4*>(&X2[(long)k*P + p0 + c4*4]);
                    v.x -= u.x; v.y -= u.y; v.z -= u.z; v.w -= u.w;
                }
                if (PSCALE) {
                    float4 pv = *reinterpret_cast<const float4*>(&psc[c4*4]);
                    v.x *= pv.x; v.y *= pv.y; v.z *= pv.z; v.w *= pv.w;
                }
            }
            xs[j*4+0] = f2tf32(v.x); xs[j*4+1] = f2tf32(v.y);
            xs[j*4+2] = f2tf32(v.z); xs[j*4+3] = f2tf32(v.w);
        }
    };
    auto loadW = [&](int k0) {
        #pragma unroll
        for (int j = 0; j < NW; ++j) {
            int id = tid + j*256;
            int co = id >> 5, kk = id & 31;
            int k = k0 + kk;
            float w = 0.f;
            if (k < Cin)
                w = TRANSA ? A[(long)k*lda + coBase + co]
                           : A[(long)(coBase + co)*lda + k];
            ws[j] = f2tf32(w);
        }
    };
    auto storeTiles = [&]() {
        #pragma unroll
        for (int j = 0; j < 4; ++j) {
            int id = tid + j*256;
            int row = id >> 5, c4 = id & 31;
            *reinterpret_cast<uint4*>(sX + row*136 + c4*4) =
                make_uint4(xs[j*4], xs[j*4+1], xs[j*4+2], xs[j*4+3]);
        }
        #pragma unroll
        for (int j = 0; j < NW; ++j) {
            int id = tid + j*256;
            int co = id >> 5, kk = id & 31;
            sW[co*36 + kk] = ws[j];
        }
    };
    auto mmaPhase = [&]() {
        #pragma unroll
        for (int k8 = 0; k8 < 4; ++k8) {
            int kb = k8*8;
            uint32_t a[MF][4];
            #pragma unroll
            for (int mf = 0; mf < MF; ++mf) {
                int r = warpM*MW + mf*16 + gid;
                a[mf][0] = sW[r*36 + kb + tig];
                a[mf][1] = sW[(r+8)*36 + kb + tig];
                a[mf][2] = sW[r*36 + kb + tig + 4];
                a[mf][3] = sW[(r+8)*36 + kb + tig + 4];
            }
            #pragma unroll
            for (int nf = 0; nf < 8; ++nf) {
                int col = warpN*64 + nf*8 + gid;
                uint32_t b0 = sX[(kb + tig)*136 + col];
                uint32_t b1 = sX[(kb + tig + 4)*136 + col];
                #pragma unroll
                for (int mf = 0; mf < MF; ++mf)
                    mma_tf32(d[mf][nf], a[mf][0], a[mf][1], a[mf][2], a[mf][3], b0, b1);
            }
        }
    };

    loadX_g(0);
    loadW(0);
    for (int c0 = 0; c0 < nchunk; ++c0) {
        storeTiles();
        __syncthreads();
        if (c0 + 1 < nchunk) { loadX_g((c0+1)*32); loadW((c0+1)*32); }
        mmaPhase();
        __syncthreads();
    }

    #pragma unroll
    for (int mf = 0; mf < MF; ++mf) {
        int r = warpM*MW + mf*16 + gid;
        int co0 = coBase + r, co1 = co0 + 8;
        float bb0 = bias ? bias[co0] : 0.f;
        float bb1 = bias ? bias[co1] : 0.f;
        double s0 = 0.0, q0 = 0.0, s1 = 0.0, q1 = 0.0;
        #pragma unroll
        for (int nf = 0; nf < 8; ++nf) {
            int p = p0 + warpN*64 + nf*8 + 2*tig;
            float o0 = d[mf][nf][0] + bb0, o1 = d[mf][nf][1] + bb0;
            float o2 = d[mf][nf][2] + bb1, o3 = d[mf][nf][3] + bb1;
            *reinterpret_cast<float2*>(&Y[(long)co0*P + p]) = make_float2(o0, o1);
            *reinterpret_cast<float2*>(&Y[(long)co1*P + p]) = make_float2(o2, o3);
            if (STATS) {
                s0 += (double)o0 + (double)o1;
                q0 += (double)o0*o0 + (double)o1*o1;
                s1 += (double)o2 + (double)o3;
                q1 += (double)o2*o2 + (double)o3*o3;
            }
        }
        if (STATS) {
            #pragma unroll
            for (int off = 1; off <= 2; off <<= 1) {
                s0 += __shfl_xor_sync(0xFFFFFFFFu, s0, off);
                q0 += __shfl_xor_sync(0xFFFFFFFFu, q0, off);
                s1 += __shfl_xor_sync(0xFFFFFFFFu, s1, off);
                q1 += __shfl_xor_sync(0xFFFFFFFFu, q1, off);
            }
            if (tig == 0) {
                atomicAdd(&ssum[co0], s0);
                atomicAdd(&ssq[co0], q0);
                atomicAdd(&ssum[co1], s1);
                atomicAdd(&ssq[co1], q1);
            }
        }
    }
}

// ---------------- finalize BN -> affine ----------------
__global__ void finalize_bn(const double* __restrict__ ssum, const double* __restrict__ ssq,
                            int Cbn, double count,
                            const float* __restrict__ g, const float* __restrict__ be,
                            float* __restrict__ scale, float* __restrict__ shift,
                            float* __restrict__ lo) {
    int c = threadIdx.x;
    if (c < Cbn) {
        double m = ssum[c] / count;
        double v = ssq[c] / count - m*m;
        float sc = g[c] * rsqrtf((float)v + EPSF);
        scale[c] = sc;
        shift[c] = be[c] - (float)m * sc;
        lo[c] = 0.f;
    } else {
        scale[c] = 1.f;
        shift[c] = 0.f;
        lo[c] = -3.4e38f;
    }
}

// ---------------- pooled BN+ReLU finalize: xp[b][c][s] ----------------
__global__ void pool_finalize(float* __restrict__ xp,
                              const float* __restrict__ pmax, const float* __restrict__ pmin,
                              const float* __restrict__ scale, const float* __restrict__ shift) {
    int i = blockIdx.x*256 + threadIdx.x;
    if (i >= BB*128*NPT) return;
    int s = i & 511, c = (i >> 9) & 127, b = i >> 16;
    int src = c*(BB*NPT) + b*NPT + s;
    float sc = scale[c], sh = shift[c];
    float v = (sc >= 0.f) ? pmax[src] : pmin[src];
    xp[i] = fmaxf(fmaf(v, sc, sh), 0.f);
}

// ---------------- softmax rows ----------------
__global__ void softmax_kernel(float* __restrict__ e) {
    int gw = (blockIdx.x*256 + threadIdx.x) >> 5;
    int lane = threadIdx.x & 31;
    if (gw >= BB*NPT) return;
    float* row = e + (long)gw * NPT;
    float v[16];
    float mx = -3.4e38f;
    #pragma unroll
    for (int i = 0; i < 16; ++i) { v[i] = row[lane + i*32]; mx = fmaxf(mx, v[i]); }
    #pragma unroll
    for (int off = 16; off > 0; off >>= 1)
        mx = fmaxf(mx, __shfl_xor_sync(0xFFFFFFFFu, mx, off));
    float sum = 0.f;
    #pragma unroll
    for (int i = 0; i < 16; ++i) { v[i] = expf(v[i] - mx); sum += v[i]; }
    #pragma unroll
    for (int off = 16; off > 0; off >>= 1)
        sum += __shfl_xor_sync(0xFFFFFFFFu, sum, off);
    #pragma unroll
    for (int i = 0; i < 16; ++i) row[lane + i*32] = v[i] / sum;
}

// ---------------- column sums (store reciprocal) ----------------
__global__ void colsum_kernel(const float* __restrict__ e, float* __restrict__ colrcp) {
    int b = blockIdx.x, m = blockIdx.y*128 + threadIdx.x;
    const float* E = e + (long)b * NPT * NPT;
    float s = 0.f;
    for (int n = 0; n < NPT; ++n) s += E[n*NPT + m];
    colrcp[b*NPT + m] = 1.f / (1e-9f + s);
}

// ---------------- final residual ----------------
__global__ void final_kernel(float* __restrict__ out, const float* __restrict__ xp,
                             const float* __restrict__ y,
                             const float* __restrict__ scale, const float* __restrict__ shift,
                             const float* __restrict__ alpha, const float* __restrict__ beta) {
    int i = blockIdx.x*256 + threadIdx.x;
    if (i >= BB*128*NPT) return;
    int c = (i >> 9) & 127;
    float xr = fmaxf(fmaf(y[i], scale[c], shift[c]), 0.f);
    out[i] = xp[i] + alpha[c]*xr + beta[c];
}

// ---------------- launch ----------------
extern "C" void kernel_launch(void* const* d_in, const int* in_sizes, int n_in,
                              void* d_out, int out_size) {
    const float* xyz    = (const float*)d_in[0];
    const float* points = (const float*)d_in[1];
    const float* w0 = (const float*)d_in[2];
    const float* b0 = (const float*)d_in[3];
    const float* g0 = (const float*)d_in[4];
    const float* be0= (const float*)d_in[5];
    const float* w1 = (const float*)d_in[6];
    const float* b1 = (const float*)d_in[7];
    const float* g1 = (const float*)d_in[8];
    const float* be1= (const float*)d_in[9];
    const float* w2 = (const float*)d_in[10];
    const float* b2 = (const float*)d_in[11];
    const float* g2 = (const float*)d_in[12];
    const float* be2= (const float*)d_in[13];
    const float* wl = (const float*)d_in[14];
    const float* bl = (const float*)d_in[15];
    const float* gl = (const float*)d_in[16];
    const float* bel= (const float*)d_in[17];
    const float* wv = (const float*)d_in[18];
    const float* bv = (const float*)d_in[19];
    const float* wt = (const float*)d_in[20];
    const float* bt = (const float*)d_in[21];
    const float* gn = (const float*)d_in[22];
    const float* gb = (const float*)d_in[23];
    const float* alpha = (const float*)d_in[24];
    const float* beta  = (const float*)d_in[25];
    float* out = (float*)d_out;

    float *xp, *x0, *energy, *x2, *y, *tfs, *tfh, *tfl, *colrcp, *pmax, *pmin;
    __half *hA, *hB;
    double *ssum, *ssq;
    int *fps, *nbr;
    cudaGetSymbolAddress((void**)&hA, g_hA);
    cudaGetSymbolAddress((void**)&hB, g_hB);
    cudaGetSymbolAddress((void**)&xp, g_xp);
    cudaGetSymbolAddress((void**)&x0, g_x0);
    cudaGetSymbolAddress((void**)&energy, g_energy);
    cudaGetSymbolAddress((void**)&x2, g_x2);
    cudaGetSymbolAddress((void**)&y, g_y);
    cudaGetSymbolAddress((void**)&ssum, g_ssum);
    cudaGetSymbolAddress((void**)&ssq, g_ssq);
    cudaGetSymbolAddress((void**)&tfs, g_tfs);
    cudaGetSymbolAddress((void**)&tfh, g_tfh);
    cudaGetSymbolAddress((void**)&tfl, g_tfl);
    cudaGetSymbolAddress((void**)&colrcp, g_colrcp);
    cudaGetSymbolAddress((void**)&pmax, g_pmax);
    cudaGetSymbolAddress((void**)&pmin, g_pmin);
    cudaGetSymbolAddress((void**)&fps, g_fps);
    cudaGetSymbolAddress((void**)&nbr, g_nbr);

    const int SMEM_PTS = 3*NN*sizeof(float);   // 48KB
    cudaFuncSetAttribute(fps_kernel,  cudaFuncAttributeMaxDynamicSharedMemorySize, 64*1024);
    cudaFuncSetAttribute(ball_kernel, cudaFuncAttributeMaxDynamicSharedMemorySize, 64*1024);

    // dynamic smem sizes
    const int SM_H64  = (NST*4096 + 128*36 + 64*40) * 2;    // 38912
    const int SM_H128 = (NST*4096 + 128*36 + 128*40) * 2;   // 44032
    const int SM_N128 = 32*136*4 + 128*36*4;                // 35840 (tf32 path)

    const double CNT_P = (double)P_TOT;
    const double CNT_S = (double)(BB*NPT);

    // geometry (4th launch = L0 fp16 GEMM for ncu capture)
    fps_kernel<<<BB, 1024, SMEM_PTS>>>(xyz, fps);
    ball_kernel<<<dim3(NPT/8, BB), 256, SMEM_PTS>>>(xyz, fps, nbr);
    feat_kernel<<<dim3(NPT, BB), 256>>>(points, xyz, fps, nbr, hB, hA + 128L*P_TOT);

    // L0: 128->64, stats slot0
    gemm_h<64,false,true,false><<<P_TOT/128, 256, SM_H64>>>(
        w0, 128, hB, hA, b0, nullptr, nullptr, nullptr,
        ssum+0, ssq+0, nullptr, nullptr, 128);
    newxyz_kernel<<<(BB*3*NPT + 255)/256, 256>>>(out, xyz, fps);
    finalize_bn<<<1, 64>>>(ssum+0, ssq+0, 64, CNT_P, g0, be0, tfs+0, tfh+0, tfl+0);

    // L1: 64->64, xform tf0, stats slot1
    gemm_h<64,true,true,false><<<P_TOT/128, 256, SM_H64>>>(
        w1, 64, hA, hB, b1, tfs+0, tfh+0, tfl+0,
        ssum+128, ssq+128, nullptr, nullptr, 64);
    finalize_bn<<<1, 64>>>(ssum+128, ssq+128, 64, CNT_P, g1, be1, tfs+132, tfh+132, tfl+132);

    // L2: 64->128, xform tf1, stats slot2
    gemm_h<128,true,true,false><<<P_TOT/128, 256, SM_H128>>>(
        w2, 64, hB, hA, b2, tfs+132, tfh+132, tfl+132,
        ssum+256, ssq+256, nullptr, nullptr, 64);
    finalize_bn<<<1, 131>>>(ssum+256, ssq+256, 128, CNT_P, g2, be2, tfs+264, tfh+264, tfl+264);

    // Ll: 131->128, xform tf2, stats slot3, POOL epilogue
    gemm_h<128,true,true,true><<<P_TOT/128, 256, SM_H128>>>(
        wl, 131, hA, nullptr, bl, tfs+264, tfh+264, tfl+264,
        ssum+384, ssq+384, pmax, pmin, 131);
    finalize_bn<<<1, 128>>>(ssum+384, ssq+384, 128, CNT_P, gl, bel, tfs+396, tfh+396, tfl+396);
    pool_finalize<<<(BB*128*NPT + 255)/256, 256>>>(xp, pmax, pmin, tfs+396, tfh+396);

    // attention (fp32 tf32 path, unchanged)
    gemm_tc<128,false,false,false,false><<<dim3(NPT/128, BB, 1), 256, SM_N128>>>(
        wv, 128, 0, xp, nullptr, PB, nullptr, 0, x0, PB, bv,
        nullptr, nullptr, 128, NPT);
    gemm_tc<128,true,false,false,false><<<dim3(NPT/128, BB, 4), 256, SM_N128>>>(
        xp, NPT, PB, x0, nullptr, PB, nullptr, 0, energy, (long)NPT*NPT, nullptr,
        nullptr, nullptr, 128, NPT);
    softmax_kernel<<<(BB*NPT*32 + 255)/256, 256>>>(energy);
    colsum_kernel<<<dim3(BB, NPT/128), 128>>>(energy, colrcp);
    gemm_tc<128,false,false,true,false><<<dim3(NPT/128, BB, 1), 256, SM_N128>>>(
        x0, NPT, PB, energy, nullptr, (long)NPT*NPT, colrcp, NPT, x2, PB, nullptr,
        nullptr, nullptr, NPT, NPT);
    gemm_tc<128,false,true,false,true><<<dim3(NPT/128, BB, 1), 256, SM_N128>>>(
        wt, 128, 0, xp, x2, PB, nullptr, 0, y, PB, bt,
        ssum+512, ssq+512, 128, NPT);
    finalize_bn<<<1, 128>>>(ssum+512, ssq+512, 128, CNT_S, gn, gb, tfs+528, tfh+528, tfl+528);

    final_kernel<<<(BB*128*NPT + 255)/256, 256>>>(out + BB*3*NPT, xp, y,
        tfs+528, tfh+528, alpha, beta);
}

// round 10
// speedup vs baseline: 2.6565x; 1.0192x over previous
#include <cuda_runtime.h>
#include <cuda_bf16.h>
#include <cuda_fp16.h>
#include <cstdint>
#include <math.h>

// ---------------- constants ----------------
#define BB   16
#define NN   4096
#define DD   64
#define NPT  512
#define KK   32
#define P_TOT (BB*NPT*KK)     // 262144
#define PB   (128*NPT)        // 65536 per-batch (c,s) block
#define EPSF 1e-5f

// ---------------- scratch ----------------
__device__ __half g_hA[131L * P_TOT];           // 131 x P halves (rows 128..130 = rel_xyz)
__device__ __half g_hB[128L * P_TOT];           // 128 x P halves
__device__ float g_xp[BB*128*NPT];
__device__ float g_x0[BB*128*NPT];
__device__ float g_energy[BB*NPT*NPT];
__device__ float g_x2[BB*128*NPT];
__device__ float g_y[BB*128*NPT];
__device__ float g_pmax[128*BB*NPT];
__device__ float g_pmin[128*BB*NPT];
__device__ double g_ssum[5*128];
__device__ double g_ssq[5*128];
__device__ float g_tfs[5*132];
__device__ float g_tfh[5*132];
__device__ float g_tfl[5*132];
__device__ float g_colrcp[BB*NPT];
__device__ int   g_fps[BB*NPT];
__device__ int   g_nbr[BB*NPT*KK];

// ---------------- FPS ----------------
__global__ void __launch_bounds__(1024) fps_kernel(const float* __restrict__ xyz,
                                                   int* __restrict__ fps) {
    extern __shared__ char xsm[];
    float* sm = (float*)xsm;
    float* sx = sm;
    float* sy = sm + NN;
    float* sz = sm + 2*NN;
    __shared__ unsigned long long swarp[32];
    __shared__ int sfar;
    int b = blockIdx.x, tid = threadIdx.x;
    const float* base = xyz + (long)b*3*NN;
    for (int i = tid; i < NN; i += 1024) {
        sx[i] = base[i];
        sy[i] = base[NN + i];
        sz[i] = base[2*NN + i];
    }
    __syncthreads();
    float dist[4];
    dist[0] = dist[1] = dist[2] = dist[3] = 1e10f;
    int far = 0;
    for (int it = 0; it < NPT; ++it) {
        if (tid == 0) fps[b*NPT + it] = far;
        float cx = sx[far], cy = sy[far], cz = sz[far];
        unsigned long long best = 0ull;
        #pragma unroll
        for (int j = 0; j < 4; ++j) {
            int n = tid + j*1024;
            float dx = sx[n]-cx, dy = sy[n]-cy, dz = sz[n]-cz;
            float d = dx*dx + dy*dy + dz*dz;
            float dd = fminf(dist[j], d);
            dist[j] = dd;
            unsigned long long key =
                ((unsigned long long)__float_as_uint(dd) << 32) |
                (unsigned long long)(0xFFFFFFFFu - (unsigned)n);
            best = (key > best) ? key : best;
        }
        #pragma unroll
        for (int off = 16; off > 0; off >>= 1) {
            unsigned long long o = __shfl_down_sync(0xFFFFFFFFu, best, off);
            best = (o > best) ? o : best;
        }
        if ((tid & 31) == 0) swarp[tid >> 5] = best;
        __syncthreads();
        if (tid < 32) {
            best = swarp[tid];
            #pragma unroll
            for (int off = 16; off > 0; off >>= 1) {
                unsigned long long o = __shfl_down_sync(0xFFFFFFFFu, best, off);
                best = (o > best) ? o : best;
            }
            if (tid == 0)
                sfar = (int)(0xFFFFFFFFu - (unsigned)(best & 0xFFFFFFFFull));
        }
        __syncthreads();
        far = sfar;
    }
}

// ---------------- new_xyz output ----------------
__global__ void newxyz_kernel(float* __restrict__ out, const float* __restrict__ xyz,
                              const int* __restrict__ fps) {
    int i = blockIdx.x*256 + threadIdx.x;
    if (i >= BB*3*NPT) return;
    int s = i & 511;
    int c = (i >> 9) % 3;
    int b = i / (3*NPT);
    out[i] = xyz[(long)b*3*NN + c*NN + fps[b*NPT + s]];
}

// ---------------- ball query ----------------
__global__ void __launch_bounds__(256) ball_kernel(const float* __restrict__ xyz,
                                                   const int* __restrict__ fps,
                                                   int* __restrict__ nbr) {
    extern __shared__ char xsm[];
    float* sm = (float*)xsm;
    float* sx = sm;
    float* sy = sm + NN;
    float* sz = sm + 2*NN;
    __shared__ int snb[8][KK];
    int b = blockIdx.y, tid = threadIdx.x;
    const float* base = xyz + (long)b*3*NN;
    for (int i = tid; i < NN; i += 256) {
        sx[i] = base[i];
        sy[i] = base[NN + i];
        sz[i] = base[2*NN + i];
    }
    __syncthreads();
    int w = tid >> 5, lane = tid & 31;
    int s = blockIdx.x*8 + w;
    int fi = fps[b*NPT + s];
    float cx = sx[fi], cy = sy[fi], cz = sz[fi];
    float cn = cx*cx + cy*cy + cz*cz;
    const float R2 = (float)(0.4*0.4);
    int cnt = 0;
    for (int n0 = 0; n0 < NN && cnt < KK; n0 += 32) {
        int n = n0 + lane;
        float px = sx[n], py = sy[n], pz = sz[n];
        float pn = px*px + py*py + pz*pz;
        float dt = cx*px + cy*py + cz*pz;
        float sq = (cn + pn) - 2.0f*dt;
        bool in = !(sq > R2);
        unsigned m = __ballot_sync(0xFFFFFFFFu, in);
        int pos = cnt + __popc(m & ((1u << lane) - 1u));
        if (in && pos < KK) snb[w][pos] = n;
        cnt += __popc(m);
    }
    __syncwarp();
    int v = (lane < cnt) ? snb[w][lane] : snb[w][0];
    nbr[(b*NPT + s)*KK + lane] = v;
}

// ---------------- feature build (half output; also zeros BN stats) ----------------
__global__ void __launch_bounds__(256) feat_kernel(const float* __restrict__ points,
                                                   const float* __restrict__ xyz,
                                                   const int* __restrict__ fps,
                                                   const int* __restrict__ nbr,
                                                   __half* __restrict__ X0,
                                                   __half* __restrict__ relbuf) {
    int s = blockIdx.x, b = blockIdx.y, tid = threadIdx.x;
    if (s == 0 && b == 0) {
        for (int i = tid; i < 5*128; i += 256) { g_ssum[i] = 0.0; g_ssq[i] = 0.0; }
    }
    __shared__ int snb[KK];
    __shared__ float scen[DD];
    __shared__ float scxyz[3];
    int fi = fps[b*NPT + s];
    if (tid < KK) snb[tid] = nbr[(b*NPT + s)*KK + tid];
    if (tid >= 32 && tid < 32+DD) scen[tid-32] = points[(long)b*DD*NN + (tid-32)*NN + fi];
    if (tid >= 96 && tid < 99)   scxyz[tid-96] = xyz[(long)b*3*NN + (tid-96)*NN + fi];
    __syncthreads();
    int k = tid & 31, cb = tid >> 5;
    int n = snb[k];
    int base = (b*NPT + s)*KK + k;
    #pragma unroll
    for (int q = 0; q < 8; ++q) {
        int c = q*8 + cb;
        float v = points[(long)b*DD*NN + c*NN + n];
        X0[(long)c*P_TOT + base] = __float2half(v);
        X0[(long)(DD+c)*P_TOT + base] = __float2half(v - scen[c]);
    }
    if (cb < 3) {
        float v = xyz[(long)b*3*NN + cb*NN + n] - scxyz[cb];
        relbuf[(long)cb*P_TOT + base] = __float2half(v);
    }
}

// ---------------- mma helpers ----------------
__device__ __forceinline__ uint32_t f2tf32(float v) {
    uint32_t r;
    asm("cvt.rna.tf32.f32 %0, %1;" : "=r"(r) : "f"(v));
    return r;
}
__device__ __forceinline__ void mma_tf32(float* d, uint32_t a0, uint32_t a1,
                                         uint32_t a2, uint32_t a3,
                                         uint32_t b0, uint32_t b1) {
    asm volatile("mma.sync.aligned.m16n8k8.row.col.f32.tf32.tf32.f32 "
        "{%0,%1,%2,%3},{%4,%5,%6,%7},{%8,%9},{%0,%1,%2,%3};"
        : "+f"(d[0]), "+f"(d[1]), "+f"(d[2]), "+f"(d[3])
        : "r"(a0), "r"(a1), "r"(a2), "r"(a3), "r"(b0), "r"(b1));
}
__device__ __forceinline__ void mma_f16(float* d, uint32_t a0, uint32_t a1,
                                        uint32_t a2, uint32_t a3,
                                        uint32_t b0, uint32_t b1) {
    asm volatile("mma.sync.aligned.m16n8k16.row.col.f32.f16.f16.f32 "
        "{%0,%1,%2,%3},{%4,%5,%6,%7},{%8,%9},{%0,%1,%2,%3};"
        : "+f"(d[0]), "+f"(d[1]), "+f"(d[2]), "+f"(d[3])
        : "r"(a0), "r"(a1), "r"(a2), "r"(a3), "r"(b0), "r"(b1));
}
__device__ __forceinline__ void ldsm_x4_trans(uint32_t& r0, uint32_t& r1,
                                              uint32_t& r2, uint32_t& r3, uint32_t addr) {
    asm volatile("ldmatrix.sync.aligned.m8n8.x4.trans.shared.b16 {%0,%1,%2,%3}, [%4];"
        : "=r"(r0), "=r"(r1), "=r"(r2), "=r"(r3) : "r"(addr));
}

// ================= fp16 big-layer GEMM (ldmatrix, swizzled [k][p] tile) =========
// Y[co][p] = sum_k W(co,k) * x'(k,p) + bias[co],  P = P_TOT fixed.
// x'(k,p) = XFORM ? max(fma(x, xscale[k], xshift[k]), xlo[k]) : x   (x = half)
// STATS: per-channel double sum/sumsq of fp32 outputs via atomics.
// POOL:  per-(channel, p/32) running max and min instead of Y store.
template<int COUT, bool XFORM, bool STATS, bool POOL>
__global__ void __launch_bounds__(256)
gemm_h(const float* __restrict__ A, int lda,
       const __half* __restrict__ X,
       __half* __restrict__ Y,
       const float* __restrict__ bias,
       const float* __restrict__ xscale, const float* __restrict__ xshift,
       const float* __restrict__ xlo,
       double* __restrict__ ssum, double* __restrict__ ssq,
       float* __restrict__ pmax, float* __restrict__ pmin,
       int Cin)
{
    constexpr int MW = COUT / 4;       // warp tile M
    constexpr int MF = MW / 16;        // m16 fragments per warp
    constexpr int NH2 = COUT / 16;     // W half2 per thread per chunk
    extern __shared__ char xsm[];
    __half* sXh = (__half*)xsm;                // [32][128] halves, XOR-swizzled segs
    __half* sWh = sXh + 32*128;                // [COUT][40]

    int p0 = blockIdx.x * 128;
    int tid = threadIdx.x;
    int lane = tid & 31, wid = tid >> 5;
    int warpM = wid >> 1, warpN = wid & 1;
    int gid = lane >> 2, tig = lane & 3;

    uint32_t sX_base = (uint32_t)__cvta_generic_to_shared(sXh);

    float d[MF][8][4];
    #pragma unroll
    for (int mf = 0; mf < MF; ++mf)
        #pragma unroll
        for (int nf = 0; nf < 8; ++nf)
            #pragma unroll
            for (int i = 0; i < 4; ++i) d[mf][nf][i] = 0.f;

    uint4 xr[2];
    float wsf[2*NH2];
    int nchunk = (Cin + 31) >> 5;

    auto loadXreg = [&](int k0c) {
        #pragma unroll
        for (int j = 0; j < 2; ++j) {
            int id = tid + j*256;
            int k = id >> 4, seg = id & 15;
            int kg = k0c + k;
            uint4 v = make_uint4(0u, 0u, 0u, 0u);
            if (kg < Cin)
                v = *reinterpret_cast<const uint4*>(&X[(long)kg*P_TOT + p0 + seg*8]);
            xr[j] = v;
        }
    };
    auto storeX = [&](int k0c) {
        #pragma unroll
        for (int j = 0; j < 2; ++j) {
            int id = tid + j*256;
            int k = id >> 4, seg = id & 15;
            uint4 v = xr[j];
            if (XFORM) {
                int kg = k0c + k;
                if (kg < Cin) {
                    float s = xscale[kg], h = xshift[kg], l = xlo[kg];
                    uint32_t* w = &v.x;
                    #pragma unroll
                    for (int q = 0; q < 4; ++q) {
                        __half2 hv = *reinterpret_cast<__half2*>(&w[q]);
                        float f0 = __low2float(hv), f1 = __high2float(hv);
                        f0 = fmaxf(fmaf(f0, s, h), l);
                        f1 = fmaxf(fmaf(f1, s, h), l);
                        __half2 ho = __floats2half2_rn(f0, f1);
                        w[q] = *reinterpret_cast<uint32_t*>(&ho);
                    }
                }
            }
            int segp = seg ^ (k & 7);
            *reinterpret_cast<uint4*>(&sXh[k*128 + segp*8]) = v;
        }
    };
    auto loadWreg = [&](int k0c) {
        #pragma unroll
        for (int j = 0; j < NH2; ++j) {
            int hid = tid + j*256;
            int co = hid >> 4, kp = hid & 15;
            int k = k0c + 2*kp;
            wsf[2*j]   = (k   < Cin) ? A[(long)co*lda + k]   : 0.f;
            wsf[2*j+1] = (k+1 < Cin) ? A[(long)co*lda + k+1] : 0.f;
        }
    };
    auto storeW = [&]() {
        #pragma unroll
        for (int j = 0; j < NH2; ++j) {
            int hid = tid + j*256;
            int co = hid >> 4, kp = hid & 15;
            __half2 hp = __floats2half2_rn(wsf[2*j], wsf[2*j+1]);
            *reinterpret_cast<__half2*>(&sWh[co*40 + 2*kp]) = hp;
        }
    };

    auto mmaPhase = [&]() {
        int mi = lane >> 3, lr = lane & 7;       // ldmatrix lane->matrix mapping
        #pragma unroll
        for (int g16 = 0; g16 < 32; g16 += 16) {
            uint32_t a[MF][4];
            #pragma unroll
            for (int mf = 0; mf < MF; ++mf) {
                int r = warpM*MW + mf*16 + gid;
                a[mf][0] = *reinterpret_cast<const uint32_t*>(&sWh[r*40 + g16 + 2*tig]);
                a[mf][1] = *reinterpret_cast<const uint32_t*>(&sWh[(r+8)*40 + g16 + 2*tig]);
                a[mf][2] = *reinterpret_cast<const uint32_t*>(&sWh[r*40 + g16 + 2*tig + 8]);
                a[mf][3] = *reinterpret_cast<const uint32_t*>(&sWh[(r+8)*40 + g16 + 2*tig + 8]);
            }
            int kl = g16 + ((mi & 1) << 3) + lr; // this lane's k row
            #pragma unroll
            for (int np = 0; np < 4; ++np) {
                int seg = warpN*8 + np*2 + (mi >> 1);
                int segp = seg ^ (kl & 7);
                uint32_t addr = sX_base + (uint32_t)((kl*128 + segp*8) * 2);
                uint32_t b0, b1, b2, b3;
                ldsm_x4_trans(b0, b1, b2, b3, addr);
                #pragma unroll
                for (int mf = 0; mf < MF; ++mf) {
                    mma_f16(d[mf][2*np],   a[mf][0], a[mf][1], a[mf][2], a[mf][3], b0, b1);
                    mma_f16(d[mf][2*np+1], a[mf][0], a[mf][1], a[mf][2], a[mf][3], b2, b3);
                }
            }
        }
    };

    loadXreg(0);
    loadWreg(0);
    for (int c0 = 0; c0 < nchunk; ++c0) {
        storeX(c0*32);
        storeW();
        __syncthreads();
        if (c0 + 1 < nchunk) { loadXreg((c0+1)*32); loadWreg((c0+1)*32); }
        mmaPhase();
        __syncthreads();
    }

    // epilogue
    #pragma unroll
    for (int mf = 0; mf < MF; ++mf) {
        int r = warpM*MW + mf*16 + gid;
        int co0 = r, co1 = r + 8;
        float bb0 = bias ? bias[co0] : 0.f;
        float bb1 = bias ? bias[co1] : 0.f;
        double s0 = 0.0, q0 = 0.0, s1 = 0.0, q1 = 0.0;
        float mxa[2], mna[2], mxb[2], mnb[2];
        if (POOL) {
            mxa[0] = mxa[1] = mxb[0] = mxb[1] = -3.4e38f;
            mna[0] = mna[1] = mnb[0] = mnb[1] =  3.4e38f;
        }
        #pragma unroll
        for (int nf = 0; nf < 8; ++nf) {
            int p = p0 + warpN*64 + nf*8 + 2*tig;
            float o0 = d[mf][nf][0] + bb0, o1 = d[mf][nf][1] + bb0;
            float o2 = d[mf][nf][2] + bb1, o3 = d[mf][nf][3] + bb1;
            if (!POOL) {
                *reinterpret_cast<__half2*>(&Y[(long)co0*P_TOT + p]) = __floats2half2_rn(o0, o1);
                *reinterpret_cast<__half2*>(&Y[(long)co1*P_TOT + p]) = __floats2half2_rn(o2, o3);
            } else {
                int g = nf >> 2;
                mxa[g] = fmaxf(mxa[g], fmaxf(o0, o1));
                mna[g] = fminf(mna[g], fminf(o0, o1));
                mxb[g] = fmaxf(mxb[g], fmaxf(o2, o3));
                mnb[g] = fminf(mnb[g], fminf(o2, o3));
            }
            if (STATS) {
                s0 += (double)o0 + (double)o1;
                q0 += (double)o0*o0 + (double)o1*o1;
                s1 += (double)o2 + (double)o3;
                q1 += (double)o2*o2 + (double)o3*o3;
            }
        }
        if (POOL) {
            const int PS = P_TOT >> 5;
            #pragma unroll
            for (int g = 0; g < 2; ++g) {
                float ma = mxa[g], na = mna[g], mb = mxb[g], nb = mnb[g];
                #pragma unroll
                for (int off = 1; off <= 2; off <<= 1) {
                    ma = fmaxf(ma, __shfl_xor_sync(0xFFFFFFFFu, ma, off));
                    na = fminf(na, __shfl_xor_sync(0xFFFFFFFFu, na, off));
                    mb = fmaxf(mb, __shfl_xor_sync(0xFFFFFFFFu, mb, off));
                    nb = fminf(nb, __shfl_xor_sync(0xFFFFFFFFu, nb, off));
                }
                if (tig == 0) {
                    int ps = (p0 >> 5) + warpN*2 + g;
                    pmax[(long)co0*PS + ps] = ma;
                    pmin[(long)co0*PS + ps] = na;
                    pmax[(long)co1*PS + ps] = mb;
                    pmin[(long)co1*PS + ps] = nb;
                }
            }
        }
        if (STATS) {
            #pragma unroll
            for (int off = 1; off <= 2; off <<= 1) {
                s0 += __shfl_xor_sync(0xFFFFFFFFu, s0, off);
                q0 += __shfl_xor_sync(0xFFFFFFFFu, q0, off);
                s1 += __shfl_xor_sync(0xFFFFFFFFu, s1, off);
                q1 += __shfl_xor_sync(0xFFFFFFFFu, q1, off);
            }
            if (tig == 0) {
                atomicAdd(&ssum[co0], s0);
                atomicAdd(&ssq[co0], q0);
                atomicAdd(&ssum[co1], s1);
                atomicAdd(&ssq[co1], q1);
            }
        }
    }
}

// ================= fp32/tf32 GEMM (attention path) =================
template<int COUT, bool TRANSA, bool SUB, bool PSCALE, bool STATS>
__global__ void __launch_bounds__(256)
gemm_tc(const float* __restrict__ A, int lda, long aStride,
        const float* __restrict__ X, const float* __restrict__ X2, long xStride,
        const float* __restrict__ pscale, int psStride,
        float* __restrict__ Y, long yStride,
        const float* __restrict__ bias,
        double* __restrict__ ssum, double* __restrict__ ssq,
        int Cin, int P)
{
    constexpr int MW = COUT / 4;
    constexpr int MF = MW / 16;
    constexpr int NW = (COUT*32)/256;
    extern __shared__ char xsm[];
    uint32_t* sX = (uint32_t*)xsm;              // 32*136
    uint32_t* sW = sX + 32*136;                 // COUT*36

    int by = blockIdx.y;
    A += (long)by * aStride;
    X += (long)by * xStride;
    if (SUB) X2 += (long)by * xStride;
    Y += (long)by * yStride;
    int coBase = blockIdx.z * COUT;
    int p0 = blockIdx.x * 128;
    const float* psc = PSCALE ? (pscale + (long)by*psStride + p0) : nullptr;

    int tid = threadIdx.x;
    int lane = tid & 31, wid = tid >> 5;
    int warpM = wid >> 1, warpN = wid & 1;
    int gid = lane >> 2, tig = lane & 3;

    float d[MF][8][4];
    #pragma unroll
    for (int mf = 0; mf < MF; ++mf)
        #pragma unroll
        for (int nf = 0; nf < 8; ++nf)
            #pragma unroll
            for (int i = 0; i < 4; ++i) d[mf][nf][i] = 0.f;

    uint32_t xs[16];
    uint32_t ws[NW];
    int nchunk = (Cin + 31) >> 5;

    auto loadX_g = [&](int k0) {
        #pragma unroll
        for (int j = 0; j < 4; ++j) {
            int id = tid + j*256;
            int row = id >> 5, c4 = id & 31;
            int k = k0 + row;
            float4 v = make_float4(0.f, 0.f, 0.f, 0.f);
            if (k < Cin) {
                v = *reinterpret_cast<const float4*>(&X[(long)k*P + p0 + c4*4]);
                if (SUB) {
                    float4 u = *reinterpret_cast<const float4*>(&X2[(long)k*P + p0 + c4*4]);
                    v.x -= u.x; v.y -= u.y; v.z -= u.z; v.w -= u.w;
                }
                if (PSCALE) {
                    float4 pv = *reinterpret_cast<const float4*>(&psc[c4*4]);
                    v.x *= pv.x; v.y *= pv.y; v.z *= pv.z; v.w *= pv.w;
                }
            }
            xs[j*4+0] = f2tf32(v.x); xs[j*4+1] = f2tf32(v.y);
            xs[j*4+2] = f2tf32(v.z); xs[j*4+3] = f2tf32(v.w);
        }
    };
    auto loadW = [&](int k0) {
        #pragma unroll
        for (int j = 0; j < NW; ++j) {
            int id = tid + j*256;
            int co = id >> 5, kk = id & 31;
            int k = k0 + kk;
            float w = 0.f;
            if (k < Cin)
                w = TRANSA ? A[(long)k*lda + coBase + co]
                           : A[(long)(coBase + co)*lda + k];
            ws[j] = f2tf32(w);
        }
    };
    auto storeTiles = [&]() {
        #pragma unroll
        for (int j = 0; j < 4; ++j) {
            int id = tid + j*256;
            int row = id >> 5, c4 = id & 31;
            *reinterpret_cast<uint4*>(sX + row*136 + c4*4) =
                make_uint4(xs[j*4], xs[j*4+1], xs[j*4+2], xs[j*4+3]);
        }
        #pragma unroll
        for (int j = 0; j < NW; ++j) {
            int id = tid + j*256;
            int co = id >> 5, kk = id & 31;
            sW[co*36 + kk] = ws[j];
        }
    };
    auto mmaPhase = [&]() {
        #pragma unroll
        for (int k8 = 0; k8 < 4; ++k8) {
            int kb = k8*8;
            uint32_t a[MF][4];
            #pragma unroll
            for (int mf = 0; mf < MF; ++mf) {
                int r = warpM*MW + mf*16 + gid;
                a[mf][0] = sW[r*36 + kb + tig];
                a[mf][1] = sW[(r+8)*36 + kb + tig];
                a[mf][2] = sW[r*36 + kb + tig + 4];
                a[mf][3] = sW[(r+8)*36 + kb + tig + 4];
            }
            #pragma unroll
            for (int nf = 0; nf < 8; ++nf) {
                int col = warpN*64 + nf*8 + gid;
                uint32_t b0 = sX[(kb + tig)*136 + col];
                uint32_t b1 = sX[(kb + tig + 4)*136 + col];
                #pragma unroll
                for (int mf = 0; mf < MF; ++mf)
                    mma_tf32(d[mf][nf], a[mf][0], a[mf][1], a[mf][2], a[mf][3], b0, b1);
            }
        }
    };

    loadX_g(0);
    loadW(0);
    for (int c0 = 0; c0 < nchunk; ++c0) {
        storeTiles();
        __syncthreads();
        if (c0 + 1 < nchunk) { loadX_g((c0+1)*32); loadW((c0+1)*32); }
        mmaPhase();
        __syncthreads();
    }

    #pragma unroll
    for (int mf = 0; mf < MF; ++mf) {
        int r = warpM*MW + mf*16 + gid;
        int co0 = coBase + r, co1 = co0 + 8;
        float bb0 = bias ? bias[co0] : 0.f;
        float bb1 = bias ? bias[co1] : 0.f;
        double s0 = 0.0, q0 = 0.0, s1 = 0.0, q1 = 0.0;
        #pragma unroll
        for (int nf = 0; nf < 8; ++nf) {
            int p = p0 + warpN*64 + nf*8 + 2*tig;
            float o0 = d[mf][nf][0] + bb0, o1 = d[mf][nf][1] + bb0;
            float o2 = d[mf][nf][2] + bb1, o3 = d[mf][nf][3] + bb1;
            *reinterpret_cast<float2*>(&Y[(long)co0*P + p]) = make_float2(o0, o1);
            *reinterpret_cast<float2*>(&Y[(long)co1*P + p]) = make_float2(o2, o3);
            if (STATS) {
                s0 += (double)o0 + (double)o1;
                q0 += (double)o0*o0 + (double)o1*o1;
                s1 += (double)o2 + (double)o3;
                q1 += (double)o2*o2 + (double)o3*o3;
            }
        }
        if (STATS) {
            #pragma unroll
            for (int off = 1; off <= 2; off <<= 1) {
                s0 += __shfl_xor_sync(0xFFFFFFFFu, s0, off);
                q0 += __shfl_xor_sync(0xFFFFFFFFu, q0, off);
                s1 += __shfl_xor_sync(0xFFFFFFFFu, s1, off);
                q1 += __shfl_xor_sync(0xFFFFFFFFu, q1, off);
            }
            if (tig == 0) {
                atomicAdd(&ssum[co0], s0);
                atomicAdd(&ssq[co0], q0);
                atomicAdd(&ssum[co1], s1);
                atomicAdd(&ssq[co1], q1);
            }
        }
    }
}

// ---------------- finalize BN -> affine ----------------
__global__ void finalize_bn(const double* __restrict__ ssum, const double* __restrict__ ssq,
                            int Cbn, double count,
                            const float* __restrict__ g, const float* __restrict__ be,
                            float* __restrict__ scale, float* __restrict__ shift,
                            float* __restrict__ lo) {
    int c = threadIdx.x;
    if (c < Cbn) {
        double m = ssum[c] / count;
        double v = ssq[c] / count - m*m;
        float sc = g[c] * rsqrtf((float)v + EPSF);
        scale[c] = sc;
        shift[c] = be[c] - (float)m * sc;
        lo[c] = 0.f;
    } else {
        scale[c] = 1.f;
        shift[c] = 0.f;
        lo[c] = -3.4e38f;
    }
}

// ---------------- pooled BN+ReLU finalize: xp[b][c][s] ----------------
__global__ void pool_finalize(float* __restrict__ xp,
                              const float* __restrict__ pmax, const float* __restrict__ pmin,
                              const float* __restrict__ scale, const float* __restrict__ shift) {
    int i = blockIdx.x*256 + threadIdx.x;
    if (i >= BB*128*NPT) return;
    int s = i & 511, c = (i >> 9) & 127, b = i >> 16;
    int src = c*(BB*NPT) + b*NPT + s;
    float sc = scale[c], sh = shift[c];
    float v = (sc >= 0.f) ? pmax[src] : pmin[src];
    xp[i] = fmaxf(fmaf(v, sc, sh), 0.f);
}

// ---------------- softmax rows ----------------
__global__ void softmax_kernel(float* __restrict__ e) {
    int gw = (blockIdx.x*256 + threadIdx.x) >> 5;
    int lane = threadIdx.x & 31;
    if (gw >= BB*NPT) return;
    float* row = e + (long)gw * NPT;
    float v[16];
    float mx = -3.4e38f;
    #pragma unroll
    for (int i = 0; i < 16; ++i) { v[i] = row[lane + i*32]; mx = fmaxf(mx, v[i]); }
    #pragma unroll
    for (int off = 16; off > 0; off >>= 1)
        mx = fmaxf(mx, __shfl_xor_sync(0xFFFFFFFFu, mx, off));
    float sum = 0.f;
    #pragma unroll
    for (int i = 0; i < 16; ++i) { v[i] = expf(v[i] - mx); sum += v[i]; }
    #pragma unroll
    for (int off = 16; off > 0; off >>= 1)
        sum += __shfl_xor_sync(0xFFFFFFFFu, sum, off);
    #pragma unroll
    for (int i = 0; i < 16; ++i) row[lane + i*32] = v[i] / sum;
}

// ---------------- column sums (store reciprocal) ----------------
__global__ void colsum_kernel(const float* __restrict__ e, float* __restrict__ colrcp) {
    int b = blockIdx.x, m = blockIdx.y*128 + threadIdx.x;
    const float* E = e + (long)b * NPT * NPT;
    float s = 0.f;
    for (int n = 0; n < NPT; ++n) s += E[n*NPT + m];
    colrcp[b*NPT + m] = 1.f / (1e-9f + s);
}

// ---------------- final residual ----------------
__global__ void final_kernel(float* __restrict__ out, const float* __restrict__ xp,
                             const float* __restrict__ y,
                             const float* __restrict__ scale, const float* __restrict__ shift,
                             const float* __restrict__ alpha, const float* __restrict__ beta) {
    int i = blockIdx.x*256 + threadIdx.x;
    if (i >= BB*128*NPT) return;
    int c = (i >> 9) & 127;
    float xr = fmaxf(fmaf(y[i], scale[c], shift[c]), 0.f);
    out[i] = xp[i] + alpha[c]*xr + beta[c];
}

// ---------------- launch ----------------
extern "C" void kernel_launch(void* const* d_in, const int* in_sizes, int n_in,
                              void* d_out, int out_size) {
    const float* xyz    = (const float*)d_in[0];
    const float* points = (const float*)d_in[1];
    const float* w0 = (const float*)d_in[2];
    const float* b0 = (const float*)d_in[3];
    const float* g0 = (const float*)d_in[4];
    const float* be0= (const float*)d_in[5];
    const float* w1 = (const float*)d_in[6];
    const float* b1 = (const float*)d_in[7];
    const float* g1 = (const float*)d_in[8];
    const float* be1= (const float*)d_in[9];
    const float* w2 = (const float*)d_in[10];
    const float* b2 = (const float*)d_in[11];
    const float* g2 = (const float*)d_in[12];
    const float* be2= (const float*)d_in[13];
    const float* wl = (const float*)d_in[14];
    const float* bl = (const float*)d_in[15];
    const float* gl = (const float*)d_in[16];
    const float* bel= (const float*)d_in[17];
    const float* wv = (const float*)d_in[18];
    const float* bv = (const float*)d_in[19];
    const float* wt = (const float*)d_in[20];
    const float* bt = (const float*)d_in[21];
    const float* gn = (const float*)d_in[22];
    const float* gb = (const float*)d_in[23];
    const float* alpha = (const float*)d_in[24];
    const float* beta  = (const float*)d_in[25];
    float* out = (float*)d_out;

    float *xp, *x0, *energy, *x2, *y, *tfs, *tfh, *tfl, *colrcp, *pmax, *pmin;
    __half *hA, *hB;
    double *ssum, *ssq;
    int *fps, *nbr;
    cudaGetSymbolAddress((void**)&hA, g_hA);
    cudaGetSymbolAddress((void**)&hB, g_hB);
    cudaGetSymbolAddress((void**)&xp, g_xp);
    cudaGetSymbolAddress((void**)&x0, g_x0);
    cudaGetSymbolAddress((void**)&energy, g_energy);
    cudaGetSymbolAddress((void**)&x2, g_x2);
    cudaGetSymbolAddress((void**)&y, g_y);
    cudaGetSymbolAddress((void**)&ssum, g_ssum);
    cudaGetSymbolAddress((void**)&ssq, g_ssq);
    cudaGetSymbolAddress((void**)&tfs, g_tfs);
    cudaGetSymbolAddress((void**)&tfh, g_tfh);
    cudaGetSymbolAddress((void**)&tfl, g_tfl);
    cudaGetSymbolAddress((void**)&colrcp, g_colrcp);
    cudaGetSymbolAddress((void**)&pmax, g_pmax);
    cudaGetSymbolAddress((void**)&pmin, g_pmin);
    cudaGetSymbolAddress((void**)&fps, g_fps);
    cudaGetSymbolAddress((void**)&nbr, g_nbr);

    const int SMEM_PTS = 3*NN*sizeof(float);   // 48KB
    cudaFuncSetAttribute(fps_kernel,  cudaFuncAttributeMaxDynamicSharedMemorySize, 64*1024);
    cudaFuncSetAttribute(ball_kernel, cudaFuncAttributeMaxDynamicSharedMemorySize, 64*1024);

    // dynamic smem sizes
    const int SM_H64  = (32*128 + 64*40) * 2;    // 13312
    const int SM_H128 = (32*128 + 128*40) * 2;   // 18432
    const int SM_N128 = 32*136*4 + 128*36*4;     // 35840 (tf32 path)

    const double CNT_P = (double)P_TOT;
    const double CNT_S = (double)(BB*NPT);

    // geometry (4th launch = L0 fp16 GEMM for ncu capture)
    fps_kernel<<<BB, 1024, SMEM_PTS>>>(xyz, fps);
    ball_kernel<<<dim3(NPT/8, BB), 256, SMEM_PTS>>>(xyz, fps, nbr);
    feat_kernel<<<dim3(NPT, BB), 256>>>(points, xyz, fps, nbr, hB, hA + 128L*P_TOT);

    // L0: 128->64, stats slot0
    gemm_h<64,false,true,false><<<P_TOT/128, 256, SM_H64>>>(
        w0, 128, hB, hA, b0, nullptr, nullptr, nullptr,
        ssum+0, ssq+0, nullptr, nullptr, 128);
    newxyz_kernel<<<(BB*3*NPT + 255)/256, 256>>>(out, xyz, fps);
    finalize_bn<<<1, 64>>>(ssum+0, ssq+0, 64, CNT_P, g0, be0, tfs+0, tfh+0, tfl+0);

    // L1: 64->64, xform tf0, stats slot1
    gemm_h<64,true,true,false><<<P_TOT/128, 256, SM_H64>>>(
        w1, 64, hA, hB, b1, tfs+0, tfh+0, tfl+0,
        ssum+128, ssq+128, nullptr, nullptr, 64);
    finalize_bn<<<1, 64>>>(ssum+128, ssq+128, 64, CNT_P, g1, be1, tfs+132, tfh+132, tfl+132);

    // L2: 64->128, xform tf1, stats slot2
    gemm_h<128,true,true,false><<<P_TOT/128, 256, SM_H128>>>(
        w2, 64, hB, hA, b2, tfs+132, tfh+132, tfl+132,
        ssum+256, ssq+256, nullptr, nullptr, 64);
    finalize_bn<<<1, 131>>>(ssum+256, ssq+256, 128, CNT_P, g2, be2, tfs+264, tfh+264, tfl+264);

    // Ll: 131->128, xform tf2, stats slot3, POOL epilogue
    gemm_h<128,true,true,true><<<P_TOT/128, 256, SM_H128>>>(
        wl, 131, hA, nullptr, bl, tfs+264, tfh+264, tfl+264,
        ssum+384, ssq+384, pmax, pmin, 131);
    finalize_bn<<<1, 128>>>(ssum+384, ssq+384, 128, CNT_P, gl, bel, tfs+396, tfh+396, tfl+396);
    pool_finalize<<<(BB*128*NPT + 255)/256, 256>>>(xp, pmax, pmin, tfs+396, tfh+396);

    // attention (fp32 tf32 path, unchanged)
    gemm_tc<128,false,false,false,false><<<dim3(NPT/128, BB, 1), 256, SM_N128>>>(
        wv, 128, 0, xp, nullptr, PB, nullptr, 0, x0, PB, bv,
        nullptr, nullptr, 128, NPT);
    gemm_tc<128,true,false,false,false><<<dim3(NPT/128, BB, 4), 256, SM_N128>>>(
        xp, NPT, PB, x0, nullptr, PB, nullptr, 0, energy, (long)NPT*NPT, nullptr,
        nullptr, nullptr, 128, NPT);
    softmax_kernel<<<(BB*NPT*32 + 255)/256, 256>>>(energy);
    colsum_kernel<<<dim3(BB, NPT/128), 128>>>(energy, colrcp);
    gemm_tc<128,false,false,true,false><<<dim3(NPT/128, BB, 1), 256, SM_N128>>>(
        x0, NPT, PB, energy, nullptr, (long)NPT*NPT, colrcp, NPT, x2, PB, nullptr,
        nullptr, nullptr, NPT, NPT);
    gemm_tc<128,false,true,false,true><<<dim3(NPT/128, BB, 1), 256, SM_N128>>>(
        wt, 128, 0, xp, x2, PB, nullptr, 0, y, PB, bt,
        ssum+512, ssq+512, 128, NPT);
    finalize_bn<<<1, 128>>>(ssum+512, ssq+512, 128, CNT_S, gn, gb, tfs+528, tfh+528, tfl+528);

    final_kernel<<<(BB*128*NPT + 255)/256, 256>>>(out + BB*3*NPT, xp, y,
        tfs+528, tfh+528, alpha, beta);
}